// round 4
// baseline (speedup 1.0000x reference)
#include <cuda_runtime.h>
#include <cuda_bf16.h>

#define IN_C   256
#define HC     256
#define HEADS  4
#define CPH    64
#define NMAX   10000
#define EMAX   320000
#define ETMAX  (EMAX + NMAX)
#define NEG_SLOPE 0.2f
#define LN_EPS 1e-5f

// ---------------- scratch (static device memory; no allocations) -------------
__device__ float g_h[NMAX * HC];        // GAT-projected features
__device__ float g_als[NMAX * HEADS];   // alpha_src logits per node
__device__ float g_ald[NMAX * HEADS];   // alpha_dst logits per node
__device__ int   g_deg[NMAX];
__device__ int   g_off[NMAX + 1];
__device__ int   g_cur[NMAX];
__device__ int   g_esrc[ETMAX];         // CSR by dst: src node of each in-edge
__device__ float g_h2[NMAX];            // post-LN scalar projection
__device__ float g_dinv[NMAX];          // rsqrt(degree)

// ---------------- CSR construction -------------------------------------------
__global__ void k_init(int N) {
    int i = blockIdx.x * blockDim.x + threadIdx.x;
    if (i < N) g_deg[i] = 1;   // self loop
}

__global__ void k_count(const int* __restrict__ dst, int E) {
    int i = blockIdx.x * blockDim.x + threadIdx.x;
    if (i < E) atomicAdd(&g_deg[dst[i]], 1);
}

// single-block exclusive scan of g_deg -> g_off / g_cur (warp-shuffle based)
__global__ void k_scan(int N) {
    __shared__ int warp_sums[32];
    __shared__ int carry_s;
    int tid = threadIdx.x;
    int lane = tid & 31, wid = tid >> 5;
    if (tid == 0) carry_s = 0;
    __syncthreads();
    for (int base = 0; base < N; base += 1024) {
        int i = base + tid;
        int v = (i < N) ? g_deg[i] : 0;
        // intra-warp inclusive scan
        int incl = v;
#pragma unroll
        for (int s = 1; s < 32; s <<= 1) {
            int t = __shfl_up_sync(0xffffffffu, incl, s);
            if (lane >= s) incl += t;
        }
        if (lane == 31) warp_sums[wid] = incl;
        __syncthreads();
        if (wid == 0) {
            int w = (lane < 32) ? warp_sums[lane] : 0;
#pragma unroll
            for (int s = 1; s < 32; s <<= 1) {
                int t = __shfl_up_sync(0xffffffffu, w, s);
                if (lane >= s) w += t;
            }
            warp_sums[lane] = w;   // inclusive warp-sum scan
        }
        __syncthreads();
        int warp_base = (wid > 0) ? warp_sums[wid - 1] : 0;
        int c = carry_s;
        int incl_blk = warp_base + incl;
        if (i < N) {
            int excl = c + incl_blk - v;
            g_off[i] = excl;
            g_cur[i] = excl;
            if (i == N - 1) g_off[N] = c + incl_blk;
        }
        __syncthreads();
        if (tid == 1023) carry_s = c + incl_blk;
        __syncthreads();
    }
}

__global__ void k_scatter(const int* __restrict__ src, const int* __restrict__ dst,
                          int E, int N) {
    int i = blockIdx.x * blockDim.x + threadIdx.x;
    if (i >= E + N) return;
    int d, s;
    if (i < E) { d = dst[i]; s = src[i]; }
    else       { d = i - E;  s = i - E;  }   // self loop
    int pos = atomicAdd(&g_cur[d], 1);
    g_esrc[pos] = s;
}

// ---------------- SGEMM: h = x @ W_gat  (64x64 tile, 16x16 threads, 4x4/thr) --
__global__ void k_gemm(const float* __restrict__ X, const float* __restrict__ W, int N) {
    __shared__ float As[16][64];
    __shared__ float Bs[16][64];
    int tx = threadIdx.x, ty = threadIdx.y;
    int tid = ty * 16 + tx;
    int m0 = blockIdx.y * 64, n0 = blockIdx.x * 64;

    float acc[4][4];
#pragma unroll
    for (int i = 0; i < 4; i++)
#pragma unroll
        for (int j = 0; j < 4; j++) acc[i][j] = 0.f;

    for (int k0 = 0; k0 < IN_C; k0 += 16) {
        {   // load A tile (transposed into shared)
            int m = tid >> 2, ks = (tid & 3) * 4;
            int row = m0 + m;
            float4 v = (row < N) ? *(const float4*)(X + (long)row * IN_C + k0 + ks)
                                 : make_float4(0.f, 0.f, 0.f, 0.f);
            As[ks + 0][m] = v.x; As[ks + 1][m] = v.y;
            As[ks + 2][m] = v.z; As[ks + 3][m] = v.w;
        }
        {   // load B tile
            int kk = tid >> 4, ns = (tid & 15) * 4;
            float4 v = *(const float4*)(W + (long)(k0 + kk) * HC + n0 + ns);
            *(float4*)&Bs[kk][ns] = v;
        }
        __syncthreads();
#pragma unroll
        for (int kk = 0; kk < 16; kk++) {
            float a[4], b[4];
#pragma unroll
            for (int i = 0; i < 4; i++) a[i] = As[kk][ty * 4 + i];
#pragma unroll
            for (int j = 0; j < 4; j++) b[j] = Bs[kk][tx * 4 + j];
#pragma unroll
            for (int i = 0; i < 4; i++)
#pragma unroll
                for (int j = 0; j < 4; j++) acc[i][j] = fmaf(a[i], b[j], acc[i][j]);
        }
        __syncthreads();
    }
#pragma unroll
    for (int i = 0; i < 4; i++) {
        int row = m0 + ty * 4 + i;
        if (row < N) {
            float4 v = make_float4(acc[i][0], acc[i][1], acc[i][2], acc[i][3]);
            *(float4*)(g_h + (long)row * HC + n0 + tx * 4) = v;
        }
    }
}

// ---------------- attention logits: al_s/al_d ---------------------------------
__global__ void k_logits(const float* __restrict__ asrc, const float* __restrict__ adst,
                         int N) {
    int n = blockIdx.x;
    int w = threadIdx.x >> 5;      // head
    int lane = threadIdx.x & 31;
    const float* hr = g_h + (long)n * HC + w * CPH;
    float s1 = 0.f, s2 = 0.f;
#pragma unroll
    for (int c = lane; c < CPH; c += 32) {
        float hv = hr[c];
        s1 = fmaf(hv, asrc[w * CPH + c], s1);
        s2 = fmaf(hv, adst[w * CPH + c], s2);
    }
#pragma unroll
    for (int o = 16; o > 0; o >>= 1) {
        s1 += __shfl_down_sync(0xffffffffu, s1, o);
        s2 += __shfl_down_sync(0xffffffffu, s2, o);
    }
    if (lane == 0) {
        g_als[n * HEADS + w] = s1;
        g_ald[n * HEADS + w] = s2;
    }
}

__device__ __forceinline__ float leaky(float v) {
    return v > 0.f ? v : NEG_SLOPE * v;
}

// ---------------- fused GAT aggregation + bias + ReLU + LN + GCN proj ---------
__global__ void __launch_bounds__(128) k_gat(const float* __restrict__ bgat,
                                             const float* __restrict__ gamma,
                                             const float* __restrict__ beta,
                                             const float* __restrict__ wgcn,
                                             int N) {
    int d = blockIdx.x;
    int tid = threadIdx.x;                 // 128 threads, 2 channels each
    int row0 = g_off[d], row1 = g_off[d + 1];

    float4 aldv = *(const float4*)(g_ald + d * HEADS);
    float ald[4] = {aldv.x, aldv.y, aldv.z, aldv.w};

    __shared__ float red[128][4];
    __shared__ float m_sh[4];
    __shared__ float z_sh[4];
    __shared__ float p_sh[128][4];
    __shared__ int   src_sh[128];
    __shared__ float stats[2];

    // ---- pass 1: per-head max over incoming edges ----
    float mx[4] = {-1e30f, -1e30f, -1e30f, -1e30f};
    for (int i = row0 + tid; i < row1; i += 128) {
        int s = g_esrc[i];
        float4 av = *(const float4*)(g_als + s * HEADS);
        mx[0] = fmaxf(mx[0], leaky(av.x + ald[0]));
        mx[1] = fmaxf(mx[1], leaky(av.y + ald[1]));
        mx[2] = fmaxf(mx[2], leaky(av.z + ald[2]));
        mx[3] = fmaxf(mx[3], leaky(av.w + ald[3]));
    }
#pragma unroll
    for (int h = 0; h < 4; h++) red[tid][h] = mx[h];
    __syncthreads();
    for (int s = 64; s > 0; s >>= 1) {
        if (tid < s)
#pragma unroll
            for (int h = 0; h < 4; h++)
                red[tid][h] = fmaxf(red[tid][h], red[tid + s][h]);
        __syncthreads();
    }
    if (tid < 4) m_sh[tid] = red[0][tid];
    __syncthreads();
    float m0 = m_sh[0], m1 = m_sh[1], m2 = m_sh[2], m3 = m_sh[3];

    // ---- pass 2: softmax numerators + weighted feature gather ----
    int hA = tid >> 6;          // head of channel tid      (0 or 1)
    int hB = hA + 2;            // head of channel tid+128  (2 or 3)
    float acc0 = 0.f, acc1 = 0.f;
    float zloc[4] = {0.f, 0.f, 0.f, 0.f};

    for (int t0 = row0; t0 < row1; t0 += 128) {
        int cnt = min(128, row1 - t0);
        if (tid < cnt) {
            int s = g_esrc[t0 + tid];
            src_sh[tid] = s;
            float4 av = *(const float4*)(g_als + s * HEADS);
            float p0 = __expf(leaky(av.x + ald[0]) - m0);
            float p1 = __expf(leaky(av.y + ald[1]) - m1);
            float p2 = __expf(leaky(av.z + ald[2]) - m2);
            float p3 = __expf(leaky(av.w + ald[3]) - m3);
            p_sh[tid][0] = p0; p_sh[tid][1] = p1;
            p_sh[tid][2] = p2; p_sh[tid][3] = p3;
            zloc[0] += p0; zloc[1] += p1; zloc[2] += p2; zloc[3] += p3;
        }
        __syncthreads();
#pragma unroll 4
        for (int e = 0; e < cnt; e++) {
            int s = src_sh[e];
            const float* hrow = g_h + (long)s * HC;
            acc0 = fmaf(p_sh[e][hA], hrow[tid], acc0);
            acc1 = fmaf(p_sh[e][hB], hrow[tid + 128], acc1);
        }
        __syncthreads();
    }

    // ---- reduce softmax denominators ----
#pragma unroll
    for (int h = 0; h < 4; h++) red[tid][h] = zloc[h];
    __syncthreads();
    for (int s = 64; s > 0; s >>= 1) {
        if (tid < s)
#pragma unroll
            for (int h = 0; h < 4; h++) red[tid][h] += red[tid + s][h];
        __syncthreads();
    }
    if (tid < 4) z_sh[tid] = red[0][tid];
    __syncthreads();

    int cA = tid, cB = tid + 128;
    float v0 = acc0 / z_sh[hA] + bgat[cA];
    float v1 = acc1 / z_sh[hB] + bgat[cB];
    v0 = fmaxf(v0, 0.f);
    v1 = fmaxf(v1, 0.f);

    // ---- LayerNorm over the 256 channels ----
    __syncthreads();
    red[tid][0] = v0 + v1;
    red[tid][1] = fmaf(v0, v0, v1 * v1);
    __syncthreads();
    for (int s = 64; s > 0; s >>= 1) {
        if (tid < s) {
            red[tid][0] += red[tid + s][0];
            red[tid][1] += red[tid + s][1];
        }
        __syncthreads();
    }
    if (tid == 0) {
        float mu = red[0][0] * (1.f / 256.f);
        float var = red[0][1] * (1.f / 256.f) - mu * mu;
        stats[0] = mu;
        stats[1] = rsqrtf(var + LN_EPS);
    }
    __syncthreads();
    float mu = stats[0], rs = stats[1];
    float a0 = (v0 - mu) * rs * gamma[cA] + beta[cA];
    float a1 = (v1 - mu) * rs * gamma[cB] + beta[cB];

    // ---- project onto W_gcn (scalar per node) ----
    __syncthreads();
    red[tid][0] = fmaf(a0, wgcn[cA], a1 * wgcn[cB]);
    __syncthreads();
    for (int s = 64; s > 0; s >>= 1) {
        if (tid < s) red[tid][0] += red[tid + s][0];
        __syncthreads();
    }
    if (tid == 0) {
        g_h2[d] = red[0][0];
        g_dinv[d] = rsqrtf((float)(row1 - row0));
    }
}

// ---------------- GCN aggregation: warp per node ------------------------------
__global__ void k_gcn(const float* __restrict__ bgcn, float* __restrict__ out, int N) {
    int d = blockIdx.x * 4 + (threadIdx.x >> 5);
    int lane = threadIdx.x & 31;
    if (d >= N) return;
    int row0 = g_off[d], row1 = g_off[d + 1];
    float sum = 0.f;
    for (int i = row0 + lane; i < row1; i += 32) {
        int s = g_esrc[i];
        sum = fmaf(g_dinv[s], g_h2[s], sum);
    }
#pragma unroll
    for (int o = 16; o > 0; o >>= 1) sum += __shfl_down_sync(0xffffffffu, sum, o);
    if (lane == 0) out[d] = bgcn[0] + g_dinv[d] * sum;
}

// ---------------- launch ------------------------------------------------------
extern "C" void kernel_launch(void* const* d_in, const int* in_sizes, int n_in,
                              void* d_out, int out_size) {
    const float* x     = (const float*)d_in[0];
    const int*   ei    = (const int*)  d_in[1];
    const float* Wgat  = (const float*)d_in[2];
    const float* asrc  = (const float*)d_in[3];
    const float* adst  = (const float*)d_in[4];
    const float* bgat  = (const float*)d_in[5];
    const float* gamma = (const float*)d_in[6];
    const float* beta  = (const float*)d_in[7];
    const float* wgcn  = (const float*)d_in[8];
    const float* bgcn  = (const float*)d_in[9];
    float* out = (float*)d_out;

    int N = in_sizes[0] / IN_C;
    int E = in_sizes[1] / 2;
    const int* src = ei;
    const int* dst = ei + E;

    k_init<<<(N + 255) / 256, 256>>>(N);
    k_count<<<(E + 255) / 256, 256>>>(dst, E);
    k_scan<<<1, 1024>>>(N);
    k_scatter<<<(E + N + 255) / 256, 256>>>(src, dst, E, N);

    dim3 gb((HC + 63) / 64, (N + 63) / 64);
    k_gemm<<<gb, dim3(16, 16)>>>(x, Wgat, N);
    k_logits<<<N, 128>>>(asrc, adst, N);
    k_gat<<<N, 128>>>(bgat, gamma, beta, wgcn, N);
    k_gcn<<<(N + 3) / 4, 128>>>(bgcn, out, N);
}

// round 5
// speedup vs baseline: 1.0697x; 1.0697x over previous
#include <cuda_runtime.h>
#include <cuda_fp16.h>

#define IN_C   256
#define HC     256
#define HEADS  4
#define CPH    64
#define HC2    128          // half2 count per row
#define NMAX   10000
#define EMAX   320000
#define ETMAX  (EMAX + NMAX)
#define NEG_SLOPE 0.2f
#define LN_EPS 1e-5f

// ---------------- scratch (static device memory; no allocations) -------------
__device__ __align__(16) __half2 g_hh[NMAX * HC2]; // GAT features (fp16 pairs)
__device__ float g_als[NMAX * HEADS];   // alpha_src logits per node
__device__ float g_ald[NMAX * HEADS];   // alpha_dst logits per node
__device__ int   g_deg[NMAX];
__device__ int   g_off[NMAX + 1];
__device__ int   g_cur[NMAX];
__device__ int   g_esrc[ETMAX];         // CSR by dst: src node of each in-edge
__device__ float g_h2[NMAX];            // post-LN scalar projection
__device__ float g_dinv[NMAX];          // rsqrt(degree)

// ---------------- CSR construction -------------------------------------------
__global__ void k_init(int N) {
    int i = blockIdx.x * blockDim.x + threadIdx.x;
    if (i < N) g_deg[i] = 0;
}

__global__ void k_count(const int* __restrict__ dst, int E) {
    int i = blockIdx.x * blockDim.x + threadIdx.x;
    if (i < E) atomicAdd(&g_deg[dst[i]], 1);
}

// single-block exclusive scan of (g_deg + 1) -> g_off / g_cur
__global__ void k_scan(int N) {
    __shared__ int warp_sums[32];
    __shared__ int carry_s;
    int tid = threadIdx.x;
    int lane = tid & 31, wid = tid >> 5;
    if (tid == 0) carry_s = 0;
    __syncthreads();
    for (int base = 0; base < N; base += 1024) {
        int i = base + tid;
        int v = (i < N) ? (g_deg[i] + 1) : 0;   // +1 = self loop
        int incl = v;
#pragma unroll
        for (int s = 1; s < 32; s <<= 1) {
            int t = __shfl_up_sync(0xffffffffu, incl, s);
            if (lane >= s) incl += t;
        }
        if (lane == 31) warp_sums[wid] = incl;
        __syncthreads();
        if (wid == 0) {
            int w = warp_sums[lane];
#pragma unroll
            for (int s = 1; s < 32; s <<= 1) {
                int t = __shfl_up_sync(0xffffffffu, w, s);
                if (lane >= s) w += t;
            }
            warp_sums[lane] = w;
        }
        __syncthreads();
        int warp_base = (wid > 0) ? warp_sums[wid - 1] : 0;
        int c = carry_s;
        int incl_blk = warp_base + incl;
        if (i < N) {
            int excl = c + incl_blk - v;
            g_off[i] = excl;
            g_cur[i] = excl;
            if (i == N - 1) g_off[N] = c + incl_blk;
        }
        __syncthreads();
        if (tid == 1023) carry_s = c + incl_blk;
        __syncthreads();
    }
}

__global__ void k_scatter(const int* __restrict__ src, const int* __restrict__ dst,
                          int E, int N) {
    int i = blockIdx.x * blockDim.x + threadIdx.x;
    if (i >= E + N) return;
    int d, s;
    if (i < E) { d = dst[i]; s = src[i]; }
    else       { d = i - E;  s = i - E;  }   // self loop
    int pos = atomicAdd(&g_cur[d], 1);
    g_esrc[pos] = s;
}

// ---- SGEMM 128x128 tile, 256 thr, 8x8/thr; fused logits + fp16 h store ------
__global__ void __launch_bounds__(256) k_gemm(const float* __restrict__ X,
                                              const float* __restrict__ W,
                                              const float* __restrict__ asrc,
                                              const float* __restrict__ adst,
                                              int N) {
    __shared__ float As[16][128];   // As[k][m]
    __shared__ float Bs[16][128];   // Bs[k][n]
    int tid = threadIdx.x;
    int tx = tid & 15, ty = tid >> 4;
    int m0 = blockIdx.y * 128, n0 = blockIdx.x * 128;

    float acc[8][8];
#pragma unroll
    for (int i = 0; i < 8; i++)
#pragma unroll
        for (int j = 0; j < 8; j++) acc[i][j] = 0.f;

    for (int k0 = 0; k0 < IN_C; k0 += 16) {
        {   // A tile: 128 rows x 16 k -> transposed into As
            int r = tid >> 1, kq = (tid & 1) * 8;
            int row = m0 + r;
            float4 v0, v1;
            if (row < N) {
                const float* p = X + (long)row * IN_C + k0 + kq;
                v0 = *(const float4*)p;
                v1 = *(const float4*)(p + 4);
            } else {
                v0 = make_float4(0.f, 0.f, 0.f, 0.f);
                v1 = v0;
            }
            As[kq + 0][r] = v0.x; As[kq + 1][r] = v0.y;
            As[kq + 2][r] = v0.z; As[kq + 3][r] = v0.w;
            As[kq + 4][r] = v1.x; As[kq + 5][r] = v1.y;
            As[kq + 6][r] = v1.z; As[kq + 7][r] = v1.w;
        }
        {   // B tile: 16 k x 128 n
            int kk = tid >> 4, c = (tid & 15) * 8;
            const float* p = W + (long)(k0 + kk) * HC + n0 + c;
            *(float4*)&Bs[kk][c]     = *(const float4*)p;
            *(float4*)&Bs[kk][c + 4] = *(const float4*)(p + 4);
        }
        __syncthreads();
#pragma unroll
        for (int kk = 0; kk < 16; kk++) {
            float4 a0 = *(float4*)&As[kk][ty * 8];
            float4 a1 = *(float4*)&As[kk][ty * 8 + 4];
            float4 b0 = *(float4*)&Bs[kk][tx * 8];
            float4 b1 = *(float4*)&Bs[kk][tx * 8 + 4];
            float a[8] = {a0.x, a0.y, a0.z, a0.w, a1.x, a1.y, a1.z, a1.w};
            float b[8] = {b0.x, b0.y, b0.z, b0.w, b1.x, b1.y, b1.z, b1.w};
#pragma unroll
            for (int i = 0; i < 8; i++)
#pragma unroll
                for (int j = 0; j < 8; j++)
                    acc[i][j] = fmaf(a[i], b[j], acc[i][j]);
        }
        __syncthreads();
    }

    // ---- epilogue: fp16 store + fused attention-logit partial reduction ----
    // This block's 128 cols = heads {bx*2, bx*2+1}; thread tx covers head tx>>3.
    int head = blockIdx.x * 2 + (tx >> 3);
    int cbase = (tx & 7) * 8;               // col offset within the head
    float as_[8], ad_[8];
#pragma unroll
    for (int j = 0; j < 8; j++) {
        as_[j] = asrc[head * CPH + cbase + j];
        ad_[j] = adst[head * CPH + cbase + j];
    }

#pragma unroll
    for (int i = 0; i < 8; i++) {
        int row = m0 + ty * 8 + i;
        // fp16 feature store (4 x half2 = 16B)
        if (row < N) {
            __half2 hp[4];
#pragma unroll
            for (int p = 0; p < 4; p++)
                hp[p] = __floats2half2_rn(acc[i][2 * p], acc[i][2 * p + 1]);
            *(uint4*)&g_hh[(long)row * HC2 + (n0 >> 1) + tx * 4] = *(uint4*)hp;
        }
        // logit partial: dot of this thread's 8 cols with a_src / a_dst
        float ps = 0.f, pd = 0.f;
#pragma unroll
        for (int j = 0; j < 8; j++) {
            ps = fmaf(acc[i][j], as_[j], ps);
            pd = fmaf(acc[i][j], ad_[j], pd);
        }
#pragma unroll
        for (int o = 4; o > 0; o >>= 1) {
            ps += __shfl_down_sync(0xffffffffu, ps, o);
            pd += __shfl_down_sync(0xffffffffu, pd, o);
        }
        if ((tx & 7) == 0 && row < N) {
            g_als[row * HEADS + head] = ps;
            g_ald[row * HEADS + head] = pd;
        }
    }
}

__device__ __forceinline__ float leaky(float v) {
    return v > 0.f ? v : NEG_SLOPE * v;
}

// ---------------- fused GAT aggregation + bias + ReLU + LN + GCN proj ---------
__global__ void __launch_bounds__(128) k_gat(const float* __restrict__ bgat,
                                             const float* __restrict__ gamma,
                                             const float* __restrict__ beta,
                                             const float* __restrict__ wgcn,
                                             int N) {
    int d = blockIdx.x;
    int tid = threadIdx.x;               // thread -> half2 index tid (channels 2t,2t+1)
    int head = tid >> 5;                 // 32 half2 per head
    int row0 = g_off[d], row1 = g_off[d + 1];

    float4 aldv = *(const float4*)(g_ald + d * HEADS);
    float ald[4] = {aldv.x, aldv.y, aldv.z, aldv.w};

    __shared__ float p_sh[128][4];
    __shared__ int   src_sh[128];
    __shared__ float red[128][4];
    __shared__ float z_sh[4];
    __shared__ float stats[2];

    float accx = 0.f, accy = 0.f;
    float zloc[4] = {0.f, 0.f, 0.f, 0.f};

    // single pass: softmax numerators (no max shift; logits are O(10)) + gather
    for (int t0 = row0; t0 < row1; t0 += 128) {
        int cnt = min(128, row1 - t0);
        if (tid < cnt) {
            int s = g_esrc[t0 + tid];
            src_sh[tid] = s;
            float4 av = *(const float4*)(g_als + s * HEADS);
            float p0 = __expf(leaky(av.x + ald[0]));
            float p1 = __expf(leaky(av.y + ald[1]));
            float p2 = __expf(leaky(av.z + ald[2]));
            float p3 = __expf(leaky(av.w + ald[3]));
            p_sh[tid][0] = p0; p_sh[tid][1] = p1;
            p_sh[tid][2] = p2; p_sh[tid][3] = p3;
            zloc[0] += p0; zloc[1] += p1; zloc[2] += p2; zloc[3] += p3;
        }
        __syncthreads();
#pragma unroll 4
        for (int e = 0; e < cnt; e++) {
            int s = src_sh[e];
            float2 hv = __half22float2(g_hh[(long)s * HC2 + tid]);
            float p = p_sh[e][head];
            accx = fmaf(p, hv.x, accx);
            accy = fmaf(p, hv.y, accy);
        }
        __syncthreads();
    }

    // ---- reduce softmax denominators across the block ----
#pragma unroll
    for (int h = 0; h < 4; h++) red[tid][h] = zloc[h];
    __syncthreads();
    for (int s = 64; s > 0; s >>= 1) {
        if (tid < s)
#pragma unroll
            for (int h = 0; h < 4; h++) red[tid][h] += red[tid + s][h];
        __syncthreads();
    }
    if (tid < 4) z_sh[tid] = red[0][tid];
    __syncthreads();

    int c0 = 2 * tid, c1 = 2 * tid + 1;
    float zinv = 1.f / z_sh[head];
    float v0 = fmaxf(accx * zinv + bgat[c0], 0.f);
    float v1 = fmaxf(accy * zinv + bgat[c1], 0.f);

    // ---- LayerNorm over 256 channels ----
    __syncthreads();
    red[tid][0] = v0 + v1;
    red[tid][1] = fmaf(v0, v0, v1 * v1);
    __syncthreads();
    for (int s = 64; s > 0; s >>= 1) {
        if (tid < s) {
            red[tid][0] += red[tid + s][0];
            red[tid][1] += red[tid + s][1];
        }
        __syncthreads();
    }
    if (tid == 0) {
        float mu = red[0][0] * (1.f / 256.f);
        float var = red[0][1] * (1.f / 256.f) - mu * mu;
        stats[0] = mu;
        stats[1] = rsqrtf(var + LN_EPS);
    }
    __syncthreads();
    float mu = stats[0], rs = stats[1];
    float a0 = (v0 - mu) * rs * gamma[c0] + beta[c0];
    float a1 = (v1 - mu) * rs * gamma[c1] + beta[c1];

    // ---- project onto W_gcn (scalar per node) ----
    __syncthreads();
    red[tid][0] = fmaf(a0, wgcn[c0], a1 * wgcn[c1]);
    __syncthreads();
    for (int s = 64; s > 0; s >>= 1) {
        if (tid < s) red[tid][0] += red[tid + s][0];
        __syncthreads();
    }
    if (tid == 0) {
        g_h2[d] = red[0][0];
        g_dinv[d] = rsqrtf((float)(row1 - row0));
    }
}

// ---------------- GCN aggregation: warp per node ------------------------------
__global__ void k_gcn(const float* __restrict__ bgcn, float* __restrict__ out, int N) {
    int d = blockIdx.x * 4 + (threadIdx.x >> 5);
    int lane = threadIdx.x & 31;
    if (d >= N) return;
    int row0 = g_off[d], row1 = g_off[d + 1];
    float sum = 0.f;
    for (int i = row0 + lane; i < row1; i += 32) {
        int s = g_esrc[i];
        sum = fmaf(g_dinv[s], g_h2[s], sum);
    }
#pragma unroll
    for (int o = 16; o > 0; o >>= 1) sum += __shfl_down_sync(0xffffffffu, sum, o);
    if (lane == 0) out[d] = bgcn[0] + g_dinv[d] * sum;
}

// ---------------- launch ------------------------------------------------------
extern "C" void kernel_launch(void* const* d_in, const int* in_sizes, int n_in,
                              void* d_out, int out_size) {
    const float* x     = (const float*)d_in[0];
    const int*   ei    = (const int*)  d_in[1];
    const float* Wgat  = (const float*)d_in[2];
    const float* asrc  = (const float*)d_in[3];
    const float* adst  = (const float*)d_in[4];
    const float* bgat  = (const float*)d_in[5];
    const float* gamma = (const float*)d_in[6];
    const float* beta  = (const float*)d_in[7];
    const float* wgcn  = (const float*)d_in[8];
    const float* bgcn  = (const float*)d_in[9];
    float* out = (float*)d_out;

    int N = in_sizes[0] / IN_C;
    int E = in_sizes[1] / 2;
    const int* src = ei;
    const int* dst = ei + E;

    k_init<<<(N + 255) / 256, 256>>>(N);
    k_count<<<(E + 255) / 256, 256>>>(dst, E);
    k_scan<<<1, 1024>>>(N);
    k_scatter<<<(E + N + 255) / 256, 256>>>(src, dst, E, N);

    dim3 gb(HC / 128, (N + 127) / 128);
    k_gemm<<<gb, 256>>>(x, Wgat, asrc, adst, N);
    k_gat<<<N, 128>>>(bgat, gamma, beta, wgcn, N);
    k_gcn<<<(N + 3) / 4, 128>>>(bgcn, out, N);
}

// round 6
// speedup vs baseline: 1.1487x; 1.0739x over previous
#include <cuda_runtime.h>
#include <cuda_fp16.h>

#define IN_C   256
#define HC     256
#define HEADS  4
#define CPH    64
#define HC2    128          // half2 count per row
#define NMAX   10000
#define EMAX   320000
#define ETMAX  (EMAX + NMAX)
#define NEG_SLOPE 0.2f
#define LN_EPS 1e-5f

// ---------------- scratch (static device memory; no allocations) -------------
__device__ __align__(16) __half2 g_hh[NMAX * HC2]; // GAT features (fp16 pairs)
__device__ float  g_als[NMAX * HEADS];
__device__ float  g_ald[NMAX * HEADS];
__device__ int    g_deg[NMAX];
__device__ int    g_off[NMAX + 1];
__device__ int    g_cur[NMAX];
__device__ int    g_esrc[ETMAX];       // CSR by dst: src node of each in-edge
__device__ float2 g_dh[NMAX];          // {dinv, h2} packed

// ---------------- CSR construction -------------------------------------------
__global__ void k_count(const int* __restrict__ dst, int E) {
    int i0 = (blockIdx.x * blockDim.x + threadIdx.x) * 4;
    if (i0 + 3 < E) {
        int4 d4 = *(const int4*)(dst + i0);
        atomicAdd(&g_deg[d4.x], 1);
        atomicAdd(&g_deg[d4.y], 1);
        atomicAdd(&g_deg[d4.z], 1);
        atomicAdd(&g_deg[d4.w], 1);
    } else {
        for (int j = 0; j < 4; j++) {
            int i = i0 + j;
            if (i < E) atomicAdd(&g_deg[dst[i]], 1);
        }
    }
}

// single-block exclusive scan of (g_deg + 1) -> g_off / g_cur
__global__ void k_scan(int N) {
    __shared__ int warp_sums[32];
    __shared__ int carry_s;
    int tid = threadIdx.x;
    int lane = tid & 31, wid = tid >> 5;
    if (tid == 0) carry_s = 0;
    __syncthreads();
    for (int base = 0; base < N; base += 1024) {
        int i = base + tid;
        int v = (i < N) ? (g_deg[i] + 1) : 0;   // +1 = self loop
        int incl = v;
#pragma unroll
        for (int s = 1; s < 32; s <<= 1) {
            int t = __shfl_up_sync(0xffffffffu, incl, s);
            if (lane >= s) incl += t;
        }
        if (lane == 31) warp_sums[wid] = incl;
        __syncthreads();
        if (wid == 0) {
            int w = warp_sums[lane];
#pragma unroll
            for (int s = 1; s < 32; s <<= 1) {
                int t = __shfl_up_sync(0xffffffffu, w, s);
                if (lane >= s) w += t;
            }
            warp_sums[lane] = w;
        }
        __syncthreads();
        int warp_base = (wid > 0) ? warp_sums[wid - 1] : 0;
        int c = carry_s;
        int incl_blk = warp_base + incl;
        if (i < N) {
            int excl = c + incl_blk - v;
            g_off[i] = excl;
            g_cur[i] = excl;
            if (i == N - 1) g_off[N] = c + incl_blk;
        }
        __syncthreads();
        if (tid == 1023) carry_s = c + incl_blk;
        __syncthreads();
    }
}

__global__ void k_scatter(const int* __restrict__ src, const int* __restrict__ dst,
                          int E, int N) {
    int i0 = (blockIdx.x * blockDim.x + threadIdx.x) * 4;
    if (i0 + 3 < E) {
        int4 s4 = *(const int4*)(src + i0);
        int4 d4 = *(const int4*)(dst + i0);
        int p0 = atomicAdd(&g_cur[d4.x], 1);
        int p1 = atomicAdd(&g_cur[d4.y], 1);
        int p2 = atomicAdd(&g_cur[d4.z], 1);
        int p3 = atomicAdd(&g_cur[d4.w], 1);
        g_esrc[p0] = s4.x; g_esrc[p1] = s4.y;
        g_esrc[p2] = s4.z; g_esrc[p3] = s4.w;
    } else {
        for (int j = 0; j < 4; j++) {
            int i = i0 + j;
            if (i >= E + N) break;
            int d, s;
            if (i < E) { d = dst[i]; s = src[i]; }
            else       { d = i - E;  s = i - E;  }   // self loop
            int pos = atomicAdd(&g_cur[d], 1);
            g_esrc[pos] = s;
        }
    }
}

// ---- SGEMM 64x64 tile, 256 thr, 4x4/thr; fused logits + fp16 h store --------
// Each 64-col block covers exactly one head.
__global__ void __launch_bounds__(256) k_gemm(const float* __restrict__ X,
                                              const float* __restrict__ W,
                                              const float* __restrict__ asrc,
                                              const float* __restrict__ adst,
                                              int N) {
    __shared__ float As[16][64];   // As[k][m]
    __shared__ float Bs[16][64];   // Bs[k][n]
    int tid = threadIdx.x;
    int tx = tid & 15, ty = tid >> 4;
    int m0 = blockIdx.y * 64, n0 = blockIdx.x * 64;

    float acc[4][4];
#pragma unroll
    for (int i = 0; i < 4; i++)
#pragma unroll
        for (int j = 0; j < 4; j++) acc[i][j] = 0.f;

    for (int k0 = 0; k0 < IN_C; k0 += 16) {
        {   // A tile: 64 rows x 16 k -> transposed
            int r = tid >> 2, ks = (tid & 3) * 4;
            int row = m0 + r;
            float4 v = (row < N) ? *(const float4*)(X + (long)row * IN_C + k0 + ks)
                                 : make_float4(0.f, 0.f, 0.f, 0.f);
            As[ks + 0][r] = v.x; As[ks + 1][r] = v.y;
            As[ks + 2][r] = v.z; As[ks + 3][r] = v.w;
        }
        {   // B tile: 16 k x 64 n
            int kk = tid >> 4, c = (tid & 15) * 4;
            *(float4*)&Bs[kk][c] = *(const float4*)(W + (long)(k0 + kk) * HC + n0 + c);
        }
        __syncthreads();
#pragma unroll
        for (int kk = 0; kk < 16; kk++) {
            float4 av = *(float4*)&As[kk][ty * 4];
            float4 bv = *(float4*)&Bs[kk][tx * 4];
            float a[4] = {av.x, av.y, av.z, av.w};
            float b[4] = {bv.x, bv.y, bv.z, bv.w};
#pragma unroll
            for (int i = 0; i < 4; i++)
#pragma unroll
                for (int j = 0; j < 4; j++)
                    acc[i][j] = fmaf(a[i], b[j], acc[i][j]);
        }
        __syncthreads();
    }

    // ---- epilogue: fp16 store + fused attention-logit reduction -------------
    int head = blockIdx.x;                  // 64 cols == one head
    float as_[4], ad_[4];
#pragma unroll
    for (int j = 0; j < 4; j++) {
        as_[j] = asrc[head * CPH + tx * 4 + j];
        ad_[j] = adst[head * CPH + tx * 4 + j];
    }

#pragma unroll
    for (int i = 0; i < 4; i++) {
        int row = m0 + ty * 4 + i;
        if (row < N) {
            __half2 hp[2];
            hp[0] = __floats2half2_rn(acc[i][0], acc[i][1]);
            hp[1] = __floats2half2_rn(acc[i][2], acc[i][3]);
            *(uint2*)&g_hh[(long)row * HC2 + head * 32 + tx * 2] = *(uint2*)hp;
        }
        float ps = 0.f, pd = 0.f;
#pragma unroll
        for (int j = 0; j < 4; j++) {
            ps = fmaf(acc[i][j], as_[j], ps);
            pd = fmaf(acc[i][j], ad_[j], pd);
        }
        // reduce over the 16 lanes (tx) sharing this row
#pragma unroll
        for (int o = 8; o > 0; o >>= 1) {
            ps += __shfl_down_sync(0xffffffffu, ps, o, 16);
            pd += __shfl_down_sync(0xffffffffu, pd, o, 16);
        }
        if (tx == 0 && row < N) {
            g_als[row * HEADS + head] = ps;
            g_ald[row * HEADS + head] = pd;
        }
    }
}

__device__ __forceinline__ float leaky(float v) {
    return v > 0.f ? v : NEG_SLOPE * v;
}

// ---------------- fused GAT aggregation + bias + ReLU + LN + GCN proj ---------
__global__ void __launch_bounds__(128) k_gat(const float* __restrict__ bgat,
                                             const float* __restrict__ gamma,
                                             const float* __restrict__ beta,
                                             const float* __restrict__ wgcn,
                                             int N) {
    int d = blockIdx.x;
    int tid = threadIdx.x;               // thread -> half2 index (channels 2t,2t+1)
    int head = tid >> 5;                 // 32 half2 per head
    int row0 = g_off[d], row1 = g_off[d + 1];

    float4 aldv = *(const float4*)(g_ald + d * HEADS);
    float ald[4] = {aldv.x, aldv.y, aldv.z, aldv.w};

    __shared__ float p_sh[128][4];
    __shared__ int   src_sh[128];
    __shared__ float red[128][4];
    __shared__ float z_sh[4];
    __shared__ float stats[2];

    float accx = 0.f, accy = 0.f;
    float zloc[4] = {0.f, 0.f, 0.f, 0.f};

    // single pass: softmax numerators (no max shift; logits are O(10)) + gather
    for (int t0 = row0; t0 < row1; t0 += 128) {
        int cnt = min(128, row1 - t0);
        if (tid < cnt) {
            int s = g_esrc[t0 + tid];
            src_sh[tid] = s;
            float4 av = *(const float4*)(g_als + s * HEADS);
            float p0 = __expf(leaky(av.x + ald[0]));
            float p1 = __expf(leaky(av.y + ald[1]));
            float p2 = __expf(leaky(av.z + ald[2]));
            float p3 = __expf(leaky(av.w + ald[3]));
            p_sh[tid][0] = p0; p_sh[tid][1] = p1;
            p_sh[tid][2] = p2; p_sh[tid][3] = p3;
            zloc[0] += p0; zloc[1] += p1; zloc[2] += p2; zloc[3] += p3;
        }
        __syncthreads();
#pragma unroll 4
        for (int e = 0; e < cnt; e++) {
            int s = src_sh[e];
            float2 hv = __half22float2(g_hh[(long)s * HC2 + tid]);
            float p = p_sh[e][head];
            accx = fmaf(p, hv.x, accx);
            accy = fmaf(p, hv.y, accy);
        }
        __syncthreads();
    }

    // ---- reduce softmax denominators across the block ----
#pragma unroll
    for (int h = 0; h < 4; h++) red[tid][h] = zloc[h];
    __syncthreads();
    for (int s = 64; s > 0; s >>= 1) {
        if (tid < s)
#pragma unroll
            for (int h = 0; h < 4; h++) red[tid][h] += red[tid + s][h];
        __syncthreads();
    }
    if (tid < 4) z_sh[tid] = red[0][tid];
    __syncthreads();

    int c0 = 2 * tid, c1 = 2 * tid + 1;
    float zinv = 1.f / z_sh[head];
    float v0 = fmaxf(accx * zinv + bgat[c0], 0.f);
    float v1 = fmaxf(accy * zinv + bgat[c1], 0.f);

    // ---- LayerNorm over 256 channels ----
    __syncthreads();
    red[tid][0] = v0 + v1;
    red[tid][1] = fmaf(v0, v0, v1 * v1);
    __syncthreads();
    for (int s = 64; s > 0; s >>= 1) {
        if (tid < s) {
            red[tid][0] += red[tid + s][0];
            red[tid][1] += red[tid + s][1];
        }
        __syncthreads();
    }
    if (tid == 0) {
        float mu = red[0][0] * (1.f / 256.f);
        float var = red[0][1] * (1.f / 256.f) - mu * mu;
        stats[0] = mu;
        stats[1] = rsqrtf(var + LN_EPS);
    }
    __syncthreads();
    float mu = stats[0], rs = stats[1];
    float a0 = (v0 - mu) * rs * gamma[c0] + beta[c0];
    float a1 = (v1 - mu) * rs * gamma[c1] + beta[c1];

    // ---- project onto W_gcn (scalar per node) ----
    __syncthreads();
    red[tid][0] = fmaf(a0, wgcn[c0], a1 * wgcn[c1]);
    __syncthreads();
    for (int s = 64; s > 0; s >>= 1) {
        if (tid < s) red[tid][0] += red[tid + s][0];
        __syncthreads();
    }
    if (tid == 0) {
        g_dh[d] = make_float2(rsqrtf((float)(row1 - row0)), red[0][0]);
    }
}

// ---------------- GCN aggregation: warp per node ------------------------------
__global__ void k_gcn(const float* __restrict__ bgcn, float* __restrict__ out, int N) {
    int d = blockIdx.x * 4 + (threadIdx.x >> 5);
    int lane = threadIdx.x & 31;
    if (d >= N) return;
    int row0 = g_off[d], row1 = g_off[d + 1];
    float sum = 0.f;
    for (int i = row0 + lane; i < row1; i += 32) {
        float2 dh = g_dh[g_esrc[i]];
        sum = fmaf(dh.x, dh.y, sum);
    }
#pragma unroll
    for (int o = 16; o > 0; o >>= 1) sum += __shfl_down_sync(0xffffffffu, sum, o);
    if (lane == 0) out[d] = bgcn[0] + g_dh[d].x * sum;
}

// ---------------- launch ------------------------------------------------------
extern "C" void kernel_launch(void* const* d_in, const int* in_sizes, int n_in,
                              void* d_out, int out_size) {
    const float* x     = (const float*)d_in[0];
    const int*   ei    = (const int*)  d_in[1];
    const float* Wgat  = (const float*)d_in[2];
    const float* asrc  = (const float*)d_in[3];
    const float* adst  = (const float*)d_in[4];
    const float* bgat  = (const float*)d_in[5];
    const float* gamma = (const float*)d_in[6];
    const float* beta  = (const float*)d_in[7];
    const float* wgcn  = (const float*)d_in[8];
    const float* bgcn  = (const float*)d_in[9];
    float* out = (float*)d_out;

    int N = in_sizes[0] / IN_C;
    int E = in_sizes[1] / 2;
    const int* src = ei;
    const int* dst = ei + E;

    void* degp = nullptr;
    cudaGetSymbolAddress(&degp, g_deg);
    cudaMemsetAsync(degp, 0, N * sizeof(int));

    k_count<<<(E + 1023) / 1024, 256>>>(dst, E);
    k_scan<<<1, 1024>>>(N);
    k_scatter<<<(E + N + 1023) / 1024, 256>>>(src, dst, E, N);

    dim3 gb(HC / 64, (N + 63) / 64);
    k_gemm<<<gb, 256>>>(x, Wgat, asrc, adst, N);
    k_gat<<<N, 128>>>(bgat, gamma, beta, wgcn, N);
    k_gcn<<<(N + 3) / 4, 128>>>(bgcn, out, N);
}

// round 8
// speedup vs baseline: 1.3286x; 1.1566x over previous
#include <cuda_runtime.h>
#include <cuda_fp16.h>

#define IN_C   256
#define HC     256
#define HEADS  4
#define CPH    64
#define HC2    128          // half2 count per row
#define NMAX   10000
#define EMAX   320000
#define ETMAX  (EMAX + NMAX)
#define NEG_SLOPE 0.2f
#define LN_EPS 1e-5f

// ---------------- scratch (static device memory; no allocations) -------------
__device__ __align__(16) __half2 g_hh[NMAX * HC2]; // GAT features (fp16 pairs)
__device__ __align__(16) __half  g_wt[HC * IN_C];  // W_gat^T in fp16: [n][k]
__device__ float  g_als[NMAX * HEADS];
__device__ float  g_ald[NMAX * HEADS];
__device__ int    g_deg[NMAX];
__device__ int    g_off[NMAX + 1];
__device__ int    g_cur[NMAX];
__device__ int    g_esrc[ETMAX];       // CSR by dst: src node of each in-edge
__device__ float2 g_dh[NMAX];          // {dinv, h2} packed

// ---------------- CSR construction -------------------------------------------
__global__ void k_count(const int* __restrict__ dst, int E) {
    int i0 = (blockIdx.x * blockDim.x + threadIdx.x) * 4;
    if (i0 + 3 < E) {
        int4 d4 = *(const int4*)(dst + i0);
        atomicAdd(&g_deg[d4.x], 1);
        atomicAdd(&g_deg[d4.y], 1);
        atomicAdd(&g_deg[d4.z], 1);
        atomicAdd(&g_deg[d4.w], 1);
    } else {
        for (int j = 0; j < 4; j++) {
            int i = i0 + j;
            if (i < E) atomicAdd(&g_deg[dst[i]], 1);
        }
    }
}

// single-block exclusive scan of (g_deg + 1) -> g_off / g_cur
__global__ void k_scan(int N) {
    __shared__ int warp_sums[32];
    __shared__ int carry_s;
    int tid = threadIdx.x;
    int lane = tid & 31, wid = tid >> 5;
    if (tid == 0) carry_s = 0;
    __syncthreads();
    for (int base = 0; base < N; base += 1024) {
        int i = base + tid;
        int v = (i < N) ? (g_deg[i] + 1) : 0;   // +1 = self loop
        int incl = v;
#pragma unroll
        for (int s = 1; s < 32; s <<= 1) {
            int t = __shfl_up_sync(0xffffffffu, incl, s);
            if (lane >= s) incl += t;
        }
        if (lane == 31) warp_sums[wid] = incl;
        __syncthreads();
        if (wid == 0) {
            int w = warp_sums[lane];
#pragma unroll
            for (int s = 1; s < 32; s <<= 1) {
                int t = __shfl_up_sync(0xffffffffu, w, s);
                if (lane >= s) w += t;
            }
            warp_sums[lane] = w;
        }
        __syncthreads();
        int warp_base = (wid > 0) ? warp_sums[wid - 1] : 0;
        int c = carry_s;
        int incl_blk = warp_base + incl;
        if (i < N) {
            int excl = c + incl_blk - v;
            g_off[i] = excl;
            g_cur[i] = excl;
            if (i == N - 1) g_off[N] = c + incl_blk;
        }
        __syncthreads();
        if (tid == 1023) carry_s = c + incl_blk;
        __syncthreads();
    }
}

__global__ void k_scatter(const int* __restrict__ src, const int* __restrict__ dst,
                          int E, int N) {
    int i0 = (blockIdx.x * blockDim.x + threadIdx.x) * 4;
    if (i0 + 3 < E) {
        int4 s4 = *(const int4*)(src + i0);
        int4 d4 = *(const int4*)(dst + i0);
        int p0 = atomicAdd(&g_cur[d4.x], 1);
        int p1 = atomicAdd(&g_cur[d4.y], 1);
        int p2 = atomicAdd(&g_cur[d4.z], 1);
        int p3 = atomicAdd(&g_cur[d4.w], 1);
        g_esrc[p0] = s4.x; g_esrc[p1] = s4.y;
        g_esrc[p2] = s4.z; g_esrc[p3] = s4.w;
    } else {
        for (int j = 0; j < 4; j++) {
            int i = i0 + j;
            if (i >= E + N) break;
            int d, s;
            if (i < E) { d = dst[i]; s = src[i]; }
            else       { d = i - E;  s = i - E;  }   // self loop
            int pos = atomicAdd(&g_cur[d], 1);
            g_esrc[pos] = s;
        }
    }
}

// ---------------- W_gat -> fp16 transpose: g_wt[n][k] -------------------------
__global__ void k_wt(const float* __restrict__ W) {
    int idx = blockIdx.x * 256 + threadIdx.x;   // 65536 total
    int k = idx >> 8, n = idx & 255;
    g_wt[n * IN_C + k] = __float2half(W[k * HC + n]);
}

// ---------------- tensor-core GEMM + fused logits + fp16 h store --------------
// 64x64 tile, 128 threads (4 warps, 2x2), m16n8k16 fp16 mma, fp32 accumulate.
// XOR-swizzled smem: unit(r,c) = r*8 + (c ^ (r&7)), 16B units, 8 units/row.
__device__ __forceinline__ void mma16816(float* c, const unsigned* a, const unsigned* b) {
    asm volatile("mma.sync.aligned.m16n8k16.row.col.f32.f16.f16.f32 "
                 "{%0,%1,%2,%3}, {%4,%5,%6,%7}, {%8,%9}, {%0,%1,%2,%3};"
                 : "+f"(c[0]), "+f"(c[1]), "+f"(c[2]), "+f"(c[3])
                 : "r"(a[0]), "r"(a[1]), "r"(a[2]), "r"(a[3]),
                   "r"(b[0]), "r"(b[1]));
}

__global__ void __launch_bounds__(128) k_gemm(const float* __restrict__ X,
                                              const float* __restrict__ asrc,
                                              const float* __restrict__ adst,
                                              int N) {
    __shared__ __align__(16) __half As[64 * 64];
    __shared__ __align__(16) __half Bs[64 * 64];
    __shared__ float part_s[64], part_d[64];   // cross-warp logit partials
    int tid = threadIdx.x;
    int lane = tid & 31, w = tid >> 5;
    int wm = w >> 1, wn = w & 1;
    int head = blockIdx.x;               // 64 cols == one head
    int mblk = blockIdx.y * 64;
    unsigned asb = (unsigned)__cvta_generic_to_shared(As);
    unsigned bsb = (unsigned)__cvta_generic_to_shared(Bs);

    float c[2][4][4];
#pragma unroll
    for (int i = 0; i < 2; i++)
#pragma unroll
        for (int j = 0; j < 4; j++)
#pragma unroll
            for (int q = 0; q < 4; q++) c[i][j][q] = 0.f;

    for (int s = 0; s < 4; s++) {
        int k0 = s * 64;
        {   // A tile: 64 rows x 64 k, fp32 global -> fp16 swizzled smem
            int r = tid >> 1;
            int cu0 = (tid & 1) * 4;
            int row = mblk + r;
#pragma unroll
            for (int u = 0; u < 4; u++) {
                int cc = cu0 + u;
                __half hbuf[8];
                if (row < N) {
                    const float* p = X + (long)row * IN_C + k0 + cc * 8;
                    float4 v0 = *(const float4*)p;
                    float4 v1 = *(const float4*)(p + 4);
                    hbuf[0] = __float2half(v0.x); hbuf[1] = __float2half(v0.y);
                    hbuf[2] = __float2half(v0.z); hbuf[3] = __float2half(v0.w);
                    hbuf[4] = __float2half(v1.x); hbuf[5] = __float2half(v1.y);
                    hbuf[6] = __float2half(v1.z); hbuf[7] = __float2half(v1.w);
                } else {
#pragma unroll
                    for (int q = 0; q < 8; q++) hbuf[q] = __float2half(0.f);
                }
                int unit = r * 8 + (cc ^ (r & 7));
                *(uint4*)((char*)As + unit * 16) = *(uint4*)hbuf;
            }
        }
        {   // B tile: 64 n-rows x 64 k from g_wt (fp16)
            int r = tid >> 1;
            int cu0 = (tid & 1) * 4;
            const __half* p = g_wt + (long)(head * 64 + r) * IN_C + k0;
#pragma unroll
            for (int u = 0; u < 4; u++) {
                int cc = cu0 + u;
                uint4 v = *(const uint4*)(p + cc * 8);
                int unit = r * 8 + (cc ^ (r & 7));
                *(uint4*)((char*)Bs + unit * 16) = v;
            }
        }
        __syncthreads();

#pragma unroll
        for (int kk = 0; kk < 4; kk++) {
            unsigned af[2][4], bf[4][2];
#pragma unroll
            for (int i = 0; i < 2; i++) {
                int r = wm * 32 + i * 16 + (lane & 15);
                int cc = 2 * kk + (lane >> 4);
                int unit = r * 8 + (cc ^ (r & 7));
                unsigned addr = asb + unit * 16;
                asm volatile("ldmatrix.sync.aligned.m8n8.x4.shared.b16 "
                             "{%0,%1,%2,%3}, [%4];"
                             : "=r"(af[i][0]), "=r"(af[i][1]),
                               "=r"(af[i][2]), "=r"(af[i][3])
                             : "r"(addr));
            }
#pragma unroll
            for (int j = 0; j < 4; j++) {
                int l = lane & 15;
                int r = wn * 32 + j * 8 + (l & 7);
                int cc = 2 * kk + (l >> 3);
                int unit = r * 8 + (cc ^ (r & 7));
                unsigned addr = bsb + unit * 16;
                asm volatile("ldmatrix.sync.aligned.m8n8.x2.shared.b16 "
                             "{%0,%1}, [%2];"
                             : "=r"(bf[j][0]), "=r"(bf[j][1])
                             : "r"(addr));
            }
#pragma unroll
            for (int i = 0; i < 2; i++)
#pragma unroll
                for (int j = 0; j < 4; j++)
                    mma16816(c[i][j], af[i], bf[j]);
        }
        __syncthreads();
    }

    // ---- epilogue: fp16 h store + fused logit reduction ----------------------
    // Each row's 64 head-cols are split across wn=0 (cols 0-31) and wn=1
    // (cols 32-63): reduce within warp over tq lanes, then across wn via smem.
    int grp = lane >> 2, tq = lane & 3;
    float as0[4], as1[4], ad0[4], ad1[4];
#pragma unroll
    for (int j = 0; j < 4; j++) {
        int col = wn * 32 + j * 8 + 2 * tq;
        as0[j] = asrc[head * CPH + col];     as1[j] = asrc[head * CPH + col + 1];
        ad0[j] = adst[head * CPH + col];     ad1[j] = adst[head * CPH + col + 1];
    }

#pragma unroll
    for (int i = 0; i < 2; i++) {
        int lr0 = wm * 32 + i * 16 + grp;     // row within block tile
        int lr1 = lr0 + 8;
        int r0 = mblk + lr0;
        int r1 = mblk + lr1;
        float ps0 = 0.f, pd0 = 0.f, ps1 = 0.f, pd1 = 0.f;
#pragma unroll
        for (int j = 0; j < 4; j++) {
            ps0 = fmaf(c[i][j][0], as0[j], fmaf(c[i][j][1], as1[j], ps0));
            pd0 = fmaf(c[i][j][0], ad0[j], fmaf(c[i][j][1], ad1[j], pd0));
            ps1 = fmaf(c[i][j][2], as0[j], fmaf(c[i][j][3], as1[j], ps1));
            pd1 = fmaf(c[i][j][2], ad0[j], fmaf(c[i][j][3], ad1[j], pd1));
            int gcol = head * 64 + wn * 32 + j * 8 + 2 * tq;
            if (r0 < N)
                g_hh[(long)r0 * HC2 + (gcol >> 1)] =
                    __floats2half2_rn(c[i][j][0], c[i][j][1]);
            if (r1 < N)
                g_hh[(long)r1 * HC2 + (gcol >> 1)] =
                    __floats2half2_rn(c[i][j][2], c[i][j][3]);
        }
#pragma unroll
        for (int o = 1; o < 4; o <<= 1) {
            ps0 += __shfl_xor_sync(0xffffffffu, ps0, o);
            pd0 += __shfl_xor_sync(0xffffffffu, pd0, o);
            ps1 += __shfl_xor_sync(0xffffffffu, ps1, o);
            pd1 += __shfl_xor_sync(0xffffffffu, pd1, o);
        }
        // cross-wn reduction: wn==0 deposits, wn==1 combines + stores
        if (tq == 0 && wn == 0) {
            part_s[lr0] = ps0; part_d[lr0] = pd0;
            part_s[lr1] = ps1; part_d[lr1] = pd1;
        }
        __syncthreads();
        if (tq == 0 && wn == 1) {
            if (r0 < N) {
                g_als[r0 * HEADS + head] = ps0 + part_s[lr0];
                g_ald[r0 * HEADS + head] = pd0 + part_d[lr0];
            }
            if (r1 < N) {
                g_als[r1 * HEADS + head] = ps1 + part_s[lr1];
                g_ald[r1 * HEADS + head] = pd1 + part_d[lr1];
            }
        }
        __syncthreads();   // part_* reused next i-iteration
    }
}

__device__ __forceinline__ float leaky(float v) {
    return v > 0.f ? v : NEG_SLOPE * v;
}

// ---------------- fused GAT aggregation + bias + ReLU + LN + GCN proj ---------
__global__ void __launch_bounds__(128) k_gat(const float* __restrict__ bgat,
                                             const float* __restrict__ gamma,
                                             const float* __restrict__ beta,
                                             const float* __restrict__ wgcn,
                                             int N) {
    int d = blockIdx.x;
    int tid = threadIdx.x;               // thread -> half2 index (channels 2t,2t+1)
    int head = tid >> 5;                 // 32 half2 per head
    int row0 = g_off[d], row1 = g_off[d + 1];

    float4 aldv = *(const float4*)(g_ald + d * HEADS);
    float ald[4] = {aldv.x, aldv.y, aldv.z, aldv.w};

    __shared__ float p_sh[128][4];
    __shared__ int   src_sh[128];
    __shared__ float red[128][4];
    __shared__ float z_sh[4];
    __shared__ float stats[2];

    float accx = 0.f, accy = 0.f;
    float zloc[4] = {0.f, 0.f, 0.f, 0.f};

    // single pass: softmax numerators (no max shift; logits are O(10)) + gather
    for (int t0 = row0; t0 < row1; t0 += 128) {
        int cnt = min(128, row1 - t0);
        if (tid < cnt) {
            int s = g_esrc[t0 + tid];
            src_sh[tid] = s;
            float4 av = *(const float4*)(g_als + s * HEADS);
            float p0 = __expf(leaky(av.x + ald[0]));
            float p1 = __expf(leaky(av.y + ald[1]));
            float p2 = __expf(leaky(av.z + ald[2]));
            float p3 = __expf(leaky(av.w + ald[3]));
            p_sh[tid][0] = p0; p_sh[tid][1] = p1;
            p_sh[tid][2] = p2; p_sh[tid][3] = p3;
            zloc[0] += p0; zloc[1] += p1; zloc[2] += p2; zloc[3] += p3;
        }
        __syncthreads();
#pragma unroll 4
        for (int e = 0; e < cnt; e++) {
            int s = src_sh[e];
            float2 hv = __half22float2(g_hh[(long)s * HC2 + tid]);
            float p = p_sh[e][head];
            accx = fmaf(p, hv.x, accx);
            accy = fmaf(p, hv.y, accy);
        }
        __syncthreads();
    }

    // ---- reduce softmax denominators across the block ----
#pragma unroll
    for (int h = 0; h < 4; h++) red[tid][h] = zloc[h];
    __syncthreads();
    for (int s = 64; s > 0; s >>= 1) {
        if (tid < s)
#pragma unroll
            for (int h = 0; h < 4; h++) red[tid][h] += red[tid + s][h];
        __syncthreads();
    }
    if (tid < 4) z_sh[tid] = red[0][tid];
    __syncthreads();

    int c0 = 2 * tid, c1 = 2 * tid + 1;
    float zinv = 1.f / z_sh[head];
    float v0 = fmaxf(accx * zinv + bgat[c0], 0.f);
    float v1 = fmaxf(accy * zinv + bgat[c1], 0.f);

    // ---- LayerNorm over 256 channels ----
    __syncthreads();
    red[tid][0] = v0 + v1;
    red[tid][1] = fmaf(v0, v0, v1 * v1);
    __syncthreads();
    for (int s = 64; s > 0; s >>= 1) {
        if (tid < s) {
            red[tid][0] += red[tid + s][0];
            red[tid][1] += red[tid + s][1];
        }
        __syncthreads();
    }
    if (tid == 0) {
        float mu = red[0][0] * (1.f / 256.f);
        float var = red[0][1] * (1.f / 256.f) - mu * mu;
        stats[0] = mu;
        stats[1] = rsqrtf(var + LN_EPS);
    }
    __syncthreads();
    float mu = stats[0], rs = stats[1];
    float a0 = (v0 - mu) * rs * gamma[c0] + beta[c0];
    float a1 = (v1 - mu) * rs * gamma[c1] + beta[c1];

    // ---- project onto W_gcn (scalar per node) ----
    __syncthreads();
    red[tid][0] = fmaf(a0, wgcn[c0], a1 * wgcn[c1]);
    __syncthreads();
    for (int s = 64; s > 0; s >>= 1) {
        if (tid < s) red[tid][0] += red[tid + s][0];
        __syncthreads();
    }
    if (tid == 0) {
        g_dh[d] = make_float2(rsqrtf((float)(row1 - row0)), red[0][0]);
    }
}

// ---------------- GCN aggregation: warp per node ------------------------------
__global__ void k_gcn(const float* __restrict__ bgcn, float* __restrict__ out, int N) {
    int d = blockIdx.x * 4 + (threadIdx.x >> 5);
    int lane = threadIdx.x & 31;
    if (d >= N) return;
    int row0 = g_off[d], row1 = g_off[d + 1];
    float sum = 0.f;
    for (int i = row0 + lane; i < row1; i += 32) {
        float2 dh = g_dh[g_esrc[i]];
        sum = fmaf(dh.x, dh.y, sum);
    }
#pragma unroll
    for (int o = 16; o > 0; o >>= 1) sum += __shfl_down_sync(0xffffffffu, sum, o);
    if (lane == 0) out[d] = bgcn[0] + g_dh[d].x * sum;
}

// ---------------- launch ------------------------------------------------------
extern "C" void kernel_launch(void* const* d_in, const int* in_sizes, int n_in,
                              void* d_out, int out_size) {
    const float* x     = (const float*)d_in[0];
    const int*   ei    = (const int*)  d_in[1];
    const float* Wgat  = (const float*)d_in[2];
    const float* asrc  = (const float*)d_in[3];
    const float* adst  = (const float*)d_in[4];
    const float* bgat  = (const float*)d_in[5];
    const float* gamma = (const float*)d_in[6];
    const float* beta  = (const float*)d_in[7];
    const float* wgcn  = (const float*)d_in[8];
    const float* bgcn  = (const float*)d_in[9];
    float* out = (float*)d_out;

    int N = in_sizes[0] / IN_C;
    int E = in_sizes[1] / 2;
    const int* src = ei;
    const int* dst = ei + E;

    void* degp = nullptr;
    cudaGetSymbolAddress(&degp, g_deg);
    cudaMemsetAsync(degp, 0, N * sizeof(int));

    k_wt<<<HC * IN_C / 256, 256>>>(Wgat);
    k_count<<<(E + 1023) / 1024, 256>>>(dst, E);
    k_scan<<<1, 1024>>>(N);
    k_scatter<<<(E + N + 1023) / 1024, 256>>>(src, dst, E, N);

    dim3 gb(HC / 64, (N + 63) / 64);
    k_gemm<<<gb, 128>>>(x, asrc, adst, N);
    k_gat<<<N, 128>>>(bgat, gamma, beta, wgcn, N);
    k_gcn<<<(N + 3) / 4, 128>>>(bgcn, out, N);
}

// round 9
// speedup vs baseline: 1.6019x; 1.2057x over previous
#include <cuda_runtime.h>
#include <cuda_fp16.h>

#define IN_C   256
#define HC     256
#define HEADS  4
#define CPH    64
#define HC2    128          // half2 count per row
#define NMAX   10000
#define EMAX   320000
#define ETMAX  (EMAX + NMAX)
#define NEG_SLOPE 0.2f
#define LN_EPS 1e-5f

// ---------------- scratch (static device memory; no allocations) -------------
__device__ __align__(16) __half2 g_hh[NMAX * HC2]; // GAT features (fp16 pairs)
__device__ __align__(16) __half  g_wt[HC * IN_C];  // W_gat^T in fp16: [n][k]
__device__ float  g_als[NMAX * HEADS];
__device__ float  g_ald[NMAX * HEADS];
__device__ __align__(16) int g_deg[NMAX];
__device__ int    g_off[NMAX + 1];
__device__ int    g_cur[NMAX];
__device__ int    g_esrc[ETMAX];       // CSR by dst: src node of each in-edge
__device__ float2 g_dh[NMAX];          // {dinv, h2} packed

// ---------------- CSR construction -------------------------------------------
__global__ void k_count(const int* __restrict__ dst, int E) {
    int i0 = (blockIdx.x * blockDim.x + threadIdx.x) * 4;
    if (i0 + 3 < E) {
        int4 d4 = *(const int4*)(dst + i0);
        atomicAdd(&g_deg[d4.x], 1);
        atomicAdd(&g_deg[d4.y], 1);
        atomicAdd(&g_deg[d4.z], 1);
        atomicAdd(&g_deg[d4.w], 1);
    } else {
        for (int j = 0; j < 4; j++) {
            int i = i0 + j;
            if (i < E) atomicAdd(&g_deg[dst[i]], 1);
        }
    }
}

// single-block exclusive scan of (g_deg + 1) -> g_off / g_cur, 4 elems/thread
__global__ void k_scan(int N) {
    __shared__ int warp_sums[32];
    __shared__ int carry_s;
    int tid = threadIdx.x;
    int lane = tid & 31, wid = tid >> 5;
    if (tid == 0) carry_s = 0;
    __syncthreads();
    for (int base = 0; base < N; base += 4096) {
        int i0 = base + tid * 4;
        int v0 = 0, v1 = 0, v2 = 0, v3 = 0;
        if (i0 + 3 < N) {
            int4 dv = *(const int4*)&g_deg[i0];
            v0 = dv.x + 1; v1 = dv.y + 1; v2 = dv.z + 1; v3 = dv.w + 1;
        } else {
            if (i0     < N) v0 = g_deg[i0]     + 1;
            if (i0 + 1 < N) v1 = g_deg[i0 + 1] + 1;
            if (i0 + 2 < N) v2 = g_deg[i0 + 2] + 1;
            if (i0 + 3 < N) v3 = g_deg[i0 + 3] + 1;
        }
        int v = v0 + v1 + v2 + v3;
        int incl = v;
#pragma unroll
        for (int s = 1; s < 32; s <<= 1) {
            int t = __shfl_up_sync(0xffffffffu, incl, s);
            if (lane >= s) incl += t;
        }
        if (lane == 31) warp_sums[wid] = incl;
        __syncthreads();
        if (wid == 0) {
            int w = warp_sums[lane];
#pragma unroll
            for (int s = 1; s < 32; s <<= 1) {
                int t = __shfl_up_sync(0xffffffffu, w, s);
                if (lane >= s) w += t;
            }
            warp_sums[lane] = w;
        }
        __syncthreads();
        int warp_base = (wid > 0) ? warp_sums[wid - 1] : 0;
        int c = carry_s;
        int incl_blk = warp_base + incl;
        int e0 = c + incl_blk - v;
        int e1 = e0 + v0, e2 = e1 + v1, e3 = e2 + v2;
        if (i0     < N) { g_off[i0]     = e0; g_cur[i0]     = e0; if (i0     == N - 1) g_off[N] = e1; }
        if (i0 + 1 < N) { g_off[i0 + 1] = e1; g_cur[i0 + 1] = e1; if (i0 + 1 == N - 1) g_off[N] = e2; }
        if (i0 + 2 < N) { g_off[i0 + 2] = e2; g_cur[i0 + 2] = e2; if (i0 + 2 == N - 1) g_off[N] = e3; }
        if (i0 + 3 < N) { g_off[i0 + 3] = e3; g_cur[i0 + 3] = e3; if (i0 + 3 == N - 1) g_off[N] = e3 + v3; }
        __syncthreads();
        if (tid == 1023) carry_s = c + incl_blk;
        __syncthreads();
    }
}

__global__ void k_scatter(const int* __restrict__ src, const int* __restrict__ dst,
                          int E, int N) {
    int i0 = (blockIdx.x * blockDim.x + threadIdx.x) * 4;
    if (i0 + 3 < E) {
        int4 s4 = *(const int4*)(src + i0);
        int4 d4 = *(const int4*)(dst + i0);
        int p0 = atomicAdd(&g_cur[d4.x], 1);
        int p1 = atomicAdd(&g_cur[d4.y], 1);
        int p2 = atomicAdd(&g_cur[d4.z], 1);
        int p3 = atomicAdd(&g_cur[d4.w], 1);
        g_esrc[p0] = s4.x; g_esrc[p1] = s4.y;
        g_esrc[p2] = s4.z; g_esrc[p3] = s4.w;
    } else {
        for (int j = 0; j < 4; j++) {
            int i = i0 + j;
            if (i >= E + N) break;
            int d, s;
            if (i < E) { d = dst[i]; s = src[i]; }
            else       { d = i - E;  s = i - E;  }   // self loop
            int pos = atomicAdd(&g_cur[d], 1);
            g_esrc[pos] = s;
        }
    }
}

// ---------------- W_gat -> fp16 transpose: g_wt[n][k] -------------------------
__global__ void k_wt(const float* __restrict__ W) {
    int idx = blockIdx.x * 256 + threadIdx.x;   // 65536 total
    int k = idx >> 8, n = idx & 255;
    g_wt[n * IN_C + k] = __float2half(W[k * HC + n]);
}

// ---------------- tensor-core GEMM + fused logits + fp16 h store --------------
// 64x64 tile, 128 threads (4 warps, 2x2), m16n8k16 fp16 mma, fp32 accumulate.
// XOR-swizzled smem: unit(r,c) = r*8 + (c ^ (r&7)), 16B units, 8 units/row.
__device__ __forceinline__ void mma16816(float* c, const unsigned* a, const unsigned* b) {
    asm volatile("mma.sync.aligned.m16n8k16.row.col.f32.f16.f16.f32 "
                 "{%0,%1,%2,%3}, {%4,%5,%6,%7}, {%8,%9}, {%0,%1,%2,%3};"
                 : "+f"(c[0]), "+f"(c[1]), "+f"(c[2]), "+f"(c[3])
                 : "r"(a[0]), "r"(a[1]), "r"(a[2]), "r"(a[3]),
                   "r"(b[0]), "r"(b[1]));
}

__global__ void __launch_bounds__(128) k_gemm(const float* __restrict__ X,
                                              const float* __restrict__ asrc,
                                              const float* __restrict__ adst,
                                              int N) {
    __shared__ __align__(16) __half As[64 * 64];
    __shared__ __align__(16) __half Bs[64 * 64];
    __shared__ float part_s[64], part_d[64];   // cross-warp logit partials
    int tid = threadIdx.x;
    int lane = tid & 31, w = tid >> 5;
    int wm = w >> 1, wn = w & 1;
    int head = blockIdx.x;               // 64 cols == one head
    int mblk = blockIdx.y * 64;
    unsigned asb = (unsigned)__cvta_generic_to_shared(As);
    unsigned bsb = (unsigned)__cvta_generic_to_shared(Bs);

    float c[2][4][4];
#pragma unroll
    for (int i = 0; i < 2; i++)
#pragma unroll
        for (int j = 0; j < 4; j++)
#pragma unroll
            for (int q = 0; q < 4; q++) c[i][j][q] = 0.f;

    for (int s = 0; s < 4; s++) {
        int k0 = s * 64;
        {   // A tile: 64 rows x 64 k, fp32 global -> fp16 swizzled smem
            int r = tid >> 1;
            int cu0 = (tid & 1) * 4;
            int row = mblk + r;
#pragma unroll
            for (int u = 0; u < 4; u++) {
                int cc = cu0 + u;
                __half hbuf[8];
                if (row < N) {
                    const float* p = X + (long)row * IN_C + k0 + cc * 8;
                    float4 v0 = *(const float4*)p;
                    float4 v1 = *(const float4*)(p + 4);
                    hbuf[0] = __float2half(v0.x); hbuf[1] = __float2half(v0.y);
                    hbuf[2] = __float2half(v0.z); hbuf[3] = __float2half(v0.w);
                    hbuf[4] = __float2half(v1.x); hbuf[5] = __float2half(v1.y);
                    hbuf[6] = __float2half(v1.z); hbuf[7] = __float2half(v1.w);
                } else {
#pragma unroll
                    for (int q = 0; q < 8; q++) hbuf[q] = __float2half(0.f);
                }
                int unit = r * 8 + (cc ^ (r & 7));
                *(uint4*)((char*)As + unit * 16) = *(uint4*)hbuf;
            }
        }
        {   // B tile: 64 n-rows x 64 k from g_wt (fp16)
            int r = tid >> 1;
            int cu0 = (tid & 1) * 4;
            const __half* p = g_wt + (long)(head * 64 + r) * IN_C + k0;
#pragma unroll
            for (int u = 0; u < 4; u++) {
                int cc = cu0 + u;
                uint4 v = *(const uint4*)(p + cc * 8);
                int unit = r * 8 + (cc ^ (r & 7));
                *(uint4*)((char*)Bs + unit * 16) = v;
            }
        }
        __syncthreads();

#pragma unroll
        for (int kk = 0; kk < 4; kk++) {
            unsigned af[2][4], bf[4][2];
#pragma unroll
            for (int i = 0; i < 2; i++) {
                int r = wm * 32 + i * 16 + (lane & 15);
                int cc = 2 * kk + (lane >> 4);
                int unit = r * 8 + (cc ^ (r & 7));
                unsigned addr = asb + unit * 16;
                asm volatile("ldmatrix.sync.aligned.m8n8.x4.shared.b16 "
                             "{%0,%1,%2,%3}, [%4];"
                             : "=r"(af[i][0]), "=r"(af[i][1]),
                               "=r"(af[i][2]), "=r"(af[i][3])
                             : "r"(addr));
            }
#pragma unroll
            for (int j = 0; j < 4; j++) {
                int l = lane & 15;
                int r = wn * 32 + j * 8 + (l & 7);
                int cc = 2 * kk + (l >> 3);
                int unit = r * 8 + (cc ^ (r & 7));
                unsigned addr = bsb + unit * 16;
                asm volatile("ldmatrix.sync.aligned.m8n8.x2.shared.b16 "
                             "{%0,%1}, [%2];"
                             : "=r"(bf[j][0]), "=r"(bf[j][1])
                             : "r"(addr));
            }
#pragma unroll
            for (int i = 0; i < 2; i++)
#pragma unroll
                for (int j = 0; j < 4; j++)
                    mma16816(c[i][j], af[i], bf[j]);
        }
        __syncthreads();
    }

    // ---- epilogue: fp16 h store + fused logit reduction ----------------------
    int grp = lane >> 2, tq = lane & 3;
    float as0[4], as1[4], ad0[4], ad1[4];
#pragma unroll
    for (int j = 0; j < 4; j++) {
        int col = wn * 32 + j * 8 + 2 * tq;
        as0[j] = asrc[head * CPH + col];     as1[j] = asrc[head * CPH + col + 1];
        ad0[j] = adst[head * CPH + col];     ad1[j] = adst[head * CPH + col + 1];
    }

#pragma unroll
    for (int i = 0; i < 2; i++) {
        int lr0 = wm * 32 + i * 16 + grp;     // row within block tile
        int lr1 = lr0 + 8;
        int r0 = mblk + lr0;
        int r1 = mblk + lr1;
        float ps0 = 0.f, pd0 = 0.f, ps1 = 0.f, pd1 = 0.f;
#pragma unroll
        for (int j = 0; j < 4; j++) {
            ps0 = fmaf(c[i][j][0], as0[j], fmaf(c[i][j][1], as1[j], ps0));
            pd0 = fmaf(c[i][j][0], ad0[j], fmaf(c[i][j][1], ad1[j], pd0));
            ps1 = fmaf(c[i][j][2], as0[j], fmaf(c[i][j][3], as1[j], ps1));
            pd1 = fmaf(c[i][j][2], ad0[j], fmaf(c[i][j][3], ad1[j], pd1));
            int gcol = head * 64 + wn * 32 + j * 8 + 2 * tq;
            if (r0 < N)
                g_hh[(long)r0 * HC2 + (gcol >> 1)] =
                    __floats2half2_rn(c[i][j][0], c[i][j][1]);
            if (r1 < N)
                g_hh[(long)r1 * HC2 + (gcol >> 1)] =
                    __floats2half2_rn(c[i][j][2], c[i][j][3]);
        }
#pragma unroll
        for (int o = 1; o < 4; o <<= 1) {
            ps0 += __shfl_xor_sync(0xffffffffu, ps0, o);
            pd0 += __shfl_xor_sync(0xffffffffu, pd0, o);
            ps1 += __shfl_xor_sync(0xffffffffu, ps1, o);
            pd1 += __shfl_xor_sync(0xffffffffu, pd1, o);
        }
        // cross-wn reduction: wn==0 deposits, wn==1 combines + stores
        if (tq == 0 && wn == 0) {
            part_s[lr0] = ps0; part_d[lr0] = pd0;
            part_s[lr1] = ps1; part_d[lr1] = pd1;
        }
        __syncthreads();
        if (tq == 0 && wn == 1) {
            if (r0 < N) {
                g_als[r0 * HEADS + head] = ps0 + part_s[lr0];
                g_ald[r0 * HEADS + head] = pd0 + part_d[lr0];
            }
            if (r1 < N) {
                g_als[r1 * HEADS + head] = ps1 + part_s[lr1];
                g_ald[r1 * HEADS + head] = pd1 + part_d[lr1];
            }
        }
        __syncthreads();   // part_* reused next i-iteration
    }
}

__device__ __forceinline__ float leaky(float v) {
    return v > 0.f ? v : NEG_SLOPE * v;
}

// ---------------- fused GAT aggregation + bias + ReLU + LN + GCN proj ---------
__global__ void __launch_bounds__(128) k_gat(const float* __restrict__ bgat,
                                             const float* __restrict__ gamma,
                                             const float* __restrict__ beta,
                                             const float* __restrict__ wgcn,
                                             int N) {
    int d = blockIdx.x;
    int tid = threadIdx.x;               // thread -> half2 index (channels 2t,2t+1)
    int head = tid >> 5;                 // 32 half2 per head
    int row0 = g_off[d], row1 = g_off[d + 1];

    float4 aldv = *(const float4*)(g_ald + d * HEADS);
    float ald[4] = {aldv.x, aldv.y, aldv.z, aldv.w};

    __shared__ float p_sh[128][4];
    __shared__ int   src_sh[128];
    __shared__ float red[128][4];
    __shared__ float z_sh[4];
    __shared__ float stats[2];

    float accx = 0.f, accy = 0.f;
    float zloc[4] = {0.f, 0.f, 0.f, 0.f};

    // single pass: softmax numerators (no max shift; logits are O(10)) + gather
    for (int t0 = row0; t0 < row1; t0 += 128) {
        int cnt = min(128, row1 - t0);
        if (tid < cnt) {
            int s = g_esrc[t0 + tid];
            src_sh[tid] = s;
            float4 av = *(const float4*)(g_als + s * HEADS);
            float p0 = __expf(leaky(av.x + ald[0]));
            float p1 = __expf(leaky(av.y + ald[1]));
            float p2 = __expf(leaky(av.z + ald[2]));
            float p3 = __expf(leaky(av.w + ald[3]));
            p_sh[tid][0] = p0; p_sh[tid][1] = p1;
            p_sh[tid][2] = p2; p_sh[tid][3] = p3;
            zloc[0] += p0; zloc[1] += p1; zloc[2] += p2; zloc[3] += p3;
        }
        __syncthreads();
#pragma unroll 4
        for (int e = 0; e < cnt; e++) {
            int s = src_sh[e];
            float2 hv = __half22float2(g_hh[(long)s * HC2 + tid]);
            float p = p_sh[e][head];
            accx = fmaf(p, hv.x, accx);
            accy = fmaf(p, hv.y, accy);
        }
        __syncthreads();
    }

    // ---- reduce softmax denominators across the block ----
#pragma unroll
    for (int h = 0; h < 4; h++) red[tid][h] = zloc[h];
    __syncthreads();
    for (int s = 64; s > 0; s >>= 1) {
        if (tid < s)
#pragma unroll
            for (int h = 0; h < 4; h++) red[tid][h] += red[tid + s][h];
        __syncthreads();
    }
    if (tid < 4) z_sh[tid] = red[0][tid];
    __syncthreads();

    int c0 = 2 * tid, c1 = 2 * tid + 1;
    float zinv = 1.f / z_sh[head];
    float v0 = fmaxf(accx * zinv + bgat[c0], 0.f);
    float v1 = fmaxf(accy * zinv + bgat[c1], 0.f);

    // ---- LayerNorm over 256 channels ----
    __syncthreads();
    red[tid][0] = v0 + v1;
    red[tid][1] = fmaf(v0, v0, v1 * v1);
    __syncthreads();
    for (int s = 64; s > 0; s >>= 1) {
        if (tid < s) {
            red[tid][0] += red[tid + s][0];
            red[tid][1] += red[tid + s][1];
        }
        __syncthreads();
    }
    if (tid == 0) {
        float mu = red[0][0] * (1.f / 256.f);
        float var = red[0][1] * (1.f / 256.f) - mu * mu;
        stats[0] = mu;
        stats[1] = rsqrtf(var + LN_EPS);
    }
    __syncthreads();
    float mu = stats[0], rs = stats[1];
    float a0 = (v0 - mu) * rs * gamma[c0] + beta[c0];
    float a1 = (v1 - mu) * rs * gamma[c1] + beta[c1];

    // ---- project onto W_gcn (scalar per node) ----
    __syncthreads();
    red[tid][0] = fmaf(a0, wgcn[c0], a1 * wgcn[c1]);
    __syncthreads();
    for (int s = 64; s > 0; s >>= 1) {
        if (tid < s) red[tid][0] += red[tid + s][0];
        __syncthreads();
    }
    if (tid == 0) {
        g_dh[d] = make_float2(rsqrtf((float)(row1 - row0)), red[0][0]);
    }
}

// ---------------- GCN aggregation: warp per node ------------------------------
__global__ void k_gcn(const float* __restrict__ bgcn, float* __restrict__ out, int N) {
    int d = blockIdx.x * 4 + (threadIdx.x >> 5);
    int lane = threadIdx.x & 31;
    if (d >= N) return;
    int row0 = g_off[d], row1 = g_off[d + 1];
    float sum = 0.f;
    for (int i = row0 + lane; i < row1; i += 32) {
        float2 dh = g_dh[g_esrc[i]];
        sum = fmaf(dh.x, dh.y, sum);
    }
#pragma unroll
    for (int o = 16; o > 0; o >>= 1) sum += __shfl_down_sync(0xffffffffu, sum, o);
    if (lane == 0) out[d] = bgcn[0] + g_dh[d].x * sum;
}

// ---------------- launch ------------------------------------------------------
extern "C" void kernel_launch(void* const* d_in, const int* in_sizes, int n_in,
                              void* d_out, int out_size) {
    const float* x     = (const float*)d_in[0];
    const int*   ei    = (const int*)  d_in[1];
    const float* Wgat  = (const float*)d_in[2];
    const float* asrc  = (const float*)d_in[3];
    const float* adst  = (const float*)d_in[4];
    const float* bgat  = (const float*)d_in[5];
    const float* gamma = (const float*)d_in[6];
    const float* beta  = (const float*)d_in[7];
    const float* wgcn  = (const float*)d_in[8];
    const float* bgcn  = (const float*)d_in[9];
    float* out = (float*)d_out;

    int N = in_sizes[0] / IN_C;
    int E = in_sizes[1] / 2;
    const int* src = ei;
    const int* dst = ei + E;

    // one-time side-stream resources (created outside any capture; the work
    // enqueued per call is identical and deterministic every time)
    static cudaStream_t s_csr = nullptr;
    static cudaEvent_t  ev_fork = nullptr, ev_join = nullptr;
    if (s_csr == nullptr) {
        cudaStreamCreateWithFlags(&s_csr, cudaStreamNonBlocking);
        cudaEventCreateWithFlags(&ev_fork, cudaEventDisableTiming);
        cudaEventCreateWithFlags(&ev_join, cudaEventDisableTiming);
    }

    void* degp = nullptr;
    cudaGetSymbolAddress(&degp, g_deg);
    cudaMemsetAsync(degp, 0, N * sizeof(int));

    // fork: CSR chain on s_csr, GEMM chain on the main (capture) stream
    cudaEventRecord(ev_fork, 0);
    cudaStreamWaitEvent(s_csr, ev_fork, 0);

    k_count<<<(E + 1023) / 1024, 256, 0, s_csr>>>(dst, E);
    k_scan<<<1, 1024, 0, s_csr>>>(N);
    k_scatter<<<(E + N + 1023) / 1024, 256, 0, s_csr>>>(src, dst, E, N);
    cudaEventRecord(ev_join, s_csr);

    k_wt<<<HC * IN_C / 256, 256>>>(Wgat);
    dim3 gb(HC / 64, (N + 63) / 64);
    k_gemm<<<gb, 128>>>(x, asrc, adst, N);

    // join: k_gat needs both CSR and GEMM outputs
    cudaStreamWaitEvent(0, ev_join, 0);
    k_gat<<<N, 128>>>(bgat, gamma, beta, wgcn, N);
    k_gcn<<<(N + 3) / 4, 128>>>(bgcn, out, N);
}

// round 10
// speedup vs baseline: 1.6760x; 1.0462x over previous
#include <cuda_runtime.h>
#include <cuda_fp16.h>

#define IN_C   256
#define HC     256
#define HEADS  4
#define CPH    64
#define HC2    128          // half2 count per row
#define NMAX   10000
#define EMAX   320000
#define ETMAX  (EMAX + NMAX)
#define NEG_SLOPE 0.2f
#define LN_EPS 1e-5f

// ---------------- scratch (static device memory; no allocations) -------------
__device__ __align__(16) __half2 g_hh[NMAX * HC2]; // GAT features (fp16 pairs)
__device__ float  g_als[NMAX * HEADS];
__device__ float  g_ald[NMAX * HEADS];
__device__ __align__(16) int g_deg[NMAX];          // zero at load + re-zeroed by k_gcn
__device__ int    g_off[NMAX + 1];
__device__ int    g_cur[NMAX];
__device__ int    g_esrc[ETMAX];       // CSR by dst: src node of each in-edge
__device__ float2 g_dh[NMAX];          // {dinv, h2} packed

// ---------------- CSR construction -------------------------------------------
__global__ void k_count(const int* __restrict__ dst, int E) {
    int i0 = (blockIdx.x * blockDim.x + threadIdx.x) * 4;
    if (i0 + 3 < E) {
        int4 d4 = *(const int4*)(dst + i0);
        atomicAdd(&g_deg[d4.x], 1);
        atomicAdd(&g_deg[d4.y], 1);
        atomicAdd(&g_deg[d4.z], 1);
        atomicAdd(&g_deg[d4.w], 1);
    } else {
        for (int j = 0; j < 4; j++) {
            int i = i0 + j;
            if (i < E) atomicAdd(&g_deg[dst[i]], 1);
        }
    }
}

// single-block exclusive scan of (g_deg + 1) -> g_off / g_cur, 4 elems/thread
__global__ void k_scan(int N) {
    __shared__ int warp_sums[32];
    __shared__ int carry_s;
    int tid = threadIdx.x;
    int lane = tid & 31, wid = tid >> 5;
    if (tid == 0) carry_s = 0;
    __syncthreads();
    for (int base = 0; base < N; base += 4096) {
        int i0 = base + tid * 4;
        int v0 = 0, v1 = 0, v2 = 0, v3 = 0;
        if (i0 + 3 < N) {
            int4 dv = *(const int4*)&g_deg[i0];
            v0 = dv.x + 1; v1 = dv.y + 1; v2 = dv.z + 1; v3 = dv.w + 1;
        } else {
            if (i0     < N) v0 = g_deg[i0]     + 1;
            if (i0 + 1 < N) v1 = g_deg[i0 + 1] + 1;
            if (i0 + 2 < N) v2 = g_deg[i0 + 2] + 1;
            if (i0 + 3 < N) v3 = g_deg[i0 + 3] + 1;
        }
        int v = v0 + v1 + v2 + v3;
        int incl = v;
#pragma unroll
        for (int s = 1; s < 32; s <<= 1) {
            int t = __shfl_up_sync(0xffffffffu, incl, s);
            if (lane >= s) incl += t;
        }
        if (lane == 31) warp_sums[wid] = incl;
        __syncthreads();
        if (wid == 0) {
            int w = warp_sums[lane];
#pragma unroll
            for (int s = 1; s < 32; s <<= 1) {
                int t = __shfl_up_sync(0xffffffffu, w, s);
                if (lane >= s) w += t;
            }
            warp_sums[lane] = w;
        }
        __syncthreads();
        int warp_base = (wid > 0) ? warp_sums[wid - 1] : 0;
        int c = carry_s;
        int incl_blk = warp_base + incl;
        int e0 = c + incl_blk - v;
        int e1 = e0 + v0, e2 = e1 + v1, e3 = e2 + v2;
        if (i0     < N) { g_off[i0]     = e0; g_cur[i0]     = e0; if (i0     == N - 1) g_off[N] = e1; }
        if (i0 + 1 < N) { g_off[i0 + 1] = e1; g_cur[i0 + 1] = e1; if (i0 + 1 == N - 1) g_off[N] = e2; }
        if (i0 + 2 < N) { g_off[i0 + 2] = e2; g_cur[i0 + 2] = e2; if (i0 + 2 == N - 1) g_off[N] = e3; }
        if (i0 + 3 < N) { g_off[i0 + 3] = e3; g_cur[i0 + 3] = e3; if (i0 + 3 == N - 1) g_off[N] = e3 + v3; }
        __syncthreads();
        if (tid == 1023) carry_s = c + incl_blk;
        __syncthreads();
    }
}

__global__ void k_scatter(const int* __restrict__ src, const int* __restrict__ dst,
                          int E, int N) {
    int i0 = (blockIdx.x * blockDim.x + threadIdx.x) * 4;
    if (i0 + 3 < E) {
        int4 s4 = *(const int4*)(src + i0);
        int4 d4 = *(const int4*)(dst + i0);
        int p0 = atomicAdd(&g_cur[d4.x], 1);
        int p1 = atomicAdd(&g_cur[d4.y], 1);
        int p2 = atomicAdd(&g_cur[d4.z], 1);
        int p3 = atomicAdd(&g_cur[d4.w], 1);
        g_esrc[p0] = s4.x; g_esrc[p1] = s4.y;
        g_esrc[p2] = s4.z; g_esrc[p3] = s4.w;
    } else {
        for (int j = 0; j < 4; j++) {
            int i = i0 + j;
            if (i >= E + N) break;
            int d, s;
            if (i < E) { d = dst[i]; s = src[i]; }
            else       { d = i - E;  s = i - E;  }   // self loop
            int pos = atomicAdd(&g_cur[d], 1);
            g_esrc[pos] = s;
        }
    }
}

// ---------------- tensor-core GEMM + fused logits + fp16 h store --------------
// 64x64 tile, 128 threads (4 warps, 2x2), m16n8k16 fp16 mma, fp32 accumulate.
// A smem: [row m][k] swizzled; B smem: [row k][n] swizzled, fragments via
// ldmatrix.x2.trans (transposed 8x8 loads give the col-major B fragment).
// XOR swizzle: unit(r,c) = r*8 + (c ^ (r&7)), 16B units, 8 units/row.
__device__ __forceinline__ void mma16816(float* c, const unsigned* a, const unsigned* b) {
    asm volatile("mma.sync.aligned.m16n8k16.row.col.f32.f16.f16.f32 "
                 "{%0,%1,%2,%3}, {%4,%5,%6,%7}, {%8,%9}, {%0,%1,%2,%3};"
                 : "+f"(c[0]), "+f"(c[1]), "+f"(c[2]), "+f"(c[3])
                 : "r"(a[0]), "r"(a[1]), "r"(a[2]), "r"(a[3]),
                   "r"(b[0]), "r"(b[1]));
}

__global__ void __launch_bounds__(128) k_gemm(const float* __restrict__ X,
                                              const float* __restrict__ W,
                                              const float* __restrict__ asrc,
                                              const float* __restrict__ adst,
                                              int N) {
    __shared__ __align__(16) __half As[64 * 64];
    __shared__ __align__(16) __half Bs[64 * 64];
    __shared__ float part_s[64], part_d[64];   // cross-warp logit partials
    int tid = threadIdx.x;
    int lane = tid & 31, w = tid >> 5;
    int wm = w >> 1, wn = w & 1;
    int head = blockIdx.x;               // 64 cols == one head
    int mblk = blockIdx.y * 64;
    unsigned asb = (unsigned)__cvta_generic_to_shared(As);
    unsigned bsb = (unsigned)__cvta_generic_to_shared(Bs);

    float c[2][4][4];
#pragma unroll
    for (int i = 0; i < 2; i++)
#pragma unroll
        for (int j = 0; j < 4; j++)
#pragma unroll
            for (int q = 0; q < 4; q++) c[i][j][q] = 0.f;

    for (int s = 0; s < 4; s++) {
        int k0 = s * 64;
        {   // A tile: 64 m-rows x 64 k, fp32 X -> fp16 swizzled smem
            int r = tid >> 1;
            int cu0 = (tid & 1) * 4;
            int row = mblk + r;
#pragma unroll
            for (int u = 0; u < 4; u++) {
                int cc = cu0 + u;
                __half hbuf[8];
                if (row < N) {
                    const float* p = X + (long)row * IN_C + k0 + cc * 8;
                    float4 v0 = *(const float4*)p;
                    float4 v1 = *(const float4*)(p + 4);
                    hbuf[0] = __float2half(v0.x); hbuf[1] = __float2half(v0.y);
                    hbuf[2] = __float2half(v0.z); hbuf[3] = __float2half(v0.w);
                    hbuf[4] = __float2half(v1.x); hbuf[5] = __float2half(v1.y);
                    hbuf[6] = __float2half(v1.z); hbuf[7] = __float2half(v1.w);
                } else {
#pragma unroll
                    for (int q = 0; q < 8; q++) hbuf[q] = __float2half(0.f);
                }
                int unit = r * 8 + (cc ^ (r & 7));
                *(uint4*)((char*)As + unit * 16) = *(uint4*)hbuf;
            }
        }
        {   // B tile: 64 k-rows x 64 n, fp32 W (k-major rows) -> fp16 swizzled
            int r = tid >> 1;                 // k row within tile
            int cu0 = (tid & 1) * 4;
            const float* p = W + (long)(k0 + r) * HC + head * 64;
#pragma unroll
            for (int u = 0; u < 4; u++) {
                int cc = cu0 + u;             // n unit
                float4 v0 = *(const float4*)(p + cc * 8);
                float4 v1 = *(const float4*)(p + cc * 8 + 4);
                __half hbuf[8];
                hbuf[0] = __float2half(v0.x); hbuf[1] = __float2half(v0.y);
                hbuf[2] = __float2half(v0.z); hbuf[3] = __float2half(v0.w);
                hbuf[4] = __float2half(v1.x); hbuf[5] = __float2half(v1.y);
                hbuf[6] = __float2half(v1.z); hbuf[7] = __float2half(v1.w);
                int unit = r * 8 + (cc ^ (r & 7));
                *(uint4*)((char*)Bs + unit * 16) = *(uint4*)hbuf;
            }
        }
        __syncthreads();

#pragma unroll
        for (int kk = 0; kk < 4; kk++) {
            unsigned af[2][4], bf[4][2];
#pragma unroll
            for (int i = 0; i < 2; i++) {
                int r = wm * 32 + i * 16 + (lane & 15);
                int cc = 2 * kk + (lane >> 4);
                int unit = r * 8 + (cc ^ (r & 7));
                unsigned addr = asb + unit * 16;
                asm volatile("ldmatrix.sync.aligned.m8n8.x4.shared.b16 "
                             "{%0,%1,%2,%3}, [%4];"
                             : "=r"(af[i][0]), "=r"(af[i][1]),
                               "=r"(af[i][2]), "=r"(af[i][3])
                             : "r"(addr));
            }
#pragma unroll
            for (int j = 0; j < 4; j++) {
                // B fragment via transposed 8x8 loads: lanes 0-15 address
                // k-rows kk*16 .. kk*16+15 at n-unit (wn*4 + j)
                int l = lane & 15;
                int r = kk * 16 + l;
                int cc = wn * 4 + j;
                int unit = r * 8 + (cc ^ (r & 7));
                unsigned addr = bsb + unit * 16;
                asm volatile("ldmatrix.sync.aligned.m8n8.x2.trans.shared.b16 "
                             "{%0,%1}, [%2];"
                             : "=r"(bf[j][0]), "=r"(bf[j][1])
                             : "r"(addr));
            }
#pragma unroll
            for (int i = 0; i < 2; i++)
#pragma unroll
                for (int j = 0; j < 4; j++)
                    mma16816(c[i][j], af[i], bf[j]);
        }
        __syncthreads();
    }

    // ---- epilogue: fp16 h store + fused logit reduction ----------------------
    int grp = lane >> 2, tq = lane & 3;
    float as0[4], as1[4], ad0[4], ad1[4];
#pragma unroll
    for (int j = 0; j < 4; j++) {
        int col = wn * 32 + j * 8 + 2 * tq;
        as0[j] = asrc[head * CPH + col];     as1[j] = asrc[head * CPH + col + 1];
        ad0[j] = adst[head * CPH + col];     ad1[j] = adst[head * CPH + col + 1];
    }

#pragma unroll
    for (int i = 0; i < 2; i++) {
        int lr0 = wm * 32 + i * 16 + grp;     // row within block tile
        int lr1 = lr0 + 8;
        int r0 = mblk + lr0;
        int r1 = mblk + lr1;
        float ps0 = 0.f, pd0 = 0.f, ps1 = 0.f, pd1 = 0.f;
#pragma unroll
        for (int j = 0; j < 4; j++) {
            ps0 = fmaf(c[i][j][0], as0[j], fmaf(c[i][j][1], as1[j], ps0));
            pd0 = fmaf(c[i][j][0], ad0[j], fmaf(c[i][j][1], ad1[j], pd0));
            ps1 = fmaf(c[i][j][2], as0[j], fmaf(c[i][j][3], as1[j], ps1));
            pd1 = fmaf(c[i][j][2], ad0[j], fmaf(c[i][j][3], ad1[j], pd1));
            int gcol = head * 64 + wn * 32 + j * 8 + 2 * tq;
            if (r0 < N)
                g_hh[(long)r0 * HC2 + (gcol >> 1)] =
                    __floats2half2_rn(c[i][j][0], c[i][j][1]);
            if (r1 < N)
                g_hh[(long)r1 * HC2 + (gcol >> 1)] =
                    __floats2half2_rn(c[i][j][2], c[i][j][3]);
        }
#pragma unroll
        for (int o = 1; o < 4; o <<= 1) {
            ps0 += __shfl_xor_sync(0xffffffffu, ps0, o);
            pd0 += __shfl_xor_sync(0xffffffffu, pd0, o);
            ps1 += __shfl_xor_sync(0xffffffffu, ps1, o);
            pd1 += __shfl_xor_sync(0xffffffffu, pd1, o);
        }
        // cross-wn reduction: wn==0 deposits, wn==1 combines + stores
        if (tq == 0 && wn == 0) {
            part_s[lr0] = ps0; part_d[lr0] = pd0;
            part_s[lr1] = ps1; part_d[lr1] = pd1;
        }
        __syncthreads();
        if (tq == 0 && wn == 1) {
            if (r0 < N) {
                g_als[r0 * HEADS + head] = ps0 + part_s[lr0];
                g_ald[r0 * HEADS + head] = pd0 + part_d[lr0];
            }
            if (r1 < N) {
                g_als[r1 * HEADS + head] = ps1 + part_s[lr1];
                g_ald[r1 * HEADS + head] = pd1 + part_d[lr1];
            }
        }
        __syncthreads();   // part_* reused next i-iteration
    }
}

__device__ __forceinline__ float leaky(float v) {
    return v > 0.f ? v : NEG_SLOPE * v;
}

// ---------------- fused GAT aggregation + bias + ReLU + LN + GCN proj ---------
__global__ void __launch_bounds__(128) k_gat(const float* __restrict__ bgat,
                                             const float* __restrict__ gamma,
                                             const float* __restrict__ beta,
                                             const float* __restrict__ wgcn,
                                             int N) {
    int d = blockIdx.x;
    int tid = threadIdx.x;               // thread -> half2 index (channels 2t,2t+1)
    int lane = tid & 31, warp = tid >> 5;
    int head = warp;                     // 32 half2 per head
    int row0 = g_off[d], row1 = g_off[d + 1];

    float4 aldv = *(const float4*)(g_ald + d * HEADS);
    float ald[4] = {aldv.x, aldv.y, aldv.z, aldv.w};

    __shared__ float p_sh[128][4];
    __shared__ int   src_sh[128];
    __shared__ float wz[4][4];     // [warp][head] z partials
    __shared__ float wm2[4][2];    // [warp][{sum, sumsq}]
    __shared__ float wg[4];        // [warp] gcn partials

    float accx = 0.f, accy = 0.f;
    float zloc[4] = {0.f, 0.f, 0.f, 0.f};

    // single pass: softmax numerators (no max shift; logits are O(10)) + gather
    for (int t0 = row0; t0 < row1; t0 += 128) {
        int cnt = min(128, row1 - t0);
        if (tid < cnt) {
            int s = g_esrc[t0 + tid];
            src_sh[tid] = s;
            float4 av = *(const float4*)(g_als + s * HEADS);
            float p0 = __expf(leaky(av.x + ald[0]));
            float p1 = __expf(leaky(av.y + ald[1]));
            float p2 = __expf(leaky(av.z + ald[2]));
            float p3 = __expf(leaky(av.w + ald[3]));
            p_sh[tid][0] = p0; p_sh[tid][1] = p1;
            p_sh[tid][2] = p2; p_sh[tid][3] = p3;
            zloc[0] += p0; zloc[1] += p1; zloc[2] += p2; zloc[3] += p3;
        }
        __syncthreads();
#pragma unroll 4
        for (int e = 0; e < cnt; e++) {
            int s = src_sh[e];
            float2 hv = __half22float2(g_hh[(long)s * HC2 + tid]);
            float p = p_sh[e][head];
            accx = fmaf(p, hv.x, accx);
            accy = fmaf(p, hv.y, accy);
        }
        __syncthreads();
    }

    // ---- softmax denominators: warp shuffle + tiny smem combine ----
#pragma unroll
    for (int o = 16; o > 0; o >>= 1) {
#pragma unroll
        for (int h = 0; h < 4; h++)
            zloc[h] += __shfl_xor_sync(0xffffffffu, zloc[h], o);
    }
    if (lane == 0) {
        wz[warp][0] = zloc[0]; wz[warp][1] = zloc[1];
        wz[warp][2] = zloc[2]; wz[warp][3] = zloc[3];
    }
    __syncthreads();
    float z = wz[0][head] + wz[1][head] + wz[2][head] + wz[3][head];

    int c0 = 2 * tid, c1 = 2 * tid + 1;
    float zinv = 1.f / z;
    float v0 = fmaxf(accx * zinv + bgat[c0], 0.f);
    float v1 = fmaxf(accy * zinv + bgat[c1], 0.f);

    // ---- LayerNorm stats: shuffle + combine ----
    float s1 = v0 + v1;
    float s2 = fmaf(v0, v0, v1 * v1);
#pragma unroll
    for (int o = 16; o > 0; o >>= 1) {
        s1 += __shfl_xor_sync(0xffffffffu, s1, o);
        s2 += __shfl_xor_sync(0xffffffffu, s2, o);
    }
    if (lane == 0) { wm2[warp][0] = s1; wm2[warp][1] = s2; }
    __syncthreads();
    float tot  = wm2[0][0] + wm2[1][0] + wm2[2][0] + wm2[3][0];
    float tot2 = wm2[0][1] + wm2[1][1] + wm2[2][1] + wm2[3][1];
    float mu = tot * (1.f / 256.f);
    float var = tot2 * (1.f / 256.f) - mu * mu;
    float rs = rsqrtf(var + LN_EPS);
    float a0 = (v0 - mu) * rs * gamma[c0] + beta[c0];
    float a1 = (v1 - mu) * rs * gamma[c1] + beta[c1];

    // ---- project onto W_gcn (scalar per node): shuffle + combine ----
    float g = fmaf(a0, wgcn[c0], a1 * wgcn[c1]);
#pragma unroll
    for (int o = 16; o > 0; o >>= 1) g += __shfl_xor_sync(0xffffffffu, g, o);
    if (lane == 0) wg[warp] = g;
    __syncthreads();
    if (tid == 0) {
        g_dh[d] = make_float2(rsqrtf((float)(row1 - row0)),
                              wg[0] + wg[1] + wg[2] + wg[3]);
    }
}

// ---------------- GCN aggregation: warp per node (+ g_deg re-zero) ------------
__global__ void k_gcn(const float* __restrict__ bgcn, float* __restrict__ out, int N) {
    int gi = blockIdx.x * 128 + threadIdx.x;   // 320000 threads >= N
    if (gi < N) g_deg[gi] = 0;                 // zero for the NEXT call
    int d = blockIdx.x * 4 + (threadIdx.x >> 5);
    int lane = threadIdx.x & 31;
    if (d >= N) return;
    int row0 = g_off[d], row1 = g_off[d + 1];
    float sum = 0.f;
    for (int i = row0 + lane; i < row1; i += 32) {
        float2 dh = g_dh[g_esrc[i]];
        sum = fmaf(dh.x, dh.y, sum);
    }
#pragma unroll
    for (int o = 16; o > 0; o >>= 1) sum += __shfl_down_sync(0xffffffffu, sum, o);
    if (lane == 0) out[d] = bgcn[0] + g_dh[d].x * sum;
}

// ---------------- launch ------------------------------------------------------
extern "C" void kernel_launch(void* const* d_in, const int* in_sizes, int n_in,
                              void* d_out, int out_size) {
    const float* x     = (const float*)d_in[0];
    const int*   ei    = (const int*)  d_in[1];
    const float* Wgat  = (const float*)d_in[2];
    const float* asrc  = (const float*)d_in[3];
    const float* adst  = (const float*)d_in[4];
    const float* bgat  = (const float*)d_in[5];
    const float* gamma = (const float*)d_in[6];
    const float* beta  = (const float*)d_in[7];
    const float* wgcn  = (const float*)d_in[8];
    const float* bgcn  = (const float*)d_in[9];
    float* out = (float*)d_out;

    int N = in_sizes[0] / IN_C;
    int E = in_sizes[1] / 2;
    const int* src = ei;
    const int* dst = ei + E;

    // one-time side-stream resources (created outside any capture)
    static cudaStream_t s_csr = nullptr;
    static cudaEvent_t  ev_fork = nullptr, ev_join = nullptr;
    if (s_csr == nullptr) {
        cudaStreamCreateWithFlags(&s_csr, cudaStreamNonBlocking);
        cudaEventCreateWithFlags(&ev_fork, cudaEventDisableTiming);
        cudaEventCreateWithFlags(&ev_join, cudaEventDisableTiming);
    }

    // fork: CSR chain on s_csr, GEMM on the main (capture) stream.
    // g_deg is zero on entry (module load zero-init; k_gcn re-zeroes each call).
    cudaEventRecord(ev_fork, 0);
    cudaStreamWaitEvent(s_csr, ev_fork, 0);

    k_count<<<(E + 1023) / 1024, 256, 0, s_csr>>>(dst, E);
    k_scan<<<1, 1024, 0, s_csr>>>(N);
    k_scatter<<<(E + N + 1023) / 1024, 256, 0, s_csr>>>(src, dst, E, N);
    cudaEventRecord(ev_join, s_csr);

    dim3 gb(HC / 64, (N + 63) / 64);
    k_gemm<<<gb, 128>>>(x, Wgat, asrc, adst, N);

    // join: k_gat needs both CSR and GEMM outputs
    cudaStreamWaitEvent(0, ev_join, 0);
    k_gat<<<N, 128>>>(bgat, gamma, beta, wgcn, N);
    k_gcn<<<(N + 3) / 4, 128>>>(bgcn, out, N);
}

// round 11
// speedup vs baseline: 1.9345x; 1.1542x over previous
#include <cuda_runtime.h>
#include <cuda_fp16.h>

#define IN_C   256
#define HC     256
#define HEADS  4
#define CPH    64
#define HC2    128          // half2 count per row
#define NMAX   10000
#define EMAX   320000
#define ETMAX  (EMAX + NMAX)
#define NEG_SLOPE 0.2f
#define LN_EPS 1e-5f

// ---------------- scratch (static device memory; no allocations) -------------
__device__ __align__(16) __half2 g_hh[NMAX * HC2]; // GAT features (fp16 pairs)
__device__ __align__(16) __half  g_xh[NMAX * IN_C]; // X in fp16
__device__ __align__(16) __half  g_wh[IN_C * HC];   // W_gat in fp16 (k-major)
__device__ float  g_als[NMAX * HEADS];
__device__ float  g_ald[NMAX * HEADS];
__device__ __align__(16) int g_deg[NMAX];          // zero at load + re-zeroed by k_gcn
__device__ int    g_off[NMAX + 1];
__device__ int    g_cur[NMAX];
__device__ int    g_esrc[ETMAX];       // CSR by dst: src node of each in-edge
__device__ float2 g_dh[NMAX];          // {dinv, h2} packed

// ---------------- CSR construction -------------------------------------------
__global__ void k_count(const int* __restrict__ dst, int E) {
    int i0 = (blockIdx.x * blockDim.x + threadIdx.x) * 4;
    if (i0 + 3 < E) {
        int4 d4 = *(const int4*)(dst + i0);
        atomicAdd(&g_deg[d4.x], 1);
        atomicAdd(&g_deg[d4.y], 1);
        atomicAdd(&g_deg[d4.z], 1);
        atomicAdd(&g_deg[d4.w], 1);
    } else {
        for (int j = 0; j < 4; j++) {
            int i = i0 + j;
            if (i < E) atomicAdd(&g_deg[dst[i]], 1);
        }
    }
}

// single-block exclusive scan of (g_deg + 1) -> g_off / g_cur, 4 elems/thread
__global__ void k_scan(int N) {
    __shared__ int warp_sums[32];
    __shared__ int carry_s;
    int tid = threadIdx.x;
    int lane = tid & 31, wid = tid >> 5;
    if (tid == 0) carry_s = 0;
    __syncthreads();
    for (int base = 0; base < N; base += 4096) {
        int i0 = base + tid * 4;
        int v0 = 0, v1 = 0, v2 = 0, v3 = 0;
        if (i0 + 3 < N) {
            int4 dv = *(const int4*)&g_deg[i0];
            v0 = dv.x + 1; v1 = dv.y + 1; v2 = dv.z + 1; v3 = dv.w + 1;
        } else {
            if (i0     < N) v0 = g_deg[i0]     + 1;
            if (i0 + 1 < N) v1 = g_deg[i0 + 1] + 1;
            if (i0 + 2 < N) v2 = g_deg[i0 + 2] + 1;
            if (i0 + 3 < N) v3 = g_deg[i0 + 3] + 1;
        }
        int v = v0 + v1 + v2 + v3;
        int incl = v;
#pragma unroll
        for (int s = 1; s < 32; s <<= 1) {
            int t = __shfl_up_sync(0xffffffffu, incl, s);
            if (lane >= s) incl += t;
        }
        if (lane == 31) warp_sums[wid] = incl;
        __syncthreads();
        if (wid == 0) {
            int w = warp_sums[lane];
#pragma unroll
            for (int s = 1; s < 32; s <<= 1) {
                int t = __shfl_up_sync(0xffffffffu, w, s);
                if (lane >= s) w += t;
            }
            warp_sums[lane] = w;
        }
        __syncthreads();
        int warp_base = (wid > 0) ? warp_sums[wid - 1] : 0;
        int c = carry_s;
        int incl_blk = warp_base + incl;
        int e0 = c + incl_blk - v;
        int e1 = e0 + v0, e2 = e1 + v1, e3 = e2 + v2;
        if (i0     < N) { g_off[i0]     = e0; g_cur[i0]     = e0; if (i0     == N - 1) g_off[N] = e1; }
        if (i0 + 1 < N) { g_off[i0 + 1] = e1; g_cur[i0 + 1] = e1; if (i0 + 1 == N - 1) g_off[N] = e2; }
        if (i0 + 2 < N) { g_off[i0 + 2] = e2; g_cur[i0 + 2] = e2; if (i0 + 2 == N - 1) g_off[N] = e3; }
        if (i0 + 3 < N) { g_off[i0 + 3] = e3; g_cur[i0 + 3] = e3; if (i0 + 3 == N - 1) g_off[N] = e3 + v3; }
        __syncthreads();
        if (tid == 1023) carry_s = c + incl_blk;
        __syncthreads();
    }
}

__global__ void k_scatter(const int* __restrict__ src, const int* __restrict__ dst,
                          int E, int N) {
    int i0 = (blockIdx.x * blockDim.x + threadIdx.x) * 4;
    if (i0 + 3 < E) {
        int4 s4 = *(const int4*)(src + i0);
        int4 d4 = *(const int4*)(dst + i0);
        int p0 = atomicAdd(&g_cur[d4.x], 1);
        int p1 = atomicAdd(&g_cur[d4.y], 1);
        int p2 = atomicAdd(&g_cur[d4.z], 1);
        int p3 = atomicAdd(&g_cur[d4.w], 1);
        g_esrc[p0] = s4.x; g_esrc[p1] = s4.y;
        g_esrc[p2] = s4.z; g_esrc[p3] = s4.w;
    } else {
        for (int j = 0; j < 4; j++) {
            int i = i0 + j;
            if (i >= E + N) break;
            int d, s;
            if (i < E) { d = dst[i]; s = src[i]; }
            else       { d = i - E;  s = i - E;  }   // self loop
            int pos = atomicAdd(&g_cur[d], 1);
            g_esrc[pos] = s;
        }
    }
}

// ---------------- fp32 -> fp16 convert for X and W (one kernel) ---------------
__global__ void k_half(const float* __restrict__ X, const float* __restrict__ W, int N) {
    int t = blockIdx.x * 256 + threadIdx.x;      // 8 elems per thread
    int nx = N * (IN_C / 8);
    const float* sp;
    __half* dp;
    if (t < nx) {
        sp = X + (long)t * 8;
        dp = g_xh + (long)t * 8;
    } else {
        int u = t - nx;
        if (u >= IN_C * HC / 8) return;
        sp = W + (long)u * 8;
        dp = g_wh + (long)u * 8;
    }
    float4 a = *(const float4*)sp;
    float4 b = *(const float4*)(sp + 4);
    __half2 h[4];
    h[0] = __floats2half2_rn(a.x, a.y);
    h[1] = __floats2half2_rn(a.z, a.w);
    h[2] = __floats2half2_rn(b.x, b.y);
    h[3] = __floats2half2_rn(b.z, b.w);
    *(uint4*)dp = *(uint4*)h;
}

// ---------------- tensor-core GEMM + fused logits + fp16 h store --------------
// 64x64 tile, 128 threads (4 warps, 2x2), m16n8k16 fp16 mma, fp32 accumulate.
// fp16 inputs (g_xh, g_wh) loaded via cp.async, double-buffered k-slices of 64.
// A smem: [m][k] swizzled; B smem: [k][n] swizzled, B frags via ldmatrix.trans.
// XOR swizzle: unit(r,c) = r*8 + (c ^ (r&7)), 16B units, 8 units/row.
__device__ __forceinline__ void mma16816(float* c, const unsigned* a, const unsigned* b) {
    asm volatile("mma.sync.aligned.m16n8k16.row.col.f32.f16.f16.f32 "
                 "{%0,%1,%2,%3}, {%4,%5,%6,%7}, {%8,%9}, {%0,%1,%2,%3};"
                 : "+f"(c[0]), "+f"(c[1]), "+f"(c[2]), "+f"(c[3])
                 : "r"(a[0]), "r"(a[1]), "r"(a[2]), "r"(a[3]),
                   "r"(b[0]), "r"(b[1]));
}

__device__ __forceinline__ void cp16(unsigned dst, const void* src, int src_sz) {
    asm volatile("cp.async.cg.shared.global [%0], [%1], 16, %2;"
                 :: "r"(dst), "l"(__cvta_generic_to_global(src)), "r"(src_sz));
}

__global__ void __launch_bounds__(128) k_gemm(const float* __restrict__ asrc,
                                              const float* __restrict__ adst,
                                              int N) {
    __shared__ __align__(16) __half As[2][64 * 64];
    __shared__ __align__(16) __half Bs[2][64 * 64];
    __shared__ float part_s[64], part_d[64];   // cross-warp logit partials
    int tid = threadIdx.x;
    int lane = tid & 31, w = tid >> 5;
    int wm = w >> 1, wn = w & 1;
    int head = blockIdx.x;               // 64 cols == one head
    int mblk = blockIdx.y * 64;
    unsigned asb = (unsigned)__cvta_generic_to_shared(&As[0][0]);
    unsigned bsb = (unsigned)__cvta_generic_to_shared(&Bs[0][0]);

    // per-thread loader geometry: row r = tid>>1, 4 units starting (tid&1)*4
    int lr = tid >> 1;
    int lcu = (tid & 1) * 4;
    int arow = mblk + lr;
    int asz = (arow < N) ? 16 : 0;
    const __half* pa = g_xh + (long)min(arow, N - 1) * IN_C + lcu * 8;
    const __half* pb = g_wh + (long)lr * HC + head * 64 + lcu * 8;

    float c[2][4][4];
#pragma unroll
    for (int i = 0; i < 2; i++)
#pragma unroll
        for (int j = 0; j < 4; j++)
#pragma unroll
            for (int q = 0; q < 4; q++) c[i][j][q] = 0.f;

    // issue slice s into buffer buf
    auto load_slice = [&](int s, int buf) {
        unsigned ab = asb + buf * 8192;
        unsigned bb = bsb + buf * 8192;
#pragma unroll
        for (int u = 0; u < 4; u++) {
            int cc = lcu + u;
            int unit = lr * 8 + (cc ^ (lr & 7));
            cp16(ab + unit * 16, pa + s * 64 + u * 8, asz);
            cp16(bb + unit * 16, pb + (long)s * 64 * HC + u * 8, 16);
        }
    };

    load_slice(0, 0);
    asm volatile("cp.async.commit_group;");

    for (int s = 0; s < 4; s++) {
        if (s < 3) {
            load_slice(s + 1, (s + 1) & 1);
            asm volatile("cp.async.commit_group;");
            asm volatile("cp.async.wait_group 1;");
        } else {
            asm volatile("cp.async.wait_group 0;");
        }
        __syncthreads();

        unsigned ab = asb + (s & 1) * 8192;
        unsigned bb = bsb + (s & 1) * 8192;
#pragma unroll
        for (int kk = 0; kk < 4; kk++) {
            unsigned af[2][4], bf[4][2];
#pragma unroll
            for (int i = 0; i < 2; i++) {
                int r = wm * 32 + i * 16 + (lane & 15);
                int cc = 2 * kk + (lane >> 4);
                int unit = r * 8 + (cc ^ (r & 7));
                unsigned addr = ab + unit * 16;
                asm volatile("ldmatrix.sync.aligned.m8n8.x4.shared.b16 "
                             "{%0,%1,%2,%3}, [%4];"
                             : "=r"(af[i][0]), "=r"(af[i][1]),
                               "=r"(af[i][2]), "=r"(af[i][3])
                             : "r"(addr));
            }
#pragma unroll
            for (int j = 0; j < 4; j++) {
                int l = lane & 15;
                int r = kk * 16 + l;
                int cc = wn * 4 + j;
                int unit = r * 8 + (cc ^ (r & 7));
                unsigned addr = bb + unit * 16;
                asm volatile("ldmatrix.sync.aligned.m8n8.x2.trans.shared.b16 "
                             "{%0,%1}, [%2];"
                             : "=r"(bf[j][0]), "=r"(bf[j][1])
                             : "r"(addr));
            }
#pragma unroll
            for (int i = 0; i < 2; i++)
#pragma unroll
                for (int j = 0; j < 4; j++)
                    mma16816(c[i][j], af[i], bf[j]);
        }
        __syncthreads();   // protect buffer (s&1) before it is refilled
    }

    // ---- epilogue: fp16 h store + fused logit reduction ----------------------
    int grp = lane >> 2, tq = lane & 3;
    float as0[4], as1[4], ad0[4], ad1[4];
#pragma unroll
    for (int j = 0; j < 4; j++) {
        int col = wn * 32 + j * 8 + 2 * tq;
        as0[j] = asrc[head * CPH + col];     as1[j] = asrc[head * CPH + col + 1];
        ad0[j] = adst[head * CPH + col];     ad1[j] = adst[head * CPH + col + 1];
    }

#pragma unroll
    for (int i = 0; i < 2; i++) {
        int lr0 = wm * 32 + i * 16 + grp;     // row within block tile
        int lr1 = lr0 + 8;
        int r0 = mblk + lr0;
        int r1 = mblk + lr1;
        float ps0 = 0.f, pd0 = 0.f, ps1 = 0.f, pd1 = 0.f;
#pragma unroll
        for (int j = 0; j < 4; j++) {
            ps0 = fmaf(c[i][j][0], as0[j], fmaf(c[i][j][1], as1[j], ps0));
            pd0 = fmaf(c[i][j][0], ad0[j], fmaf(c[i][j][1], ad1[j], pd0));
            ps1 = fmaf(c[i][j][2], as0[j], fmaf(c[i][j][3], as1[j], ps1));
            pd1 = fmaf(c[i][j][2], ad0[j], fmaf(c[i][j][3], ad1[j], pd1));
            int gcol = head * 64 + wn * 32 + j * 8 + 2 * tq;
            if (r0 < N)
                g_hh[(long)r0 * HC2 + (gcol >> 1)] =
                    __floats2half2_rn(c[i][j][0], c[i][j][1]);
            if (r1 < N)
                g_hh[(long)r1 * HC2 + (gcol >> 1)] =
                    __floats2half2_rn(c[i][j][2], c[i][j][3]);
        }
#pragma unroll
        for (int o = 1; o < 4; o <<= 1) {
            ps0 += __shfl_xor_sync(0xffffffffu, ps0, o);
            pd0 += __shfl_xor_sync(0xffffffffu, pd0, o);
            ps1 += __shfl_xor_sync(0xffffffffu, ps1, o);
            pd1 += __shfl_xor_sync(0xffffffffu, pd1, o);
        }
        // cross-wn reduction: wn==0 deposits, wn==1 combines + stores
        if (tq == 0 && wn == 0) {
            part_s[lr0] = ps0; part_d[lr0] = pd0;
            part_s[lr1] = ps1; part_d[lr1] = pd1;
        }
        __syncthreads();
        if (tq == 0 && wn == 1) {
            if (r0 < N) {
                g_als[r0 * HEADS + head] = ps0 + part_s[lr0];
                g_ald[r0 * HEADS + head] = pd0 + part_d[lr0];
            }
            if (r1 < N) {
                g_als[r1 * HEADS + head] = ps1 + part_s[lr1];
                g_ald[r1 * HEADS + head] = pd1 + part_d[lr1];
            }
        }
        __syncthreads();   // part_* reused next i-iteration
    }
}

__device__ __forceinline__ float leaky(float v) {
    return v > 0.f ? v : NEG_SLOPE * v;
}

// ---------------- fused GAT aggregation + bias + ReLU + LN + GCN proj ---------
__global__ void __launch_bounds__(128) k_gat(const float* __restrict__ bgat,
                                             const float* __restrict__ gamma,
                                             const float* __restrict__ beta,
                                             const float* __restrict__ wgcn,
                                             int N) {
    int d = blockIdx.x;
    int tid = threadIdx.x;               // thread -> half2 index (channels 2t,2t+1)
    int lane = tid & 31, warp = tid >> 5;
    int head = warp;                     // 32 half2 per head
    int row0 = g_off[d], row1 = g_off[d + 1];

    float4 aldv = *(const float4*)(g_ald + d * HEADS);
    float ald[4] = {aldv.x, aldv.y, aldv.z, aldv.w};

    __shared__ float p_sh[128][4];
    __shared__ int   src_sh[128];
    __shared__ float wz[4][4];     // [warp][head] z partials
    __shared__ float wm2[4][2];    // [warp][{sum, sumsq}]
    __shared__ float wg[4];        // [warp] gcn partials

    float accx = 0.f, accy = 0.f;
    float zloc[4] = {0.f, 0.f, 0.f, 0.f};

    // single pass: softmax numerators (no max shift; logits are O(10)) + gather
    for (int t0 = row0; t0 < row1; t0 += 128) {
        int cnt = min(128, row1 - t0);
        if (tid < cnt) {
            int s = g_esrc[t0 + tid];
            src_sh[tid] = s;
            float4 av = *(const float4*)(g_als + s * HEADS);
            float p0 = __expf(leaky(av.x + ald[0]));
            float p1 = __expf(leaky(av.y + ald[1]));
            float p2 = __expf(leaky(av.z + ald[2]));
            float p3 = __expf(leaky(av.w + ald[3]));
            p_sh[tid][0] = p0; p_sh[tid][1] = p1;
            p_sh[tid][2] = p2; p_sh[tid][3] = p3;
            zloc[0] += p0; zloc[1] += p1; zloc[2] += p2; zloc[3] += p3;
        }
        __syncthreads();
#pragma unroll 4
        for (int e = 0; e < cnt; e++) {
            int s = src_sh[e];
            float2 hv = __half22float2(g_hh[(long)s * HC2 + tid]);
            float p = p_sh[e][head];
            accx = fmaf(p, hv.x, accx);
            accy = fmaf(p, hv.y, accy);
        }
        __syncthreads();
    }

    // ---- softmax denominators: warp shuffle + tiny smem combine ----
#pragma unroll
    for (int o = 16; o > 0; o >>= 1) {
#pragma unroll
        for (int h = 0; h < 4; h++)
            zloc[h] += __shfl_xor_sync(0xffffffffu, zloc[h], o);
    }
    if (lane == 0) {
        wz[warp][0] = zloc[0]; wz[warp][1] = zloc[1];
        wz[warp][2] = zloc[2]; wz[warp][3] = zloc[3];
    }
    __syncthreads();
    float z = wz[0][head] + wz[1][head] + wz[2][head] + wz[3][head];

    int c0 = 2 * tid, c1 = 2 * tid + 1;
    float zinv = 1.f / z;
    float v0 = fmaxf(accx * zinv + bgat[c0], 0.f);
    float v1 = fmaxf(accy * zinv + bgat[c1], 0.f);

    // ---- LayerNorm stats: shuffle + combine ----
    float s1 = v0 + v1;
    float s2 = fmaf(v0, v0, v1 * v1);
#pragma unroll
    for (int o = 16; o > 0; o >>= 1) {
        s1 += __shfl_xor_sync(0xffffffffu, s1, o);
        s2 += __shfl_xor_sync(0xffffffffu, s2, o);
    }
    if (lane == 0) { wm2[warp][0] = s1; wm2[warp][1] = s2; }
    __syncthreads();
    float tot  = wm2[0][0] + wm2[1][0] + wm2[2][0] + wm2[3][0];
    float tot2 = wm2[0][1] + wm2[1][1] + wm2[2][1] + wm2[3][1];
    float mu = tot * (1.f / 256.f);
    float var = tot2 * (1.f / 256.f) - mu * mu;
    float rs = rsqrtf(var + LN_EPS);
    float a0 = (v0 - mu) * rs * gamma[c0] + beta[c0];
    float a1 = (v1 - mu) * rs * gamma[c1] + beta[c1];

    // ---- project onto W_gcn (scalar per node): shuffle + combine ----
    float g = fmaf(a0, wgcn[c0], a1 * wgcn[c1]);
#pragma unroll
    for (int o = 16; o > 0; o >>= 1) g += __shfl_xor_sync(0xffffffffu, g, o);
    if (lane == 0) wg[warp] = g;
    __syncthreads();
    if (tid == 0) {
        g_dh[d] = make_float2(rsqrtf((float)(row1 - row0)),
                              wg[0] + wg[1] + wg[2] + wg[3]);
    }
}

// ---------------- GCN aggregation: warp per node (+ g_deg re-zero) ------------
__global__ void k_gcn(const float* __restrict__ bgcn, float* __restrict__ out, int N) {
    int gi = blockIdx.x * 128 + threadIdx.x;   // 320000 threads >= N
    if (gi < N) g_deg[gi] = 0;                 // zero for the NEXT call
    int d = blockIdx.x * 4 + (threadIdx.x >> 5);
    int lane = threadIdx.x & 31;
    if (d >= N) return;
    int row0 = g_off[d], row1 = g_off[d + 1];
    float sum = 0.f;
    for (int i = row0 + lane; i < row1; i += 32) {
        float2 dh = g_dh[g_esrc[i]];
        sum = fmaf(dh.x, dh.y, sum);
    }
#pragma unroll
    for (int o = 16; o > 0; o >>= 1) sum += __shfl_down_sync(0xffffffffu, sum, o);
    if (lane == 0) out[d] = bgcn[0] + g_dh[d].x * sum;
}

// ---------------- launch ------------------------------------------------------
extern "C" void kernel_launch(void* const* d_in, const int* in_sizes, int n_in,
                              void* d_out, int out_size) {
    const float* x     = (const float*)d_in[0];
    const int*   ei    = (const int*)  d_in[1];
    const float* Wgat  = (const float*)d_in[2];
    const float* asrc  = (const float*)d_in[3];
    const float* adst  = (const float*)d_in[4];
    const float* bgat  = (const float*)d_in[5];
    const float* gamma = (const float*)d_in[6];
    const float* beta  = (const float*)d_in[7];
    const float* wgcn  = (const float*)d_in[8];
    const float* bgcn  = (const float*)d_in[9];
    float* out = (float*)d_out;

    int N = in_sizes[0] / IN_C;
    int E = in_sizes[1] / 2;
    const int* src = ei;
    const int* dst = ei + E;

    // one-time side-stream resources (created outside any capture)
    static cudaStream_t s_csr = nullptr;
    static cudaEvent_t  ev_fork = nullptr, ev_join = nullptr;
    if (s_csr == nullptr) {
        cudaStreamCreateWithFlags(&s_csr, cudaStreamNonBlocking);
        cudaEventCreateWithFlags(&ev_fork, cudaEventDisableTiming);
        cudaEventCreateWithFlags(&ev_join, cudaEventDisableTiming);
    }

    // fork: CSR chain on s_csr, fp16 convert + GEMM on the main stream.
    cudaEventRecord(ev_fork, 0);
    cudaStreamWaitEvent(s_csr, ev_fork, 0);

    k_count<<<(E + 1023) / 1024, 256, 0, s_csr>>>(dst, E);
    k_scan<<<1, 1024, 0, s_csr>>>(N);
    k_scatter<<<(E + N + 1023) / 1024, 256, 0, s_csr>>>(src, dst, E, N);
    cudaEventRecord(ev_join, s_csr);

    int conv_threads = N * (IN_C / 8) + (IN_C * HC / 8);
    k_half<<<(conv_threads + 255) / 256, 256>>>(x, Wgat, N);
    dim3 gb(HC / 64, (N + 63) / 64);
    k_gemm<<<gb, 128>>>(asrc, adst, N);

    // join: k_gat needs both CSR and GEMM outputs
    cudaStreamWaitEvent(0, ev_join, 0);
    k_gat<<<N, 128>>>(bgat, gamma, beta, wgcn, N);
    k_gcn<<<(N + 3) / 4, 128>>>(bgcn, out, N);
}

// round 12
// speedup vs baseline: 2.4744x; 1.2791x over previous
#include <cuda_runtime.h>
#include <cuda_fp16.h>

#define IN_C   256
#define HC     256
#define HEADS  4
#define CPH    64
#define HC2    128          // half2 count per row
#define NMAX   10000
#define EMAX   320000
#define ETMAX  (EMAX + NMAX)
#define NEG_SLOPE 0.2f
#define LN_EPS 1e-5f

// ---------------- scratch (static device memory; no allocations) -------------
__device__ __align__(16) __half2 g_hh[NMAX * HC2]; // GAT features (fp16 pairs)
__device__ __align__(16) __half  g_xh[NMAX * IN_C]; // X in fp16
__device__ __align__(16) __half  g_wh[IN_C * HC];   // W_gat in fp16 (k-major)
__device__ float  g_als[NMAX * HEADS];
__device__ float  g_ald[NMAX * HEADS];
__device__ __align__(16) int g_deg[NMAX];          // zero at load + re-zeroed by k_gcn
__device__ int    g_off[NMAX + 1];
__device__ int    g_cur[NMAX];
__device__ int    g_esrc[ETMAX];       // CSR by dst: src node of each in-edge
__device__ float2 g_dh[NMAX];          // {dinv, h2} packed

// ---------------- CSR construction -------------------------------------------
__global__ void k_count(const int* __restrict__ dst, int E) {
    int i0 = (blockIdx.x * blockDim.x + threadIdx.x) * 4;
    if (i0 + 3 < E) {
        int4 d4 = *(const int4*)(dst + i0);
        atomicAdd(&g_deg[d4.x], 1);
        atomicAdd(&g_deg[d4.y], 1);
        atomicAdd(&g_deg[d4.z], 1);
        atomicAdd(&g_deg[d4.w], 1);
    } else {
        for (int j = 0; j < 4; j++) {
            int i = i0 + j;
            if (i < E) atomicAdd(&g_deg[dst[i]], 1);
        }
    }
}

// single-block exclusive scan of (g_deg + 1) -> g_off / g_cur, 4 elems/thread
__global__ void k_scan(int N) {
    __shared__ int warp_sums[32];
    __shared__ int carry_s;
    int tid = threadIdx.x;
    int lane = tid & 31, wid = tid >> 5;
    if (tid == 0) carry_s = 0;
    __syncthreads();
    for (int base = 0; base < N; base += 4096) {
        int i0 = base + tid * 4;
        int v0 = 0, v1 = 0, v2 = 0, v3 = 0;
        if (i0 + 3 < N) {
            int4 dv = *(const int4*)&g_deg[i0];
            v0 = dv.x + 1; v1 = dv.y + 1; v2 = dv.z + 1; v3 = dv.w + 1;
        } else {
            if (i0     < N) v0 = g_deg[i0]     + 1;
            if (i0 + 1 < N) v1 = g_deg[i0 + 1] + 1;
            if (i0 + 2 < N) v2 = g_deg[i0 + 2] + 1;
            if (i0 + 3 < N) v3 = g_deg[i0 + 3] + 1;
        }
        int v = v0 + v1 + v2 + v3;
        int incl = v;
#pragma unroll
        for (int s = 1; s < 32; s <<= 1) {
            int t = __shfl_up_sync(0xffffffffu, incl, s);
            if (lane >= s) incl += t;
        }
        if (lane == 31) warp_sums[wid] = incl;
        __syncthreads();
        if (wid == 0) {
            int w = warp_sums[lane];
#pragma unroll
            for (int s = 1; s < 32; s <<= 1) {
                int t = __shfl_up_sync(0xffffffffu, w, s);
                if (lane >= s) w += t;
            }
            warp_sums[lane] = w;
        }
        __syncthreads();
        int warp_base = (wid > 0) ? warp_sums[wid - 1] : 0;
        int c = carry_s;
        int incl_blk = warp_base + incl;
        int e0 = c + incl_blk - v;
        int e1 = e0 + v0, e2 = e1 + v1, e3 = e2 + v2;
        if (i0     < N) { g_off[i0]     = e0; g_cur[i0]     = e0; if (i0     == N - 1) g_off[N] = e1; }
        if (i0 + 1 < N) { g_off[i0 + 1] = e1; g_cur[i0 + 1] = e1; if (i0 + 1 == N - 1) g_off[N] = e2; }
        if (i0 + 2 < N) { g_off[i0 + 2] = e2; g_cur[i0 + 2] = e2; if (i0 + 2 == N - 1) g_off[N] = e3; }
        if (i0 + 3 < N) { g_off[i0 + 3] = e3; g_cur[i0 + 3] = e3; if (i0 + 3 == N - 1) g_off[N] = e3 + v3; }
        __syncthreads();
        if (tid == 1023) carry_s = c + incl_blk;
        __syncthreads();
    }
}

__global__ void k_scatter(const int* __restrict__ src, const int* __restrict__ dst,
                          int E, int N) {
    int i0 = (blockIdx.x * blockDim.x + threadIdx.x) * 4;
    if (i0 + 3 < E) {
        int4 s4 = *(const int4*)(src + i0);
        int4 d4 = *(const int4*)(dst + i0);
        int p0 = atomicAdd(&g_cur[d4.x], 1);
        int p1 = atomicAdd(&g_cur[d4.y], 1);
        int p2 = atomicAdd(&g_cur[d4.z], 1);
        int p3 = atomicAdd(&g_cur[d4.w], 1);
        g_esrc[p0] = s4.x; g_esrc[p1] = s4.y;
        g_esrc[p2] = s4.z; g_esrc[p3] = s4.w;
    } else {
        for (int j = 0; j < 4; j++) {
            int i = i0 + j;
            if (i >= E + N) break;
            int d, s;
            if (i < E) { d = dst[i]; s = src[i]; }
            else       { d = i - E;  s = i - E;  }   // self loop
            int pos = atomicAdd(&g_cur[d], 1);
            g_esrc[pos] = s;
        }
    }
}

// ---------------- fp32 -> fp16 convert for X and W (one kernel) ---------------
__global__ void k_half(const float* __restrict__ X, const float* __restrict__ W, int N) {
    int t = blockIdx.x * 256 + threadIdx.x;      // 8 elems per thread
    int nx = N * (IN_C / 8);
    const float* sp;
    __half* dp;
    if (t < nx) {
        sp = X + (long)t * 8;
        dp = g_xh + (long)t * 8;
    } else {
        int u = t - nx;
        if (u >= IN_C * HC / 8) return;
        sp = W + (long)u * 8;
        dp = g_wh + (long)u * 8;
    }
    float4 a = *(const float4*)sp;
    float4 b = *(const float4*)(sp + 4);
    __half2 h[4];
    h[0] = __floats2half2_rn(a.x, a.y);
    h[1] = __floats2half2_rn(a.z, a.w);
    h[2] = __floats2half2_rn(b.x, b.y);
    h[3] = __floats2half2_rn(b.z, b.w);
    *(uint4*)dp = *(uint4*)h;
}

// ---------------- tensor-core GEMM + fused logits + fp16 h store --------------
// 64x64 tile, 128 threads (4 warps, 2x2), m16n8k16 fp16 mma, fp32 accumulate.
// fp16 inputs (g_xh, g_wh) loaded via cp.async, double-buffered k-slices of 64.
// A smem: [m][k] swizzled; B smem: [k][n] swizzled, B frags via ldmatrix.trans.
// XOR swizzle: unit(r,c) = r*8 + (c ^ (r&7)), 16B units, 8 units/row.
__device__ __forceinline__ void mma16816(float* c, const unsigned* a, const unsigned* b) {
    asm volatile("mma.sync.aligned.m16n8k16.row.col.f32.f16.f16.f32 "
                 "{%0,%1,%2,%3}, {%4,%5,%6,%7}, {%8,%9}, {%0,%1,%2,%3};"
                 : "+f"(c[0]), "+f"(c[1]), "+f"(c[2]), "+f"(c[3])
                 : "r"(a[0]), "r"(a[1]), "r"(a[2]), "r"(a[3]),
                   "r"(b[0]), "r"(b[1]));
}

__device__ __forceinline__ void cp16(unsigned dst, const void* src, int src_sz) {
    asm volatile("cp.async.cg.shared.global [%0], [%1], 16, %2;"
                 :: "r"(dst), "l"(__cvta_generic_to_global(src)), "r"(src_sz));
}

__global__ void __launch_bounds__(128) k_gemm(const float* __restrict__ asrc,
                                              const float* __restrict__ adst,
                                              int N) {
    __shared__ __align__(16) __half As[2][64 * 64];
    __shared__ __align__(16) __half Bs[2][64 * 64];
    __shared__ float part_s[64], part_d[64];   // cross-warp logit partials
    int tid = threadIdx.x;
    int lane = tid & 31, w = tid >> 5;
    int wm = w >> 1, wn = w & 1;
    int head = blockIdx.x;               // 64 cols == one head
    int mblk = blockIdx.y * 64;
    unsigned asb = (unsigned)__cvta_generic_to_shared(&As[0][0]);
    unsigned bsb = (unsigned)__cvta_generic_to_shared(&Bs[0][0]);

    // per-thread loader geometry: row r = tid>>1, 4 units starting (tid&1)*4
    int lr = tid >> 1;
    int lcu = (tid & 1) * 4;
    int arow = mblk + lr;
    int asz = (arow < N) ? 16 : 0;
    const __half* pa = g_xh + (long)min(arow, N - 1) * IN_C + lcu * 8;
    const __half* pb = g_wh + (long)lr * HC + head * 64 + lcu * 8;

    float c[2][4][4];
#pragma unroll
    for (int i = 0; i < 2; i++)
#pragma unroll
        for (int j = 0; j < 4; j++)
#pragma unroll
            for (int q = 0; q < 4; q++) c[i][j][q] = 0.f;

    // issue slice s into buffer buf
    auto load_slice = [&](int s, int buf) {
        unsigned ab = asb + buf * 8192;
        unsigned bb = bsb + buf * 8192;
#pragma unroll
        for (int u = 0; u < 4; u++) {
            int cc = lcu + u;
            int unit = lr * 8 + (cc ^ (lr & 7));
            cp16(ab + unit * 16, pa + s * 64 + u * 8, asz);
            cp16(bb + unit * 16, pb + (long)s * 64 * HC + u * 8, 16);
        }
    };

    load_slice(0, 0);
    asm volatile("cp.async.commit_group;");

    for (int s = 0; s < 4; s++) {
        if (s < 3) {
            load_slice(s + 1, (s + 1) & 1);
            asm volatile("cp.async.commit_group;");
            asm volatile("cp.async.wait_group 1;");
        } else {
            asm volatile("cp.async.wait_group 0;");
        }
        __syncthreads();

        unsigned ab = asb + (s & 1) * 8192;
        unsigned bb = bsb + (s & 1) * 8192;
#pragma unroll
        for (int kk = 0; kk < 4; kk++) {
            unsigned af[2][4], bf[4][2];
#pragma unroll
            for (int i = 0; i < 2; i++) {
                int r = wm * 32 + i * 16 + (lane & 15);
                int cc = 2 * kk + (lane >> 4);
                int unit = r * 8 + (cc ^ (r & 7));
                unsigned addr = ab + unit * 16;
                asm volatile("ldmatrix.sync.aligned.m8n8.x4.shared.b16 "
                             "{%0,%1,%2,%3}, [%4];"
                             : "=r"(af[i][0]), "=r"(af[i][1]),
                               "=r"(af[i][2]), "=r"(af[i][3])
                             : "r"(addr));
            }
#pragma unroll
            for (int j = 0; j < 4; j++) {
                int l = lane & 15;
                int r = kk * 16 + l;
                int cc = wn * 4 + j;
                int unit = r * 8 + (cc ^ (r & 7));
                unsigned addr = bb + unit * 16;
                asm volatile("ldmatrix.sync.aligned.m8n8.x2.trans.shared.b16 "
                             "{%0,%1}, [%2];"
                             : "=r"(bf[j][0]), "=r"(bf[j][1])
                             : "r"(addr));
            }
#pragma unroll
            for (int i = 0; i < 2; i++)
#pragma unroll
                for (int j = 0; j < 4; j++)
                    mma16816(c[i][j], af[i], bf[j]);
        }
        __syncthreads();   // protect buffer (s&1) before it is refilled
    }

    // ---- epilogue: fp16 h store + fused logit reduction ----------------------
    int grp = lane >> 2, tq = lane & 3;
    float as0[4], as1[4], ad0[4], ad1[4];
#pragma unroll
    for (int j = 0; j < 4; j++) {
        int col = wn * 32 + j * 8 + 2 * tq;
        as0[j] = asrc[head * CPH + col];     as1[j] = asrc[head * CPH + col + 1];
        ad0[j] = adst[head * CPH + col];     ad1[j] = adst[head * CPH + col + 1];
    }

#pragma unroll
    for (int i = 0; i < 2; i++) {
        int lr0 = wm * 32 + i * 16 + grp;     // row within block tile
        int lr1 = lr0 + 8;
        int r0 = mblk + lr0;
        int r1 = mblk + lr1;
        float ps0 = 0.f, pd0 = 0.f, ps1 = 0.f, pd1 = 0.f;
#pragma unroll
        for (int j = 0; j < 4; j++) {
            ps0 = fmaf(c[i][j][0], as0[j], fmaf(c[i][j][1], as1[j], ps0));
            pd0 = fmaf(c[i][j][0], ad0[j], fmaf(c[i][j][1], ad1[j], pd0));
            ps1 = fmaf(c[i][j][2], as0[j], fmaf(c[i][j][3], as1[j], ps1));
            pd1 = fmaf(c[i][j][2], ad0[j], fmaf(c[i][j][3], ad1[j], pd1));
            int gcol = head * 64 + wn * 32 + j * 8 + 2 * tq;
            if (r0 < N)
                g_hh[(long)r0 * HC2 + (gcol >> 1)] =
                    __floats2half2_rn(c[i][j][0], c[i][j][1]);
            if (r1 < N)
                g_hh[(long)r1 * HC2 + (gcol >> 1)] =
                    __floats2half2_rn(c[i][j][2], c[i][j][3]);
        }
#pragma unroll
        for (int o = 1; o < 4; o <<= 1) {
            ps0 += __shfl_xor_sync(0xffffffffu, ps0, o);
            pd0 += __shfl_xor_sync(0xffffffffu, pd0, o);
            ps1 += __shfl_xor_sync(0xffffffffu, ps1, o);
            pd1 += __shfl_xor_sync(0xffffffffu, pd1, o);
        }
        // cross-wn reduction: wn==0 deposits, wn==1 combines + stores
        if (tq == 0 && wn == 0) {
            part_s[lr0] = ps0; part_d[lr0] = pd0;
            part_s[lr1] = ps1; part_d[lr1] = pd1;
        }
        __syncthreads();
        if (tq == 0 && wn == 1) {
            if (r0 < N) {
                g_als[r0 * HEADS + head] = ps0 + part_s[lr0];
                g_ald[r0 * HEADS + head] = pd0 + part_d[lr0];
            }
            if (r1 < N) {
                g_als[r1 * HEADS + head] = ps1 + part_s[lr1];
                g_ald[r1 * HEADS + head] = pd1 + part_d[lr1];
            }
        }
        __syncthreads();   // part_* reused next i-iteration
    }
}

__device__ __forceinline__ float leaky(float v) {
    return v > 0.f ? v : NEG_SLOPE * v;
}

// ---------------- fused GAT aggregation + bias + ReLU + LN + GCN proj ---------
// One WARP per dst node; lane covers 8 channels (uint4 = 16B of the fp16 row).
// All reductions are warp shuffles; no __syncthreads anywhere.
__global__ void __launch_bounds__(128) k_gat(const float* __restrict__ bgat,
                                             const float* __restrict__ gamma,
                                             const float* __restrict__ beta,
                                             const float* __restrict__ wgcn,
                                             int N) {
    __shared__ float4 p_sm[4][32];
    __shared__ int    src_sm[4][32];
    int w = threadIdx.x >> 5, lane = threadIdx.x & 31;
    int d = blockIdx.x * 4 + w;
    if (d >= N) return;
    int head = lane >> 3;                 // 8 lanes per head
    int row0 = g_off[d], row1 = g_off[d + 1];

    float4 aldv = *(const float4*)(g_ald + d * HEADS);

    float acc[8];
#pragma unroll
    for (int j = 0; j < 8; j++) acc[j] = 0.f;
    float zloc[4] = {0.f, 0.f, 0.f, 0.f};

    for (int t0 = row0; t0 < row1; t0 += 32) {
        int cnt = min(32, row1 - t0);
        if (lane < cnt) {
            int s = g_esrc[t0 + lane];
            src_sm[w][lane] = s;
            float4 av = *(const float4*)(g_als + s * HEADS);
            float p0 = __expf(leaky(av.x + aldv.x));
            float p1 = __expf(leaky(av.y + aldv.y));
            float p2 = __expf(leaky(av.z + aldv.z));
            float p3 = __expf(leaky(av.w + aldv.w));
            p_sm[w][lane] = make_float4(p0, p1, p2, p3);
            zloc[0] += p0; zloc[1] += p1; zloc[2] += p2; zloc[3] += p3;
        }
        __syncwarp();
#pragma unroll 4
        for (int e = 0; e < cnt; e++) {
            int s = src_sm[w][e];
            uint4 hv = *(const uint4*)(g_hh + (long)s * HC2 + lane * 4);
            float p = ((const float*)&p_sm[w][e])[head];
            float2 f0 = __half22float2(*(__half2*)&hv.x);
            float2 f1 = __half22float2(*(__half2*)&hv.y);
            float2 f2 = __half22float2(*(__half2*)&hv.z);
            float2 f3 = __half22float2(*(__half2*)&hv.w);
            acc[0] = fmaf(p, f0.x, acc[0]); acc[1] = fmaf(p, f0.y, acc[1]);
            acc[2] = fmaf(p, f1.x, acc[2]); acc[3] = fmaf(p, f1.y, acc[3]);
            acc[4] = fmaf(p, f2.x, acc[4]); acc[5] = fmaf(p, f2.y, acc[5]);
            acc[6] = fmaf(p, f3.x, acc[6]); acc[7] = fmaf(p, f3.y, acc[7]);
        }
        __syncwarp();        // p_sm/src_sm reused next tile
    }

    // ---- softmax denominators across lanes ----
#pragma unroll
    for (int o = 16; o > 0; o >>= 1) {
#pragma unroll
        for (int h = 0; h < 4; h++)
            zloc[h] += __shfl_xor_sync(0xffffffffu, zloc[h], o);
    }
    float zinv = 1.f / zloc[head];

    // ---- bias + ReLU ----
    int ch = lane * 8;
    float4 b0 = *(const float4*)(bgat + ch);
    float4 b1 = *(const float4*)(bgat + ch + 4);
    float v[8];
    v[0] = fmaxf(fmaf(acc[0], zinv, b0.x), 0.f);
    v[1] = fmaxf(fmaf(acc[1], zinv, b0.y), 0.f);
    v[2] = fmaxf(fmaf(acc[2], zinv, b0.z), 0.f);
    v[3] = fmaxf(fmaf(acc[3], zinv, b0.w), 0.f);
    v[4] = fmaxf(fmaf(acc[4], zinv, b1.x), 0.f);
    v[5] = fmaxf(fmaf(acc[5], zinv, b1.y), 0.f);
    v[6] = fmaxf(fmaf(acc[6], zinv, b1.z), 0.f);
    v[7] = fmaxf(fmaf(acc[7], zinv, b1.w), 0.f);

    // ---- LayerNorm stats ----
    float s1 = 0.f, s2 = 0.f;
#pragma unroll
    for (int j = 0; j < 8; j++) { s1 += v[j]; s2 = fmaf(v[j], v[j], s2); }
#pragma unroll
    for (int o = 16; o > 0; o >>= 1) {
        s1 += __shfl_xor_sync(0xffffffffu, s1, o);
        s2 += __shfl_xor_sync(0xffffffffu, s2, o);
    }
    float mu = s1 * (1.f / 256.f);
    float var = s2 * (1.f / 256.f) - mu * mu;
    float rs = rsqrtf(var + LN_EPS);

    // ---- LN affine + W_gcn projection ----
    float4 gm0 = *(const float4*)(gamma + ch);
    float4 gm1 = *(const float4*)(gamma + ch + 4);
    float4 bt0 = *(const float4*)(beta + ch);
    float4 bt1 = *(const float4*)(beta + ch + 4);
    float4 wg0 = *(const float4*)(wgcn + ch);
    float4 wg1 = *(const float4*)(wgcn + ch + 4);
    float gmv[8] = {gm0.x, gm0.y, gm0.z, gm0.w, gm1.x, gm1.y, gm1.z, gm1.w};
    float btv[8] = {bt0.x, bt0.y, bt0.z, bt0.w, bt1.x, bt1.y, bt1.z, bt1.w};
    float wgv[8] = {wg0.x, wg0.y, wg0.z, wg0.w, wg1.x, wg1.y, wg1.z, wg1.w};
    float g = 0.f;
#pragma unroll
    for (int j = 0; j < 8; j++) {
        float a = fmaf((v[j] - mu) * rs, gmv[j], btv[j]);
        g = fmaf(a, wgv[j], g);
    }
#pragma unroll
    for (int o = 16; o > 0; o >>= 1) g += __shfl_xor_sync(0xffffffffu, g, o);

    if (lane == 0)
        g_dh[d] = make_float2(rsqrtf((float)(row1 - row0)), g);
}

// ---------------- GCN aggregation: warp per node (+ g_deg re-zero) ------------
__global__ void k_gcn(const float* __restrict__ bgcn, float* __restrict__ out, int N) {
    int gi = blockIdx.x * 128 + threadIdx.x;   // 320000 threads >= N
    if (gi < N) g_deg[gi] = 0;                 // zero for the NEXT call
    int d = blockIdx.x * 4 + (threadIdx.x >> 5);
    int lane = threadIdx.x & 31;
    if (d >= N) return;
    int row0 = g_off[d], row1 = g_off[d + 1];
    float sum = 0.f;
    for (int i = row0 + lane; i < row1; i += 32) {
        float2 dh = g_dh[g_esrc[i]];
        sum = fmaf(dh.x, dh.y, sum);
    }
#pragma unroll
    for (int o = 16; o > 0; o >>= 1) sum += __shfl_down_sync(0xffffffffu, sum, o);
    if (lane == 0) out[d] = bgcn[0] + g_dh[d].x * sum;
}

// ---------------- launch ------------------------------------------------------
extern "C" void kernel_launch(void* const* d_in, const int* in_sizes, int n_in,
                              void* d_out, int out_size) {
    const float* x     = (const float*)d_in[0];
    const int*   ei    = (const int*)  d_in[1];
    const float* Wgat  = (const float*)d_in[2];
    const float* asrc  = (const float*)d_in[3];
    const float* adst  = (const float*)d_in[4];
    const float* bgat  = (const float*)d_in[5];
    const float* gamma = (const float*)d_in[6];
    const float* beta  = (const float*)d_in[7];
    const float* wgcn  = (const float*)d_in[8];
    const float* bgcn  = (const float*)d_in[9];
    float* out = (float*)d_out;

    int N = in_sizes[0] / IN_C;
    int E = in_sizes[1] / 2;
    const int* src = ei;
    const int* dst = ei + E;

    // one-time side-stream resources (created outside any capture)
    static cudaStream_t s_csr = nullptr;
    static cudaEvent_t  ev_fork = nullptr, ev_join = nullptr;
    if (s_csr == nullptr) {
        cudaStreamCreateWithFlags(&s_csr, cudaStreamNonBlocking);
        cudaEventCreateWithFlags(&ev_fork, cudaEventDisableTiming);
        cudaEventCreateWithFlags(&ev_join, cudaEventDisableTiming);
    }

    // fork: CSR chain on s_csr, fp16 convert + GEMM on the main stream.
    cudaEventRecord(ev_fork, 0);
    cudaStreamWaitEvent(s_csr, ev_fork, 0);

    k_count<<<(E + 1023) / 1024, 256, 0, s_csr>>>(dst, E);
    k_scan<<<1, 1024, 0, s_csr>>>(N);
    k_scatter<<<(E + N + 1023) / 1024, 256, 0, s_csr>>>(src, dst, E, N);
    cudaEventRecord(ev_join, s_csr);

    int conv_threads = N * (IN_C / 8) + (IN_C * HC / 8);
    k_half<<<(conv_threads + 255) / 256, 256>>>(x, Wgat, N);
    dim3 gb(HC / 64, (N + 63) / 64);
    k_gemm<<<gb, 128>>>(asrc, adst, N);

    // join: k_gat needs both CSR and GEMM outputs
    cudaStreamWaitEvent(0, ev_join, 0);
    k_gat<<<(N + 3) / 4, 128>>>(bgat, gamma, beta, wgcn, N);
    k_gcn<<<(N + 3) / 4, 128>>>(bgcn, out, N);
}

// round 13
// speedup vs baseline: 2.5499x; 1.0305x over previous
#include <cuda_runtime.h>
#include <cuda_fp16.h>

#define IN_C   256
#define HC     256
#define HEADS  4
#define CPH    64
#define HC2    128          // half2 count per row
#define NMAX   10000
#define EMAX   320000
#define ETMAX  (EMAX + NMAX)
#define NEG_SLOPE 0.2f
#define LN_EPS 1e-5f

// ---------------- scratch (static device memory; no allocations) -------------
__device__ __align__(16) __half2 g_hh[NMAX * HC2]; // GAT features (fp16 pairs)
__device__ __align__(16) __half  g_xh[NMAX * IN_C]; // X in fp16
__device__ __align__(16) __half  g_wh[IN_C * HC];   // W_gat in fp16 (k-major)
__device__ float  g_als[NMAX * HEADS];
__device__ float  g_ald[NMAX * HEADS];
__device__ __align__(16) int g_deg[NMAX];          // zero at load + re-zeroed by k_gcn
__device__ int    g_off[NMAX + 1];
__device__ int    g_cur[NMAX];
__device__ int    g_esrc[ETMAX];       // CSR by dst: src node of each in-edge
__device__ float2 g_dh[NMAX];          // {dinv, h2} packed

// ---------------- CSR construction -------------------------------------------
__global__ void k_count(const int* __restrict__ dst, int E) {
    int i0 = (blockIdx.x * blockDim.x + threadIdx.x) * 4;
    if (i0 + 3 < E) {
        int4 d4 = *(const int4*)(dst + i0);
        atomicAdd(&g_deg[d4.x], 1);
        atomicAdd(&g_deg[d4.y], 1);
        atomicAdd(&g_deg[d4.z], 1);
        atomicAdd(&g_deg[d4.w], 1);
    } else {
        for (int j = 0; j < 4; j++) {
            int i = i0 + j;
            if (i < E) atomicAdd(&g_deg[dst[i]], 1);
        }
    }
}

// single-block exclusive scan of (g_deg + 1) -> g_off / g_cur, 4 elems/thread
__global__ void k_scan(int N) {
    __shared__ int warp_sums[32];
    __shared__ int carry_s;
    int tid = threadIdx.x;
    int lane = tid & 31, wid = tid >> 5;
    if (tid == 0) carry_s = 0;
    __syncthreads();
    for (int base = 0; base < N; base += 4096) {
        int i0 = base + tid * 4;
        int v0 = 0, v1 = 0, v2 = 0, v3 = 0;
        if (i0 + 3 < N) {
            int4 dv = *(const int4*)&g_deg[i0];
            v0 = dv.x + 1; v1 = dv.y + 1; v2 = dv.z + 1; v3 = dv.w + 1;
        } else {
            if (i0     < N) v0 = g_deg[i0]     + 1;
            if (i0 + 1 < N) v1 = g_deg[i0 + 1] + 1;
            if (i0 + 2 < N) v2 = g_deg[i0 + 2] + 1;
            if (i0 + 3 < N) v3 = g_deg[i0 + 3] + 1;
        }
        int v = v0 + v1 + v2 + v3;
        int incl = v;
#pragma unroll
        for (int s = 1; s < 32; s <<= 1) {
            int t = __shfl_up_sync(0xffffffffu, incl, s);
            if (lane >= s) incl += t;
        }
        if (lane == 31) warp_sums[wid] = incl;
        __syncthreads();
        if (wid == 0) {
            int w = warp_sums[lane];
#pragma unroll
            for (int s = 1; s < 32; s <<= 1) {
                int t = __shfl_up_sync(0xffffffffu, w, s);
                if (lane >= s) w += t;
            }
            warp_sums[lane] = w;
        }
        __syncthreads();
        int warp_base = (wid > 0) ? warp_sums[wid - 1] : 0;
        int c = carry_s;
        int incl_blk = warp_base + incl;
        int e0 = c + incl_blk - v;
        int e1 = e0 + v0, e2 = e1 + v1, e3 = e2 + v2;
        if (i0     < N) { g_off[i0]     = e0; g_cur[i0]     = e0; if (i0     == N - 1) g_off[N] = e1; }
        if (i0 + 1 < N) { g_off[i0 + 1] = e1; g_cur[i0 + 1] = e1; if (i0 + 1 == N - 1) g_off[N] = e2; }
        if (i0 + 2 < N) { g_off[i0 + 2] = e2; g_cur[i0 + 2] = e2; if (i0 + 2 == N - 1) g_off[N] = e3; }
        if (i0 + 3 < N) { g_off[i0 + 3] = e3; g_cur[i0 + 3] = e3; if (i0 + 3 == N - 1) g_off[N] = e3 + v3; }
        __syncthreads();
        if (tid == 1023) carry_s = c + incl_blk;
        __syncthreads();
    }
}

__global__ void k_scatter(const int* __restrict__ src, const int* __restrict__ dst,
                          int E, int N) {
    int i0 = (blockIdx.x * blockDim.x + threadIdx.x) * 4;
    if (i0 + 3 < E) {
        int4 s4 = *(const int4*)(src + i0);
        int4 d4 = *(const int4*)(dst + i0);
        int p0 = atomicAdd(&g_cur[d4.x], 1);
        int p1 = atomicAdd(&g_cur[d4.y], 1);
        int p2 = atomicAdd(&g_cur[d4.z], 1);
        int p3 = atomicAdd(&g_cur[d4.w], 1);
        g_esrc[p0] = s4.x; g_esrc[p1] = s4.y;
        g_esrc[p2] = s4.z; g_esrc[p3] = s4.w;
    } else {
        for (int j = 0; j < 4; j++) {
            int i = i0 + j;
            if (i >= E + N) break;
            int d, s;
            if (i < E) { d = dst[i]; s = src[i]; }
            else       { d = i - E;  s = i - E;  }   // self loop
            int pos = atomicAdd(&g_cur[d], 1);
            g_esrc[pos] = s;
        }
    }
}

// ---------------- fp32 -> fp16 convert for X and W (2 chunks/thread) ----------
__device__ __forceinline__ void conv8(int c, const float* __restrict__ X,
                                      const float* __restrict__ W, int nx) {
    const float* sp;
    __half* dp;
    if (c < nx) {
        sp = X + (long)c * 8;
        dp = g_xh + (long)c * 8;
    } else {
        int u = c - nx;
        if (u >= IN_C * HC / 8) return;
        sp = W + (long)u * 8;
        dp = g_wh + (long)u * 8;
    }
    float4 a = *(const float4*)sp;
    float4 b = *(const float4*)(sp + 4);
    __half2 h[4];
    h[0] = __floats2half2_rn(a.x, a.y);
    h[1] = __floats2half2_rn(a.z, a.w);
    h[2] = __floats2half2_rn(b.x, b.y);
    h[3] = __floats2half2_rn(b.z, b.w);
    *(uint4*)dp = *(uint4*)h;
}

__global__ void k_half(const float* __restrict__ X, const float* __restrict__ W, int N) {
    int t = blockIdx.x * 256 + threadIdx.x;
    int nx = N * (IN_C / 8);
    conv8(t * 2,     X, W, nx);
    conv8(t * 2 + 1, X, W, nx);
}

// ---------------- tensor-core GEMM + fused logits + fp16 h store --------------
// 64x64 tile, 128 threads (4 warps, 2x2), m16n8k16 fp16 mma, fp32 accumulate.
// fp16 inputs (g_xh, g_wh) loaded via cp.async, double-buffered k-slices of 64.
// A smem: [m][k] swizzled; B smem: [k][n] swizzled, B frags via ldmatrix.trans.
// XOR swizzle: unit(r,c) = r*8 + (c ^ (r&7)), 16B units, 8 units/row.
__device__ __forceinline__ void mma16816(float* c, const unsigned* a, const unsigned* b) {
    asm volatile("mma.sync.aligned.m16n8k16.row.col.f32.f16.f16.f32 "
                 "{%0,%1,%2,%3}, {%4,%5,%6,%7}, {%8,%9}, {%0,%1,%2,%3};"
                 : "+f"(c[0]), "+f"(c[1]), "+f"(c[2]), "+f"(c[3])
                 : "r"(a[0]), "r"(a[1]), "r"(a[2]), "r"(a[3]),
                   "r"(b[0]), "r"(b[1]));
}

__device__ __forceinline__ void cp16(unsigned dst, const void* src, int src_sz) {
    asm volatile("cp.async.cg.shared.global [%0], [%1], 16, %2;"
                 :: "r"(dst), "l"(__cvta_generic_to_global(src)), "r"(src_sz));
}

__global__ void __launch_bounds__(128) k_gemm(const float* __restrict__ asrc,
                                              const float* __restrict__ adst,
                                              int N) {
    __shared__ __align__(16) __half As[2][64 * 64];
    __shared__ __align__(16) __half Bs[2][64 * 64];
    __shared__ float part_s[64], part_d[64];   // cross-warp logit partials
    int tid = threadIdx.x;
    int lane = tid & 31, w = tid >> 5;
    int wm = w >> 1, wn = w & 1;
    int head = blockIdx.x;               // 64 cols == one head
    int mblk = blockIdx.y * 64;
    unsigned asb = (unsigned)__cvta_generic_to_shared(&As[0][0]);
    unsigned bsb = (unsigned)__cvta_generic_to_shared(&Bs[0][0]);

    // per-thread loader geometry: row r = tid>>1, 4 units starting (tid&1)*4
    int lr = tid >> 1;
    int lcu = (tid & 1) * 4;
    int arow = mblk + lr;
    int asz = (arow < N) ? 16 : 0;
    const __half* pa = g_xh + (long)min(arow, N - 1) * IN_C + lcu * 8;
    const __half* pb = g_wh + (long)lr * HC + head * 64 + lcu * 8;

    float c[2][4][4];
#pragma unroll
    for (int i = 0; i < 2; i++)
#pragma unroll
        for (int j = 0; j < 4; j++)
#pragma unroll
            for (int q = 0; q < 4; q++) c[i][j][q] = 0.f;

    // issue slice s into buffer buf
    auto load_slice = [&](int s, int buf) {
        unsigned ab = asb + buf * 8192;
        unsigned bb = bsb + buf * 8192;
#pragma unroll
        for (int u = 0; u < 4; u++) {
            int cc = lcu + u;
            int unit = lr * 8 + (cc ^ (lr & 7));
            cp16(ab + unit * 16, pa + s * 64 + u * 8, asz);
            cp16(bb + unit * 16, pb + (long)s * 64 * HC + u * 8, 16);
        }
    };

    load_slice(0, 0);
    asm volatile("cp.async.commit_group;");

    for (int s = 0; s < 4; s++) {
        if (s < 3) {
            load_slice(s + 1, (s + 1) & 1);
            asm volatile("cp.async.commit_group;");
            asm volatile("cp.async.wait_group 1;");
        } else {
            asm volatile("cp.async.wait_group 0;");
        }
        __syncthreads();

        unsigned ab = asb + (s & 1) * 8192;
        unsigned bb = bsb + (s & 1) * 8192;
#pragma unroll
        for (int kk = 0; kk < 4; kk++) {
            unsigned af[2][4], bf[4][2];
#pragma unroll
            for (int i = 0; i < 2; i++) {
                int r = wm * 32 + i * 16 + (lane & 15);
                int cc = 2 * kk + (lane >> 4);
                int unit = r * 8 + (cc ^ (r & 7));
                unsigned addr = ab + unit * 16;
                asm volatile("ldmatrix.sync.aligned.m8n8.x4.shared.b16 "
                             "{%0,%1,%2,%3}, [%4];"
                             : "=r"(af[i][0]), "=r"(af[i][1]),
                               "=r"(af[i][2]), "=r"(af[i][3])
                             : "r"(addr));
            }
#pragma unroll
            for (int j = 0; j < 4; j++) {
                int l = lane & 15;
                int r = kk * 16 + l;
                int cc = wn * 4 + j;
                int unit = r * 8 + (cc ^ (r & 7));
                unsigned addr = bb + unit * 16;
                asm volatile("ldmatrix.sync.aligned.m8n8.x2.trans.shared.b16 "
                             "{%0,%1}, [%2];"
                             : "=r"(bf[j][0]), "=r"(bf[j][1])
                             : "r"(addr));
            }
#pragma unroll
            for (int i = 0; i < 2; i++)
#pragma unroll
                for (int j = 0; j < 4; j++)
                    mma16816(c[i][j], af[i], bf[j]);
        }
        __syncthreads();   // protect buffer (s&1) before it is refilled
    }

    // ---- epilogue: fp16 h store + fused logit reduction ----------------------
    int grp = lane >> 2, tq = lane & 3;
    float as0[4], as1[4], ad0[4], ad1[4];
#pragma unroll
    for (int j = 0; j < 4; j++) {
        int col = wn * 32 + j * 8 + 2 * tq;
        as0[j] = asrc[head * CPH + col];     as1[j] = asrc[head * CPH + col + 1];
        ad0[j] = adst[head * CPH + col];     ad1[j] = adst[head * CPH + col + 1];
    }

#pragma unroll
    for (int i = 0; i < 2; i++) {
        int lr0 = wm * 32 + i * 16 + grp;     // row within block tile
        int lr1 = lr0 + 8;
        int r0 = mblk + lr0;
        int r1 = mblk + lr1;
        float ps0 = 0.f, pd0 = 0.f, ps1 = 0.f, pd1 = 0.f;
#pragma unroll
        for (int j = 0; j < 4; j++) {
            ps0 = fmaf(c[i][j][0], as0[j], fmaf(c[i][j][1], as1[j], ps0));
            pd0 = fmaf(c[i][j][0], ad0[j], fmaf(c[i][j][1], ad1[j], pd0));
            ps1 = fmaf(c[i][j][2], as0[j], fmaf(c[i][j][3], as1[j], ps1));
            pd1 = fmaf(c[i][j][2], ad0[j], fmaf(c[i][j][3], ad1[j], pd1));
            int gcol = head * 64 + wn * 32 + j * 8 + 2 * tq;
            if (r0 < N)
                g_hh[(long)r0 * HC2 + (gcol >> 1)] =
                    __floats2half2_rn(c[i][j][0], c[i][j][1]);
            if (r1 < N)
                g_hh[(long)r1 * HC2 + (gcol >> 1)] =
                    __floats2half2_rn(c[i][j][2], c[i][j][3]);
        }
#pragma unroll
        for (int o = 1; o < 4; o <<= 1) {
            ps0 += __shfl_xor_sync(0xffffffffu, ps0, o);
            pd0 += __shfl_xor_sync(0xffffffffu, pd0, o);
            ps1 += __shfl_xor_sync(0xffffffffu, ps1, o);
            pd1 += __shfl_xor_sync(0xffffffffu, pd1, o);
        }
        // cross-wn reduction: wn==0 deposits, wn==1 combines + stores
        if (tq == 0 && wn == 0) {
            part_s[lr0] = ps0; part_d[lr0] = pd0;
            part_s[lr1] = ps1; part_d[lr1] = pd1;
        }
        __syncthreads();
        if (tq == 0 && wn == 1) {
            if (r0 < N) {
                g_als[r0 * HEADS + head] = ps0 + part_s[lr0];
                g_ald[r0 * HEADS + head] = pd0 + part_d[lr0];
            }
            if (r1 < N) {
                g_als[r1 * HEADS + head] = ps1 + part_s[lr1];
                g_ald[r1 * HEADS + head] = pd1 + part_d[lr1];
            }
        }
        __syncthreads();   // part_* reused next i-iteration
    }
}

__device__ __forceinline__ float leaky(float v) {
    return v > 0.f ? v : NEG_SLOPE * v;
}

// ---------------- fused GAT aggregation + bias + ReLU + LN + GCN proj ---------
// One WARP per dst node; lane covers 8 channels (uint4 = 16B of the fp16 row).
// Gather is batch-8: 8 independent LDG.128 in flight per lane.
__global__ void __launch_bounds__(128) k_gat(const float* __restrict__ bgat,
                                             const float* __restrict__ gamma,
                                             const float* __restrict__ beta,
                                             const float* __restrict__ wgcn,
                                             int N) {
    __shared__ float4 p_sm[4][32];
    __shared__ int    src_sm[4][32];
    int w = threadIdx.x >> 5, lane = threadIdx.x & 31;
    int d = blockIdx.x * 4 + w;
    if (d >= N) return;
    int head = lane >> 3;                 // 8 lanes per head
    int row0 = g_off[d], row1 = g_off[d + 1];

    float4 aldv = *(const float4*)(g_ald + d * HEADS);

    float acc[8];
#pragma unroll
    for (int j = 0; j < 8; j++) acc[j] = 0.f;
    float zloc[4] = {0.f, 0.f, 0.f, 0.f};

    const __half2* hhp = g_hh;

    for (int t0 = row0; t0 < row1; t0 += 32) {
        int cnt = min(32, row1 - t0);
        if (lane < cnt) {
            int s = g_esrc[t0 + lane];
            src_sm[w][lane] = s;
            float4 av = *(const float4*)(g_als + s * HEADS);
            float p0 = __expf(leaky(av.x + aldv.x));
            float p1 = __expf(leaky(av.y + aldv.y));
            float p2 = __expf(leaky(av.z + aldv.z));
            float p3 = __expf(leaky(av.w + aldv.w));
            p_sm[w][lane] = make_float4(p0, p1, p2, p3);
            zloc[0] += p0; zloc[1] += p1; zloc[2] += p2; zloc[3] += p3;
        }
        __syncwarp();
        int e = 0;
        for (; e + 8 <= cnt; e += 8) {
            uint4 hv[8];
            float pv[8];
#pragma unroll
            for (int u = 0; u < 8; u++) {
                int s = src_sm[w][e + u];
                hv[u] = *(const uint4*)(hhp + (long)s * HC2 + lane * 4);
                pv[u] = ((const float*)&p_sm[w][e + u])[head];
            }
#pragma unroll
            for (int u = 0; u < 8; u++) {
                float p = pv[u];
                float2 f0 = __half22float2(*(__half2*)&hv[u].x);
                float2 f1 = __half22float2(*(__half2*)&hv[u].y);
                float2 f2 = __half22float2(*(__half2*)&hv[u].z);
                float2 f3 = __half22float2(*(__half2*)&hv[u].w);
                acc[0] = fmaf(p, f0.x, acc[0]); acc[1] = fmaf(p, f0.y, acc[1]);
                acc[2] = fmaf(p, f1.x, acc[2]); acc[3] = fmaf(p, f1.y, acc[3]);
                acc[4] = fmaf(p, f2.x, acc[4]); acc[5] = fmaf(p, f2.y, acc[5]);
                acc[6] = fmaf(p, f3.x, acc[6]); acc[7] = fmaf(p, f3.y, acc[7]);
            }
        }
        for (; e < cnt; e++) {
            int s = src_sm[w][e];
            uint4 hv = *(const uint4*)(hhp + (long)s * HC2 + lane * 4);
            float p = ((const float*)&p_sm[w][e])[head];
            float2 f0 = __half22float2(*(__half2*)&hv.x);
            float2 f1 = __half22float2(*(__half2*)&hv.y);
            float2 f2 = __half22float2(*(__half2*)&hv.z);
            float2 f3 = __half22float2(*(__half2*)&hv.w);
            acc[0] = fmaf(p, f0.x, acc[0]); acc[1] = fmaf(p, f0.y, acc[1]);
            acc[2] = fmaf(p, f1.x, acc[2]); acc[3] = fmaf(p, f1.y, acc[3]);
            acc[4] = fmaf(p, f2.x, acc[4]); acc[5] = fmaf(p, f2.y, acc[5]);
            acc[6] = fmaf(p, f3.x, acc[6]); acc[7] = fmaf(p, f3.y, acc[7]);
        }
        __syncwarp();        // p_sm/src_sm reused next tile
    }

    // ---- softmax denominators across lanes ----
#pragma unroll
    for (int o = 16; o > 0; o >>= 1) {
#pragma unroll
        for (int h = 0; h < 4; h++)
            zloc[h] += __shfl_xor_sync(0xffffffffu, zloc[h], o);
    }
    float zinv = 1.f / zloc[head];

    // ---- bias + ReLU ----
    int ch = lane * 8;
    float4 b0 = *(const float4*)(bgat + ch);
    float4 b1 = *(const float4*)(bgat + ch + 4);
    float v[8];
    v[0] = fmaxf(fmaf(acc[0], zinv, b0.x), 0.f);
    v[1] = fmaxf(fmaf(acc[1], zinv, b0.y), 0.f);
    v[2] = fmaxf(fmaf(acc[2], zinv, b0.z), 0.f);
    v[3] = fmaxf(fmaf(acc[3], zinv, b0.w), 0.f);
    v[4] = fmaxf(fmaf(acc[4], zinv, b1.x), 0.f);
    v[5] = fmaxf(fmaf(acc[5], zinv, b1.y), 0.f);
    v[6] = fmaxf(fmaf(acc[6], zinv, b1.z), 0.f);
    v[7] = fmaxf(fmaf(acc[7], zinv, b1.w), 0.f);

    // ---- LayerNorm stats ----
    float s1 = 0.f, s2 = 0.f;
#pragma unroll
    for (int j = 0; j < 8; j++) { s1 += v[j]; s2 = fmaf(v[j], v[j], s2); }
#pragma unroll
    for (int o = 16; o > 0; o >>= 1) {
        s1 += __shfl_xor_sync(0xffffffffu, s1, o);
        s2 += __shfl_xor_sync(0xffffffffu, s2, o);
    }
    float mu = s1 * (1.f / 256.f);
    float var = s2 * (1.f / 256.f) - mu * mu;
    float rs = rsqrtf(var + LN_EPS);

    // ---- LN affine + W_gcn projection ----
    float4 gm0 = *(const float4*)(gamma + ch);
    float4 gm1 = *(const float4*)(gamma + ch + 4);
    float4 bt0 = *(const float4*)(beta + ch);
    float4 bt1 = *(const float4*)(beta + ch + 4);
    float4 wg0 = *(const float4*)(wgcn + ch);
    float4 wg1 = *(const float4*)(wgcn + ch + 4);
    float gmv[8] = {gm0.x, gm0.y, gm0.z, gm0.w, gm1.x, gm1.y, gm1.z, gm1.w};
    float btv[8] = {bt0.x, bt0.y, bt0.z, bt0.w, bt1.x, bt1.y, bt1.z, bt1.w};
    float wgv[8] = {wg0.x, wg0.y, wg0.z, wg0.w, wg1.x, wg1.y, wg1.z, wg1.w};
    float g = 0.f;
#pragma unroll
    for (int j = 0; j < 8; j++) {
        float a = fmaf((v[j] - mu) * rs, gmv[j], btv[j]);
        g = fmaf(a, wgv[j], g);
    }
#pragma unroll
    for (int o = 16; o > 0; o >>= 1) g += __shfl_xor_sync(0xffffffffu, g, o);

    if (lane == 0)
        g_dh[d] = make_float2(rsqrtf((float)(row1 - row0)), g);
}

// ---------------- GCN aggregation: warp per node (+ g_deg re-zero) ------------
__global__ void k_gcn(const float* __restrict__ bgcn, float* __restrict__ out, int N) {
    int gi = blockIdx.x * 128 + threadIdx.x;   // 320000 threads >= N
    if (gi < N) g_deg[gi] = 0;                 // zero for the NEXT call
    int d = blockIdx.x * 4 + (threadIdx.x >> 5);
    int lane = threadIdx.x & 31;
    if (d >= N) return;
    int row0 = g_off[d], row1 = g_off[d + 1];
    float sum = 0.f;
    for (int i = row0 + lane; i < row1; i += 32) {
        float2 dh = g_dh[g_esrc[i]];
        sum = fmaf(dh.x, dh.y, sum);
    }
#pragma unroll
    for (int o = 16; o > 0; o >>= 1) sum += __shfl_down_sync(0xffffffffu, sum, o);
    if (lane == 0) out[d] = bgcn[0] + g_dh[d].x * sum;
}

// ---------------- launch ------------------------------------------------------
extern "C" void kernel_launch(void* const* d_in, const int* in_sizes, int n_in,
                              void* d_out, int out_size) {
    const float* x     = (const float*)d_in[0];
    const int*   ei    = (const int*)  d_in[1];
    const float* Wgat  = (const float*)d_in[2];
    const float* asrc  = (const float*)d_in[3];
    const float* adst  = (const float*)d_in[4];
    const float* bgat  = (const float*)d_in[5];
    const float* gamma = (const float*)d_in[6];
    const float* beta  = (const float*)d_in[7];
    const float* wgcn  = (const float*)d_in[8];
    const float* bgcn  = (const float*)d_in[9];
    float* out = (float*)d_out;

    int N = in_sizes[0] / IN_C;
    int E = in_sizes[1] / 2;
    const int* src = ei;
    const int* dst = ei + E;

    // one-time side-stream resources (created outside any capture)
    static cudaStream_t s_csr = nullptr;
    static cudaEvent_t  ev_fork = nullptr, ev_join = nullptr;
    if (s_csr == nullptr) {
        cudaStreamCreateWithFlags(&s_csr, cudaStreamNonBlocking);
        cudaEventCreateWithFlags(&ev_fork, cudaEventDisableTiming);
        cudaEventCreateWithFlags(&ev_join, cudaEventDisableTiming);
    }

    // fork: CSR chain on s_csr, fp16 convert + GEMM on the main stream.
    cudaEventRecord(ev_fork, 0);
    cudaStreamWaitEvent(s_csr, ev_fork, 0);

    k_count<<<(E + 1023) / 1024, 256, 0, s_csr>>>(dst, E);
    k_scan<<<1, 1024, 0, s_csr>>>(N);
    k_scatter<<<(E + N + 1023) / 1024, 256, 0, s_csr>>>(src, dst, E, N);
    cudaEventRecord(ev_join, s_csr);

    int total_chunks = N * (IN_C / 8) + (IN_C * HC / 8);
    k_half<<<((total_chunks + 1) / 2 + 255) / 256, 256>>>(x, Wgat, N);
    dim3 gb(HC / 64, (N + 63) / 64);
    k_gemm<<<gb, 128>>>(asrc, adst, N);

    // join: k_gat needs both CSR and GEMM outputs
    cudaStreamWaitEvent(0, ev_join, 0);
    k_gat<<<(N + 3) / 4, 128>>>(bgat, gamma, beta, wgcn, N);
    k_gcn<<<(N + 3) / 4, 128>>>(bgcn, out, N);
}

// round 14
// speedup vs baseline: 2.7217x; 1.0674x over previous
#include <cuda_runtime.h>
#include <cuda_fp16.h>

#define IN_C   256
#define HC     256
#define HEADS  4
#define CPH    64
#define HC2    128          // half2 count per row
#define NMAX   10000
#define EMAX   320000
#define ETMAX  (EMAX + NMAX)
#define NEG_SLOPE 0.2f
#define LN_EPS 1e-5f

// ---------------- scratch (static device memory; no allocations) -------------
__device__ __align__(16) __half2 g_hh[NMAX * HC2]; // GAT features (fp16 pairs)
__device__ __align__(16) __half  g_xh[NMAX * IN_C]; // X in fp16
__device__ __align__(16) __half  g_wh[IN_C * HC];   // W_gat in fp16 (k-major)
__device__ float  g_als[NMAX * HEADS];
__device__ float  g_ald[NMAX * HEADS];
__device__ __align__(16) int g_deg[NMAX];          // zero at load + re-zeroed by k_gcn
__device__ int    g_off[NMAX + 1];
__device__ int    g_cur[NMAX];
__device__ int    g_esrc[ETMAX];       // CSR by dst: src node of each in-edge
__device__ float2 g_dh[NMAX];          // {dinv, h2} packed

// ---------------- CSR construction -------------------------------------------
__global__ void k_count(const int* __restrict__ dst, int E) {
    int i0 = (blockIdx.x * blockDim.x + threadIdx.x) * 4;
    if (i0 + 3 < E) {
        int4 d4 = *(const int4*)(dst + i0);
        atomicAdd(&g_deg[d4.x], 1);
        atomicAdd(&g_deg[d4.y], 1);
        atomicAdd(&g_deg[d4.z], 1);
        atomicAdd(&g_deg[d4.w], 1);
    } else {
        for (int j = 0; j < 4; j++) {
            int i = i0 + j;
            if (i < E) atomicAdd(&g_deg[dst[i]], 1);
        }
    }
}

// single-block exclusive scan of (g_deg + 1) -> g_off / g_cur, 4 elems/thread
__global__ void k_scan(int N) {
    __shared__ int warp_sums[32];
    __shared__ int carry_s;
    int tid = threadIdx.x;
    int lane = tid & 31, wid = tid >> 5;
    if (tid == 0) carry_s = 0;
    __syncthreads();
    for (int base = 0; base < N; base += 4096) {
        int i0 = base + tid * 4;
        int v0 = 0, v1 = 0, v2 = 0, v3 = 0;
        if (i0 + 3 < N) {
            int4 dv = *(const int4*)&g_deg[i0];
            v0 = dv.x + 1; v1 = dv.y + 1; v2 = dv.z + 1; v3 = dv.w + 1;
        } else {
            if (i0     < N) v0 = g_deg[i0]     + 1;
            if (i0 + 1 < N) v1 = g_deg[i0 + 1] + 1;
            if (i0 + 2 < N) v2 = g_deg[i0 + 2] + 1;
            if (i0 + 3 < N) v3 = g_deg[i0 + 3] + 1;
        }
        int v = v0 + v1 + v2 + v3;
        int incl = v;
#pragma unroll
        for (int s = 1; s < 32; s <<= 1) {
            int t = __shfl_up_sync(0xffffffffu, incl, s);
            if (lane >= s) incl += t;
        }
        if (lane == 31) warp_sums[wid] = incl;
        __syncthreads();
        if (wid == 0) {
            int w = warp_sums[lane];
#pragma unroll
            for (int s = 1; s < 32; s <<= 1) {
                int t = __shfl_up_sync(0xffffffffu, w, s);
                if (lane >= s) w += t;
            }
            warp_sums[lane] = w;
        }
        __syncthreads();
        int warp_base = (wid > 0) ? warp_sums[wid - 1] : 0;
        int c = carry_s;
        int incl_blk = warp_base + incl;
        int e0 = c + incl_blk - v;
        int e1 = e0 + v0, e2 = e1 + v1, e3 = e2 + v2;
        if (i0     < N) { g_off[i0]     = e0; g_cur[i0]     = e0; if (i0     == N - 1) g_off[N] = e1; }
        if (i0 + 1 < N) { g_off[i0 + 1] = e1; g_cur[i0 + 1] = e1; if (i0 + 1 == N - 1) g_off[N] = e2; }
        if (i0 + 2 < N) { g_off[i0 + 2] = e2; g_cur[i0 + 2] = e2; if (i0 + 2 == N - 1) g_off[N] = e3; }
        if (i0 + 3 < N) { g_off[i0 + 3] = e3; g_cur[i0 + 3] = e3; if (i0 + 3 == N - 1) g_off[N] = e3 + v3; }
        __syncthreads();
        if (tid == 1023) carry_s = c + incl_blk;
        __syncthreads();
    }
}

__global__ void k_scatter(const int* __restrict__ src, const int* __restrict__ dst,
                          int E, int N) {
    int i0 = (blockIdx.x * blockDim.x + threadIdx.x) * 4;
    if (i0 + 3 < E) {
        int4 s4 = *(const int4*)(src + i0);
        int4 d4 = *(const int4*)(dst + i0);
        int p0 = atomicAdd(&g_cur[d4.x], 1);
        int p1 = atomicAdd(&g_cur[d4.y], 1);
        int p2 = atomicAdd(&g_cur[d4.z], 1);
        int p3 = atomicAdd(&g_cur[d4.w], 1);
        g_esrc[p0] = s4.x; g_esrc[p1] = s4.y;
        g_esrc[p2] = s4.z; g_esrc[p3] = s4.w;
    } else {
        for (int j = 0; j < 4; j++) {
            int i = i0 + j;
            if (i >= E + N) break;
            int d, s;
            if (i < E) { d = dst[i]; s = src[i]; }
            else       { d = i - E;  s = i - E;  }   // self loop
            int pos = atomicAdd(&g_cur[d], 1);
            g_esrc[pos] = s;
        }
    }
}

// ---------------- fp32 -> fp16 convert for X and W (1 chunk/thread) -----------
__global__ void k_half(const float* __restrict__ X, const float* __restrict__ W, int N) {
    int t = blockIdx.x * 256 + threadIdx.x;      // 8 elems per thread
    int nx = N * (IN_C / 8);
    const float* sp;
    __half* dp;
    if (t < nx) {
        sp = X + (long)t * 8;
        dp = g_xh + (long)t * 8;
    } else {
        int u = t - nx;
        if (u >= IN_C * HC / 8) return;
        sp = W + (long)u * 8;
        dp = g_wh + (long)u * 8;
    }
    float4 a = *(const float4*)sp;
    float4 b = *(const float4*)(sp + 4);
    __half2 h[4];
    h[0] = __floats2half2_rn(a.x, a.y);
    h[1] = __floats2half2_rn(a.z, a.w);
    h[2] = __floats2half2_rn(b.x, b.y);
    h[3] = __floats2half2_rn(b.z, b.w);
    *(uint4*)dp = *(uint4*)h;
}

// ---------------- tensor-core GEMM + fused logits + fp16 h store --------------
__device__ __forceinline__ void mma16816(float* c, const unsigned* a, const unsigned* b) {
    asm volatile("mma.sync.aligned.m16n8k16.row.col.f32.f16.f16.f32 "
                 "{%0,%1,%2,%3}, {%4,%5,%6,%7}, {%8,%9}, {%0,%1,%2,%3};"
                 : "+f"(c[0]), "+f"(c[1]), "+f"(c[2]), "+f"(c[3])
                 : "r"(a[0]), "r"(a[1]), "r"(a[2]), "r"(a[3]),
                   "r"(b[0]), "r"(b[1]));
}

__device__ __forceinline__ void cp16(unsigned dst, const void* src, int src_sz) {
    asm volatile("cp.async.cg.shared.global [%0], [%1], 16, %2;"
                 :: "r"(dst), "l"(__cvta_generic_to_global(src)), "r"(src_sz));
}

__global__ void __launch_bounds__(128) k_gemm(const float* __restrict__ asrc,
                                              const float* __restrict__ adst,
                                              int N) {
    __shared__ __align__(16) __half As[2][64 * 64];
    __shared__ __align__(16) __half Bs[2][64 * 64];
    __shared__ float part_s[64], part_d[64];   // cross-warp logit partials
    int tid = threadIdx.x;
    int lane = tid & 31, w = tid >> 5;
    int wm = w >> 1, wn = w & 1;
    int head = blockIdx.x;               // 64 cols == one head
    int mblk = blockIdx.y * 64;
    unsigned asb = (unsigned)__cvta_generic_to_shared(&As[0][0]);
    unsigned bsb = (unsigned)__cvta_generic_to_shared(&Bs[0][0]);

    int lr = tid >> 1;
    int lcu = (tid & 1) * 4;
    int arow = mblk + lr;
    int asz = (arow < N) ? 16 : 0;
    const __half* pa = g_xh + (long)min(arow, N - 1) * IN_C + lcu * 8;
    const __half* pb = g_wh + (long)lr * HC + head * 64 + lcu * 8;

    float c[2][4][4];
#pragma unroll
    for (int i = 0; i < 2; i++)
#pragma unroll
        for (int j = 0; j < 4; j++)
#pragma unroll
            for (int q = 0; q < 4; q++) c[i][j][q] = 0.f;

    auto load_slice = [&](int s, int buf) {
        unsigned ab = asb + buf * 8192;
        unsigned bb = bsb + buf * 8192;
#pragma unroll
        for (int u = 0; u < 4; u++) {
            int cc = lcu + u;
            int unit = lr * 8 + (cc ^ (lr & 7));
            cp16(ab + unit * 16, pa + s * 64 + u * 8, asz);
            cp16(bb + unit * 16, pb + (long)s * 64 * HC + u * 8, 16);
        }
    };

    load_slice(0, 0);
    asm volatile("cp.async.commit_group;");

    for (int s = 0; s < 4; s++) {
        if (s < 3) {
            load_slice(s + 1, (s + 1) & 1);
            asm volatile("cp.async.commit_group;");
            asm volatile("cp.async.wait_group 1;");
        } else {
            asm volatile("cp.async.wait_group 0;");
        }
        __syncthreads();

        unsigned ab = asb + (s & 1) * 8192;
        unsigned bb = bsb + (s & 1) * 8192;
#pragma unroll
        for (int kk = 0; kk < 4; kk++) {
            unsigned af[2][4], bf[4][2];
#pragma unroll
            for (int i = 0; i < 2; i++) {
                int r = wm * 32 + i * 16 + (lane & 15);
                int cc = 2 * kk + (lane >> 4);
                int unit = r * 8 + (cc ^ (r & 7));
                unsigned addr = ab + unit * 16;
                asm volatile("ldmatrix.sync.aligned.m8n8.x4.shared.b16 "
                             "{%0,%1,%2,%3}, [%4];"
                             : "=r"(af[i][0]), "=r"(af[i][1]),
                               "=r"(af[i][2]), "=r"(af[i][3])
                             : "r"(addr));
            }
#pragma unroll
            for (int j = 0; j < 4; j++) {
                int l = lane & 15;
                int r = kk * 16 + l;
                int cc = wn * 4 + j;
                int unit = r * 8 + (cc ^ (r & 7));
                unsigned addr = bb + unit * 16;
                asm volatile("ldmatrix.sync.aligned.m8n8.x2.trans.shared.b16 "
                             "{%0,%1}, [%2];"
                             : "=r"(bf[j][0]), "=r"(bf[j][1])
                             : "r"(addr));
            }
#pragma unroll
            for (int i = 0; i < 2; i++)
#pragma unroll
                for (int j = 0; j < 4; j++)
                    mma16816(c[i][j], af[i], bf[j]);
        }
        __syncthreads();
    }

    // ---- epilogue: fp16 h store + fused logit reduction ----------------------
    int grp = lane >> 2, tq = lane & 3;
    float as0[4], as1[4], ad0[4], ad1[4];
#pragma unroll
    for (int j = 0; j < 4; j++) {
        int col = wn * 32 + j * 8 + 2 * tq;
        as0[j] = asrc[head * CPH + col];     as1[j] = asrc[head * CPH + col + 1];
        ad0[j] = adst[head * CPH + col];     ad1[j] = adst[head * CPH + col + 1];
    }

#pragma unroll
    for (int i = 0; i < 2; i++) {
        int lr0 = wm * 32 + i * 16 + grp;
        int lr1 = lr0 + 8;
        int r0 = mblk + lr0;
        int r1 = mblk + lr1;
        float ps0 = 0.f, pd0 = 0.f, ps1 = 0.f, pd1 = 0.f;
#pragma unroll
        for (int j = 0; j < 4; j++) {
            ps0 = fmaf(c[i][j][0], as0[j], fmaf(c[i][j][1], as1[j], ps0));
            pd0 = fmaf(c[i][j][0], ad0[j], fmaf(c[i][j][1], ad1[j], pd0));
            ps1 = fmaf(c[i][j][2], as0[j], fmaf(c[i][j][3], as1[j], ps1));
            pd1 = fmaf(c[i][j][2], ad0[j], fmaf(c[i][j][3], ad1[j], pd1));
            int gcol = head * 64 + wn * 32 + j * 8 + 2 * tq;
            if (r0 < N)
                g_hh[(long)r0 * HC2 + (gcol >> 1)] =
                    __floats2half2_rn(c[i][j][0], c[i][j][1]);
            if (r1 < N)
                g_hh[(long)r1 * HC2 + (gcol >> 1)] =
                    __floats2half2_rn(c[i][j][2], c[i][j][3]);
        }
#pragma unroll
        for (int o = 1; o < 4; o <<= 1) {
            ps0 += __shfl_xor_sync(0xffffffffu, ps0, o);
            pd0 += __shfl_xor_sync(0xffffffffu, pd0, o);
            ps1 += __shfl_xor_sync(0xffffffffu, ps1, o);
            pd1 += __shfl_xor_sync(0xffffffffu, pd1, o);
        }
        if (tq == 0 && wn == 0) {
            part_s[lr0] = ps0; part_d[lr0] = pd0;
            part_s[lr1] = ps1; part_d[lr1] = pd1;
        }
        __syncthreads();
        if (tq == 0 && wn == 1) {
            if (r0 < N) {
                g_als[r0 * HEADS + head] = ps0 + part_s[lr0];
                g_ald[r0 * HEADS + head] = pd0 + part_d[lr0];
            }
            if (r1 < N) {
                g_als[r1 * HEADS + head] = ps1 + part_s[lr1];
                g_ald[r1 * HEADS + head] = pd1 + part_d[lr1];
            }
        }
        __syncthreads();
    }
}

__device__ __forceinline__ float leaky(float v) {
    return v > 0.f ? v : NEG_SLOPE * v;
}

// ---------------- fused GAT aggregation + bias + ReLU + LN + GCN proj ---------
// One WARP per dst node; lane covers 8 channels (uint4 = 16B of the fp16 row).
// Software-pipelined: tile t+1's src indices + logit rows are prefetched into
// registers BEFORE tile t's gather, hiding the dependent LDG->LDG->exp chain.
__global__ void __launch_bounds__(128) k_gat(const float* __restrict__ bgat,
                                             const float* __restrict__ gamma,
                                             const float* __restrict__ beta,
                                             const float* __restrict__ wgcn,
                                             int N) {
    __shared__ float4 p_sm[4][32];
    __shared__ int    src_sm[4][32];
    int w = threadIdx.x >> 5, lane = threadIdx.x & 31;
    int d = blockIdx.x * 4 + w;
    if (d >= N) return;
    int head = lane >> 3;                 // 8 lanes per head
    int row0 = g_off[d], row1 = g_off[d + 1];

    float4 aldv = *(const float4*)(g_ald + d * HEADS);

    float acc[8];
#pragma unroll
    for (int j = 0; j < 8; j++) acc[j] = 0.f;
    float zloc[4] = {0.f, 0.f, 0.f, 0.f};

    const __half2* hhp = g_hh;

    // prefetch tile 0
    int s_nx = 0;
    float4 av_nx = make_float4(0.f, 0.f, 0.f, 0.f);
    {
        int cnt0 = min(32, row1 - row0);
        if (lane < cnt0) {
            s_nx = g_esrc[row0 + lane];
            av_nx = *(const float4*)(g_als + s_nx * HEADS);
        }
    }

    for (int t0 = row0; t0 < row1; t0 += 32) {
        int cnt = min(32, row1 - t0);
        if (lane < cnt) {
            float p0 = __expf(leaky(av_nx.x + aldv.x));
            float p1 = __expf(leaky(av_nx.y + aldv.y));
            float p2 = __expf(leaky(av_nx.z + aldv.z));
            float p3 = __expf(leaky(av_nx.w + aldv.w));
            p_sm[w][lane] = make_float4(p0, p1, p2, p3);
            src_sm[w][lane] = s_nx;
            zloc[0] += p0; zloc[1] += p1; zloc[2] += p2; zloc[3] += p3;
        }
        __syncwarp();

        // prefetch NEXT tile's indices + logit rows (latency hidden under gather)
        int t1 = t0 + 32;
        if (t1 < row1) {
            int c2 = min(32, row1 - t1);
            if (lane < c2) {
                s_nx = g_esrc[t1 + lane];
                av_nx = *(const float4*)(g_als + s_nx * HEADS);
            }
        }

        // gather current tile, batch-8
        int e = 0;
        for (; e + 8 <= cnt; e += 8) {
            uint4 hv[8];
            float pv[8];
#pragma unroll
            for (int u = 0; u < 8; u++) {
                int s = src_sm[w][e + u];
                hv[u] = *(const uint4*)(hhp + (long)s * HC2 + lane * 4);
                pv[u] = ((const float*)&p_sm[w][e + u])[head];
            }
#pragma unroll
            for (int u = 0; u < 8; u++) {
                float p = pv[u];
                float2 f0 = __half22float2(*(__half2*)&hv[u].x);
                float2 f1 = __half22float2(*(__half2*)&hv[u].y);
                float2 f2 = __half22float2(*(__half2*)&hv[u].z);
                float2 f3 = __half22float2(*(__half2*)&hv[u].w);
                acc[0] = fmaf(p, f0.x, acc[0]); acc[1] = fmaf(p, f0.y, acc[1]);
                acc[2] = fmaf(p, f1.x, acc[2]); acc[3] = fmaf(p, f1.y, acc[3]);
                acc[4] = fmaf(p, f2.x, acc[4]); acc[5] = fmaf(p, f2.y, acc[5]);
                acc[6] = fmaf(p, f3.x, acc[6]); acc[7] = fmaf(p, f3.y, acc[7]);
            }
        }
        for (; e < cnt; e++) {
            int s = src_sm[w][e];
            uint4 hv = *(const uint4*)(hhp + (long)s * HC2 + lane * 4);
            float p = ((const float*)&p_sm[w][e])[head];
            float2 f0 = __half22float2(*(__half2*)&hv.x);
            float2 f1 = __half22float2(*(__half2*)&hv.y);
            float2 f2 = __half22float2(*(__half2*)&hv.z);
            float2 f3 = __half22float2(*(__half2*)&hv.w);
            acc[0] = fmaf(p, f0.x, acc[0]); acc[1] = fmaf(p, f0.y, acc[1]);
            acc[2] = fmaf(p, f1.x, acc[2]); acc[3] = fmaf(p, f1.y, acc[3]);
            acc[4] = fmaf(p, f2.x, acc[4]); acc[5] = fmaf(p, f2.y, acc[5]);
            acc[6] = fmaf(p, f3.x, acc[6]); acc[7] = fmaf(p, f3.y, acc[7]);
        }
        __syncwarp();        // p_sm/src_sm reused next tile
    }

    // ---- softmax denominators across lanes ----
#pragma unroll
    for (int o = 16; o > 0; o >>= 1) {
#pragma unroll
        for (int h = 0; h < 4; h++)
            zloc[h] += __shfl_xor_sync(0xffffffffu, zloc[h], o);
    }
    float zinv = 1.f / zloc[head];

    // ---- bias + ReLU ----
    int ch = lane * 8;
    float4 b0 = *(const float4*)(bgat + ch);
    float4 b1 = *(const float4*)(bgat + ch + 4);
    float v[8];
    v[0] = fmaxf(fmaf(acc[0], zinv, b0.x), 0.f);
    v[1] = fmaxf(fmaf(acc[1], zinv, b0.y), 0.f);
    v[2] = fmaxf(fmaf(acc[2], zinv, b0.z), 0.f);
    v[3] = fmaxf(fmaf(acc[3], zinv, b0.w), 0.f);
    v[4] = fmaxf(fmaf(acc[4], zinv, b1.x), 0.f);
    v[5] = fmaxf(fmaf(acc[5], zinv, b1.y), 0.f);
    v[6] = fmaxf(fmaf(acc[6], zinv, b1.z), 0.f);
    v[7] = fmaxf(fmaf(acc[7], zinv, b1.w), 0.f);

    // ---- LayerNorm stats ----
    float s1 = 0.f, s2 = 0.f;
#pragma unroll
    for (int j = 0; j < 8; j++) { s1 += v[j]; s2 = fmaf(v[j], v[j], s2); }
#pragma unroll
    for (int o = 16; o > 0; o >>= 1) {
        s1 += __shfl_xor_sync(0xffffffffu, s1, o);
        s2 += __shfl_xor_sync(0xffffffffu, s2, o);
    }
    float mu = s1 * (1.f / 256.f);
    float var = s2 * (1.f / 256.f) - mu * mu;
    float rs = rsqrtf(var + LN_EPS);

    // ---- LN affine + W_gcn projection ----
    float4 gm0 = *(const float4*)(gamma + ch);
    float4 gm1 = *(const float4*)(gamma + ch + 4);
    float4 bt0 = *(const float4*)(beta + ch);
    float4 bt1 = *(const float4*)(beta + ch + 4);
    float4 wg0 = *(const float4*)(wgcn + ch);
    float4 wg1 = *(const float4*)(wgcn + ch + 4);
    float gmv[8] = {gm0.x, gm0.y, gm0.z, gm0.w, gm1.x, gm1.y, gm1.z, gm1.w};
    float btv[8] = {bt0.x, bt0.y, bt0.z, bt0.w, bt1.x, bt1.y, bt1.z, bt1.w};
    float wgv[8] = {wg0.x, wg0.y, wg0.z, wg0.w, wg1.x, wg1.y, wg1.z, wg1.w};
    float g = 0.f;
#pragma unroll
    for (int j = 0; j < 8; j++) {
        float a = fmaf((v[j] - mu) * rs, gmv[j], btv[j]);
        g = fmaf(a, wgv[j], g);
    }
#pragma unroll
    for (int o = 16; o > 0; o >>= 1) g += __shfl_xor_sync(0xffffffffu, g, o);

    if (lane == 0)
        g_dh[d] = make_float2(rsqrtf((float)(row1 - row0)), g);
}

// ---------------- GCN aggregation: warp per node (+ g_deg re-zero) ------------
__global__ void k_gcn(const float* __restrict__ bgcn, float* __restrict__ out, int N) {
    int gi = blockIdx.x * 128 + threadIdx.x;   // 320000 threads >= N
    if (gi < N) g_deg[gi] = 0;                 // zero for the NEXT call
    int d = blockIdx.x * 4 + (threadIdx.x >> 5);
    int lane = threadIdx.x & 31;
    if (d >= N) return;
    int row0 = g_off[d], row1 = g_off[d + 1];
    float sum = 0.f;
    for (int i = row0 + lane; i < row1; i += 32) {
        float2 dh = g_dh[g_esrc[i]];
        sum = fmaf(dh.x, dh.y, sum);
    }
#pragma unroll
    for (int o = 16; o > 0; o >>= 1) sum += __shfl_down_sync(0xffffffffu, sum, o);
    if (lane == 0) out[d] = bgcn[0] + g_dh[d].x * sum;
}

// ---------------- launch ------------------------------------------------------
extern "C" void kernel_launch(void* const* d_in, const int* in_sizes, int n_in,
                              void* d_out, int out_size) {
    const float* x     = (const float*)d_in[0];
    const int*   ei    = (const int*)  d_in[1];
    const float* Wgat  = (const float*)d_in[2];
    const float* asrc  = (const float*)d_in[3];
    const float* adst  = (const float*)d_in[4];
    const float* bgat  = (const float*)d_in[5];
    const float* gamma = (const float*)d_in[6];
    const float* beta  = (const float*)d_in[7];
    const float* wgcn  = (const float*)d_in[8];
    const float* bgcn  = (const float*)d_in[9];
    float* out = (float*)d_out;

    int N = in_sizes[0] / IN_C;
    int E = in_sizes[1] / 2;
    const int* src = ei;
    const int* dst = ei + E;

    // one-time side-stream resources (created outside any capture)
    static cudaStream_t s_csr = nullptr;
    static cudaEvent_t  ev_fork = nullptr, ev_join = nullptr;
    if (s_csr == nullptr) {
        cudaStreamCreateWithFlags(&s_csr, cudaStreamNonBlocking);
        cudaEventCreateWithFlags(&ev_fork, cudaEventDisableTiming);
        cudaEventCreateWithFlags(&ev_join, cudaEventDisableTiming);
    }

    // fork: CSR chain on s_csr, fp16 convert + GEMM on the main stream.
    cudaEventRecord(ev_fork, 0);
    cudaStreamWaitEvent(s_csr, ev_fork, 0);

    k_count<<<(E + 1023) / 1024, 256, 0, s_csr>>>(dst, E);
    k_scan<<<1, 1024, 0, s_csr>>>(N);
    k_scatter<<<(E + N + 1023) / 1024, 256, 0, s_csr>>>(src, dst, E, N);
    cudaEventRecord(ev_join, s_csr);

    int total_chunks = N * (IN_C / 8) + (IN_C * HC / 8);
    k_half<<<(total_chunks + 255) / 256, 256>>>(x, Wgat, N);
    dim3 gb(HC / 64, (N + 63) / 64);
    k_gemm<<<gb, 128>>>(asrc, adst, N);

    // join: k_gat needs both CSR and GEMM outputs
    cudaStreamWaitEvent(0, ev_join, 0);
    k_gat<<<(N + 3) / 4, 128>>>(bgat, gamma, beta, wgcn, N);
    k_gcn<<<(N + 3) / 4, 128>>>(bgcn, out, N);
}